// round 7
// baseline (speedup 1.0000x reference)
#include <cuda_runtime.h>
#include <cuda_bf16.h>
#include <mma.h>
#include <cstdint>

using namespace nvcuda;

// Problem constants
#define TBv 16          // T*B
#define Nv  1024
#define Dv  512
#define Hv  8
#define HDv 64
#define Mv  (TBv * Nv)  // 16384 tokens

// Global bf16 hi/lo planes (3xBF16 decomposition: x = hi + lo)
__device__ __nv_bfloat16 gx_hi[(size_t)Mv * Dv], gx_lo[(size_t)Mv * Dv];
__device__ __nv_bfloat16 gw_hi[4 * Dv * Dv],     gw_lo[4 * Dv * Dv];   // q,k,v,o
__device__ __nv_bfloat16 gq_hi[(size_t)Mv * Dv], gq_lo[(size_t)Mv * Dv]; // head-major
__device__ __nv_bfloat16 gk_hi[(size_t)Mv * Dv], gk_lo[(size_t)Mv * Dv];
__device__ __nv_bfloat16 gv_hi[(size_t)Mv * Dv], gv_lo[(size_t)Mv * Dv];
__device__ __nv_bfloat16 gc_hi[(size_t)Mv * Dv], gc_lo[(size_t)Mv * Dv]; // ctx token-major

// ---------------------------------------------------------------------------
// helpers
// ---------------------------------------------------------------------------
__device__ __forceinline__ void split_store4(float4 v,
                                             __nv_bfloat16* __restrict__ hp,
                                             __nv_bfloat16* __restrict__ lp)
{
    __nv_bfloat16 hx = __float2bfloat16_rn(v.x);
    __nv_bfloat16 hy = __float2bfloat16_rn(v.y);
    __nv_bfloat16 hz = __float2bfloat16_rn(v.z);
    __nv_bfloat16 hw = __float2bfloat16_rn(v.w);
    __nv_bfloat16 lx = __float2bfloat16_rn(v.x - __bfloat162float(hx));
    __nv_bfloat16 ly = __float2bfloat16_rn(v.y - __bfloat162float(hy));
    __nv_bfloat16 lz = __float2bfloat16_rn(v.z - __bfloat162float(hz));
    __nv_bfloat16 lw = __float2bfloat16_rn(v.w - __bfloat162float(hw));
    ((__nv_bfloat162*)hp)[0] = __halves2bfloat162(hx, hy);
    ((__nv_bfloat162*)hp)[1] = __halves2bfloat162(hz, hw);
    ((__nv_bfloat162*)lp)[0] = __halves2bfloat162(lx, ly);
    ((__nv_bfloat162*)lp)[1] = __halves2bfloat162(lz, lw);
}

__device__ __forceinline__ void cp16(uint32_t dst, const void* src) {
    asm volatile("cp.async.cg.shared.global [%0], [%1], 16;" :: "r"(dst), "l"(src));
}
__device__ __forceinline__ void cp_commit() {
    asm volatile("cp.async.commit_group;" ::: "memory");
}

using BFragA  = wmma::fragment<wmma::matrix_a, 16, 16, 16, __nv_bfloat16, wmma::row_major>;
using BFragBc = wmma::fragment<wmma::matrix_b, 16, 16, 16, __nv_bfloat16, wmma::col_major>;
using BFragBr = wmma::fragment<wmma::matrix_b, 16, 16, 16, __nv_bfloat16, wmma::row_major>;
using FragC   = wmma::fragment<wmma::accumulator, 16, 16, 16, float>;

// ---------------------------------------------------------------------------
// split kernel: x + 4 weights -> hi/lo bf16 planes
// ---------------------------------------------------------------------------
#define NXf4 (Mv * Dv / 4)      // 2097152
#define NWf4 (Dv * Dv / 4)      // 65536

__global__ __launch_bounds__(256) void split_kernel(
    const float* __restrict__ x,
    const float* __restrict__ wq, const float* __restrict__ wk,
    const float* __restrict__ wv, const float* __restrict__ wo)
{
    int i = blockIdx.x * 256 + threadIdx.x;
    const float* src;
    __nv_bfloat16 *dh, *dl;
    int j;
    if (i < NXf4) {
        src = x; j = i; dh = gx_hi; dl = gx_lo;
    } else {
        int r = i - NXf4;
        if (r >= 4 * NWf4) return;
        int sel = r / NWf4; j = r % NWf4;
        src = (sel == 0) ? wq : (sel == 1) ? wk : (sel == 2) ? wv : wo;
        dh = gw_hi + (size_t)sel * Dv * Dv;
        dl = gw_lo + (size_t)sel * Dv * Dv;
    }
    float4 v = ((const float4*)src)[j];
    split_store4(v, dh + 4 * (size_t)j, dl + 4 * (size_t)j);
}

// ===========================================================================
// GEMM core: C[128x128] = A(hi+lo) . B(hi+lo)^T, K=512, 3-term bf16.
// 256 threads, 8 warps (2m x 4n), warp tile 64x32. K-chunk 32, 2-stage
// cp.async pipeline. smem stage: Ahi|Alo|Bhi|Blo, each 128 x 40 bf16.
// ===========================================================================
#define G_PLE   5120             // plane elems (128*40)
#define G_PLB   10240            // plane bytes
#define G_STAGE 40960            // stage bytes
#define G_BIAS  81920            // bias offset (bytes)
#define GEMM_SMEM (81920 + 512)

__device__ __forceinline__ void gemm_prefetch(
    uint32_t sb, int stage,
    const __nv_bfloat16* __restrict__ Ah, const __nv_bfloat16* __restrict__ Al,
    const __nv_bfloat16* __restrict__ Bh, const __nv_bfloat16* __restrict__ Bl,
    int k0, int t)
{
    const __nv_bfloat16* pl[4] = {Ah, Al, Bh, Bl};
    const uint32_t base = sb + stage * G_STAGE;
#pragma unroll
    for (int p = 0; p < 4; ++p) {
#pragma unroll
        for (int hh = 0; hh < 2; ++hh) {
            const int o = t + 256 * hh;       // 0..511
            const int row = o >> 2;
            const int seg = o & 3;
            cp16(base + p * G_PLB + row * 80 + seg * 16,
                 pl[p] + (size_t)row * Dv + k0 + seg * 8);
        }
    }
}

__device__ __forceinline__ void g_kstep(const char* smc, int stage, int ks,
                                        int wm, int wn, FragC (&acc)[4][2])
{
    const __nv_bfloat16* S  = (const __nv_bfloat16*)(smc + stage * G_STAGE);
    const __nv_bfloat16* Ah = S;
    const __nv_bfloat16* Al = S + G_PLE;
    const __nv_bfloat16* Bh = S + 2 * G_PLE;
    const __nv_bfloat16* Bl = S + 3 * G_PLE;

    BFragA ahi[4], alo[4];
#pragma unroll
    for (int i = 0; i < 4; ++i) {
        wmma::load_matrix_sync(ahi[i], Ah + (wm + 16 * i) * 40 + ks * 16, 40);
        wmma::load_matrix_sync(alo[i], Al + (wm + 16 * i) * 40 + ks * 16, 40);
    }
#pragma unroll
    for (int j = 0; j < 2; ++j) {
        BFragBc bhi, blo;
        wmma::load_matrix_sync(bhi, Bh + (wn + 16 * j) * 40 + ks * 16, 40);
        wmma::load_matrix_sync(blo, Bl + (wn + 16 * j) * 40 + ks * 16, 40);
#pragma unroll
        for (int i = 0; i < 4; ++i) {
            wmma::mma_sync(acc[i][j], ahi[i], bhi, acc[i][j]);
            wmma::mma_sync(acc[i][j], ahi[i], blo, acc[i][j]);
            wmma::mma_sync(acc[i][j], alo[i], bhi, acc[i][j]);
        }
    }
}

__device__ __forceinline__ void gemm_main(
    const __nv_bfloat16* __restrict__ Ah, const __nv_bfloat16* __restrict__ Al,
    const __nv_bfloat16* __restrict__ Bh, const __nv_bfloat16* __restrict__ Bl,
    char* smc, FragC (&acc)[4][2])
{
    const int t = threadIdx.x;
    const int w = t >> 5;
    const int wm = (w & 1) * 64;
    const int wn = (w >> 1) * 32;
    const uint32_t sb = (uint32_t)__cvta_generic_to_shared(smc);

#pragma unroll
    for (int i = 0; i < 4; ++i)
#pragma unroll
        for (int j = 0; j < 2; ++j)
            wmma::fill_fragment(acc[i][j], 0.0f);

    gemm_prefetch(sb, 0, Ah, Al, Bh, Bl, 0, t);
    cp_commit();

    for (int ch = 0; ch < 16; ++ch) {
        if (ch < 15) {
            gemm_prefetch(sb, (ch + 1) & 1, Ah, Al, Bh, Bl, (ch + 1) * 32, t);
            cp_commit();
            asm volatile("cp.async.wait_group 1;" ::: "memory");
        } else {
            asm volatile("cp.async.wait_group 0;" ::: "memory");
        }
        __syncthreads();                 // stage ch data visible
        g_kstep(smc, ch & 1, 0, wm, wn, acc);
        g_kstep(smc, ch & 1, 1, wm, wn, acc);
        __syncthreads();                 // readers done before overwrite
    }
}

// ---------------------------------------------------------------------------
// QKV projection. grid (128, 12). Epilogue writes head-major hi/lo planes.
// ---------------------------------------------------------------------------
__global__ __launch_bounds__(256, 2) void qkv_gemm_p(
    const float* __restrict__ bq, const float* __restrict__ bk,
    const float* __restrict__ bv)
{
    extern __shared__ char smc[];
    const int t = threadIdx.x;
    const int m0   = blockIdx.x * 128;
    const int wsel = blockIdx.y >> 2;
    const int n0   = (blockIdx.y & 3) * 128;

    const float* bias = (wsel == 0) ? bq : (wsel == 1) ? bk : bv;
    __nv_bfloat16* oh = (wsel == 0) ? gq_hi : (wsel == 1) ? gk_hi : gv_hi;
    __nv_bfloat16* ol = (wsel == 0) ? gq_lo : (wsel == 1) ? gk_lo : gv_lo;

    float* biasS = (float*)(smc + G_BIAS);
    if (t < 128) biasS[t] = bias[n0 + t];

    FragC acc[4][2];
    gemm_main(gx_hi + (size_t)m0 * Dv, gx_lo + (size_t)m0 * Dv,
              gw_hi + (size_t)wsel * Dv * Dv + (size_t)n0 * Dv,
              gw_lo + (size_t)wsel * Dv * Dv + (size_t)n0 * Dv,
              smc, acc);

    // Epilogue: frags -> smem fp32, then bias + split + head-major scatter
    float* Cs = (float*)smc;
    const int w = t >> 5;
    const int wm = (w & 1) * 64;
    const int wn = (w >> 1) * 32;
#pragma unroll
    for (int i = 0; i < 4; ++i)
#pragma unroll
        for (int j = 0; j < 2; ++j)
            wmma::store_matrix_sync(&Cs[(wm + 16 * i) * 132 + wn + 16 * j],
                                    acc[i][j], 132, wmma::mem_row_major);
    __syncthreads();

    const int row = t >> 1;
    const int c0  = (t & 1) * 64;
    const int m  = m0 + row;
    const int tb = m >> 10;
    const int n  = m & 1023;
    const int h  = (n0 + c0) >> 6;
    __nv_bfloat16* dh = oh + ((size_t)(tb * Hv + h) * Nv + n) * HDv;
    __nv_bfloat16* dl = ol + ((size_t)(tb * Hv + h) * Nv + n) * HDv;
#pragma unroll
    for (int c = 0; c < 64; c += 4) {
        float4 v = *(float4*)&Cs[row * 132 + c0 + c];
        v.x += biasS[c0 + c + 0];
        v.y += biasS[c0 + c + 1];
        v.z += biasS[c0 + c + 2];
        v.w += biasS[c0 + c + 3];
        split_store4(v, dh + c, dl + c);
    }
}

// ---------------------------------------------------------------------------
// Output projection: out = ctx @ wo^T + bo. grid (128, 4).
// ---------------------------------------------------------------------------
__global__ __launch_bounds__(256, 2) void out_gemm_p(
    const float* __restrict__ bo, float* __restrict__ out)
{
    extern __shared__ char smc[];
    const int t = threadIdx.x;
    const int m0 = blockIdx.x * 128;
    const int n0 = blockIdx.y * 128;

    float* biasS = (float*)(smc + G_BIAS);
    if (t < 128) biasS[t] = bo[n0 + t];

    FragC acc[4][2];
    gemm_main(gc_hi + (size_t)m0 * Dv, gc_lo + (size_t)m0 * Dv,
              gw_hi + (size_t)3 * Dv * Dv + (size_t)n0 * Dv,
              gw_lo + (size_t)3 * Dv * Dv + (size_t)n0 * Dv,
              smc, acc);

    float* Cs = (float*)smc;
    const int w = t >> 5;
    const int wm = (w & 1) * 64;
    const int wn = (w >> 1) * 32;
#pragma unroll
    for (int i = 0; i < 4; ++i)
#pragma unroll
        for (int j = 0; j < 2; ++j)
            wmma::store_matrix_sync(&Cs[(wm + 16 * i) * 132 + wn + 16 * j],
                                    acc[i][j], 132, wmma::mem_row_major);
    __syncthreads();

    const int row = t >> 1;
    const int c0  = (t & 1) * 64;
    const int m = m0 + row;
    float* dst = out + (size_t)m * Dv + n0 + c0;
#pragma unroll
    for (int c = 0; c < 64; c += 4) {
        float4 v = *(float4*)&Cs[row * 132 + c0 + c];
        v.x += biasS[c0 + c + 0];
        v.y += biasS[c0 + c + 1];
        v.z += biasS[c0 + c + 2];
        v.w += biasS[c0 + c + 3];
        *(float4*)(dst + c) = v;
    }
}

// ===========================================================================
// Attention (3xBF16). Block: 128 q-rows of one (tb,h); 256 threads,
// 8 warps (4m x 2n), warp 32x32. K/V tiles (64 keys) cp.async double-buffered.
// smem layout (bytes):
//   Q planes:   [0, 36864)            128x72 bf16 x2
//   KV stages:  [36864, 110592)       2 stages x 4 planes x (64x72 bf16)
//   S fp32:     [110592, 145408)      128x68 f32
//   S planes:   [145408, 182272)      128x72 bf16 x2
//   dsum:       [182272, 183296)      256 f32
// ===========================================================================
#define A_QHI  0
#define A_QLO  18432
#define A_KV   36864
#define A_KVST 36864            // stage stride (bytes)
#define A_PL   9216             // plane stride within stage (bytes)
#define A_SFP  110592
#define A_SHI  145408
#define A_SLO  163840
#define A_DS   182272
#define ATTN_SMEM 183296

__device__ __forceinline__ void kv_prefetch(uint32_t sb, int stage,
                                            size_t hb, int kt, int t)
{
    const __nv_bfloat16* pl[4] = {gk_hi + hb, gk_lo + hb, gv_hi + hb, gv_lo + hb};
    const uint32_t base = sb + A_KV + stage * A_KVST;
#pragma unroll
    for (int p = 0; p < 4; ++p) {
#pragma unroll
        for (int hh = 0; hh < 2; ++hh) {
            const int o = t + 256 * hh;       // 0..511
            const int row = o >> 3;
            const int seg = o & 7;
            cp16(base + p * A_PL + row * 144 + seg * 16,
                 pl[p] + (size_t)(kt * 64 + row) * HDv + seg * 8);
        }
    }
}

__global__ __launch_bounds__(256) void attn_p()
{
    extern __shared__ char smc[];
    const uint32_t sb = (uint32_t)__cvta_generic_to_shared(smc);
    const int t = threadIdx.x;
    const int w = t >> 5;
    const int wm = (w >> 1) * 32;     // q-rows
    const int wn = (w & 1) * 32;      // key cols (S) / hd cols (ctx)
    const int qt  = blockIdx.x;
    const int tbh = blockIdx.y;
    const int qn0 = qt * 128;
    const size_t hb = (size_t)tbh * Nv * HDv;

    // prefetch Q planes + KV tile 0 as group 0
    {
        const __nv_bfloat16* qs[2] = {gq_hi + hb, gq_lo + hb};
#pragma unroll
        for (int p = 0; p < 2; ++p) {
#pragma unroll
            for (int hh = 0; hh < 4; ++hh) {
                const int o = t + 256 * hh;       // 0..1023
                const int row = o >> 3;
                const int seg = o & 7;
                cp16(sb + A_QHI + p * 18432 + row * 144 + seg * 16,
                     qs[p] + (size_t)(qn0 + row) * HDv + seg * 8);
            }
        }
    }
    kv_prefetch(sb, 0, hb, 0, t);
    cp_commit();

    FragC ctx[2][2];
#pragma unroll
    for (int i = 0; i < 2; ++i)
#pragma unroll
        for (int j = 0; j < 2; ++j)
            wmma::fill_fragment(ctx[i][j], 0.0f);
    float dsum = 0.f;

    const __nv_bfloat16* qhi = (const __nv_bfloat16*)(smc + A_QHI);
    const __nv_bfloat16* qlo = (const __nv_bfloat16*)(smc + A_QLO);
    __nv_bfloat16* shi = (__nv_bfloat16*)(smc + A_SHI);
    __nv_bfloat16* slo = (__nv_bfloat16*)(smc + A_SLO);
    float* sfp = (float*)(smc + A_SFP);

    for (int kt = 0; kt < 16; ++kt) {
        if (kt < 15) {
            kv_prefetch(sb, (kt + 1) & 1, hb, kt + 1, t);
            cp_commit();
            asm volatile("cp.async.wait_group 1;" ::: "memory");
        } else {
            asm volatile("cp.async.wait_group 0;" ::: "memory");
        }
        __syncthreads();   // (1) tile kt K/V (and Q) visible

        const __nv_bfloat16* kh = (const __nv_bfloat16*)(smc + A_KV + (kt & 1) * A_KVST);
        const __nv_bfloat16* kl = kh + A_PL / 2;
        const __nv_bfloat16* vh = kh + A_PL;
        const __nv_bfloat16* vl = kh + 3 * A_PL / 2;

        // S = Q K^T (3xBF16)
        FragC sacc[2][2];
#pragma unroll
        for (int i = 0; i < 2; ++i)
#pragma unroll
            for (int j = 0; j < 2; ++j)
                wmma::fill_fragment(sacc[i][j], 0.0f);
#pragma unroll
        for (int ks = 0; ks < 4; ++ks) {
            BFragA fqh[2], fql[2];
#pragma unroll
            for (int i = 0; i < 2; ++i) {
                wmma::load_matrix_sync(fqh[i], qhi + (wm + 16 * i) * 72 + ks * 16, 72);
                wmma::load_matrix_sync(fql[i], qlo + (wm + 16 * i) * 72 + ks * 16, 72);
            }
#pragma unroll
            for (int j = 0; j < 2; ++j) {
                BFragBc fkh, fkl;
                wmma::load_matrix_sync(fkh, kh + (wn + 16 * j) * 72 + ks * 16, 72);
                wmma::load_matrix_sync(fkl, kl + (wn + 16 * j) * 72 + ks * 16, 72);
#pragma unroll
                for (int i = 0; i < 2; ++i) {
                    wmma::mma_sync(sacc[i][j], fqh[i], fkh, sacc[i][j]);
                    wmma::mma_sync(sacc[i][j], fqh[i], fkl, sacc[i][j]);
                    wmma::mma_sync(sacc[i][j], fql[i], fkh, sacc[i][j]);
                }
            }
        }
#pragma unroll
        for (int i = 0; i < 2; ++i)
#pragma unroll
            for (int j = 0; j < 2; ++j)
                wmma::store_matrix_sync(&sfp[(wm + 16 * i) * 68 + wn + 16 * j],
                                        sacc[i][j], 68, wmma::mem_row_major);
        __syncthreads();   // (2) S fp32 staged

        // relu * 0.125, rowsum partial, split hi/lo
        {
            const int row = t >> 1;
            const int c0  = (t & 1) * 32;
#pragma unroll
            for (int u = 0; u < 8; ++u) {
                float4 s = *(const float4*)&sfp[row * 68 + c0 + 4 * u];
                s.x = fmaxf(s.x * 0.125f, 0.f);
                s.y = fmaxf(s.y * 0.125f, 0.f);
                s.z = fmaxf(s.z * 0.125f, 0.f);
                s.w = fmaxf(s.w * 0.125f, 0.f);
                dsum += s.x + s.y + s.z + s.w;
                split_store4(s, shi + row * 72 + c0 + 4 * u,
                                slo + row * 72 + c0 + 4 * u);
            }
        }
        __syncthreads();   // (3) S planes ready

        // ctx += S V (3xBF16)
#pragma unroll
        for (int ks = 0; ks < 4; ++ks) {
            BFragA fsh[2], fsl[2];
#pragma unroll
            for (int i = 0; i < 2; ++i) {
                wmma::load_matrix_sync(fsh[i], shi + (wm + 16 * i) * 72 + ks * 16, 72);
                wmma::load_matrix_sync(fsl[i], slo + (wm + 16 * i) * 72 + ks * 16, 72);
            }
#pragma unroll
            for (int j = 0; j < 2; ++j) {
                BFragBr fvh, fvl;
                wmma::load_matrix_sync(fvh, vh + ks * 16 * 72 + wn + 16 * j, 72);
                wmma::load_matrix_sync(fvl, vl + ks * 16 * 72 + wn + 16 * j, 72);
#pragma unroll
                for (int i = 0; i < 2; ++i) {
                    wmma::mma_sync(ctx[i][j], fsh[i], fvh, ctx[i][j]);
                    wmma::mma_sync(ctx[i][j], fsh[i], fvl, ctx[i][j]);
                    wmma::mma_sync(ctx[i][j], fsl[i], fvh, ctx[i][j]);
                }
            }
        }
        __syncthreads();   // (4) KV stage / S planes free for reuse
    }

    // Epilogue: rowsum reduce, normalize, write ctx hi/lo planes token-major
    ((float*)(smc + A_DS))[t] = dsum;
#pragma unroll
    for (int i = 0; i < 2; ++i)
#pragma unroll
        for (int j = 0; j < 2; ++j)
            wmma::store_matrix_sync(&sfp[(wm + 16 * i) * 68 + wn + 16 * j],
                                    ctx[i][j], 68, wmma::mem_row_major);
    __syncthreads();

    {
        const float* dso = (const float*)(smc + A_DS);
        const int row = t >> 1;
        const int c0  = (t & 1) * 32;
        const float den = dso[2 * row] + dso[2 * row + 1];
        const float inv = 1.f / (den + 1e-6f);
        const int m = (tbh >> 3) * Nv + qn0 + row;
        __nv_bfloat16* dh = gc_hi + (size_t)m * Dv + (tbh & 7) * HDv + c0;
        __nv_bfloat16* dl = gc_lo + (size_t)m * Dv + (tbh & 7) * HDv + c0;
#pragma unroll
        for (int u = 0; u < 8; ++u) {
            float4 v = *(const float4*)&sfp[row * 68 + c0 + 4 * u];
            v.x *= inv; v.y *= inv; v.z *= inv; v.w *= inv;
            split_store4(v, dh + 4 * u, dl + 4 * u);
        }
    }
}

// ---------------------------------------------------------------------------
extern "C" void kernel_launch(void* const* d_in, const int* in_sizes, int n_in,
                              void* d_out, int out_size)
{
    const float* x  = (const float*)d_in[0];
    const float* wq = (const float*)d_in[1];
    const float* bq = (const float*)d_in[2];
    const float* wk = (const float*)d_in[3];
    const float* bk = (const float*)d_in[4];
    const float* wv = (const float*)d_in[5];
    const float* bv = (const float*)d_in[6];
    const float* wo = (const float*)d_in[7];
    const float* bo = (const float*)d_in[8];
    float* out = (float*)d_out;

    cudaFuncSetAttribute(qkv_gemm_p, cudaFuncAttributeMaxDynamicSharedMemorySize,
                         GEMM_SMEM);
    cudaFuncSetAttribute(out_gemm_p, cudaFuncAttributeMaxDynamicSharedMemorySize,
                         GEMM_SMEM);
    cudaFuncSetAttribute(attn_p, cudaFuncAttributeMaxDynamicSharedMemorySize,
                         ATTN_SMEM);

    const int splitBlocks = (NXf4 + 4 * NWf4 + 255) / 256;   // 9216
    split_kernel<<<splitBlocks, 256>>>(x, wq, wk, wv, wo);
    qkv_gemm_p<<<dim3(Mv / 128, 12), 256, GEMM_SMEM>>>(bq, bk, bv);
    attn_p<<<dim3(Nv / 128, TBv * Hv), 256, ATTN_SMEM>>>();
    out_gemm_p<<<dim3(Mv / 128, Dv / 128), 256, GEMM_SMEM>>>(bo, out);
}

// round 8
// speedup vs baseline: 1.0294x; 1.0294x over previous
#include <cuda_runtime.h>
#include <cuda_bf16.h>
#include <mma.h>
#include <cstdint>

using namespace nvcuda;

#define TBv 16
#define Nv  1024
#define Dv  512
#define Hv  8
#define HDv 64
#define Mv  (TBv * Nv)

__device__ __nv_bfloat16 gx_hi[(size_t)Mv * Dv], gx_lo[(size_t)Mv * Dv];
__device__ __nv_bfloat16 gw_hi[4 * Dv * Dv],     gw_lo[4 * Dv * Dv];
__device__ __nv_bfloat16 gq_hi[(size_t)Mv * Dv], gq_lo[(size_t)Mv * Dv];
__device__ __nv_bfloat16 gk_hi[(size_t)Mv * Dv], gk_lo[(size_t)Mv * Dv];
__device__ __nv_bfloat16 gv_hi[(size_t)Mv * Dv], gv_lo[(size_t)Mv * Dv];
__device__ __nv_bfloat16 gc_hi[(size_t)Mv * Dv], gc_lo[(size_t)Mv * Dv];

__device__ __forceinline__ uint32_t pack_bf2(__nv_bfloat16 a, __nv_bfloat16 b) {
    __nv_bfloat162 p = __halves2bfloat162(a, b);
    return *(uint32_t*)&p;
}
__device__ __forceinline__ void split_store4(float4 v,
                                             __nv_bfloat16* __restrict__ hp,
                                             __nv_bfloat16* __restrict__ lp)
{
    __nv_bfloat16 hx = __float2bfloat16_rn(v.x), hy = __float2bfloat16_rn(v.y);
    __nv_bfloat16 hz = __float2bfloat16_rn(v.z), hw = __float2bfloat16_rn(v.w);
    ((uint32_t*)hp)[0] = pack_bf2(hx, hy);
    ((uint32_t*)hp)[1] = pack_bf2(hz, hw);
    ((uint32_t*)lp)[0] = pack_bf2(__float2bfloat16_rn(v.x - __bfloat162float(hx)),
                                  __float2bfloat16_rn(v.y - __bfloat162float(hy)));
    ((uint32_t*)lp)[1] = pack_bf2(__float2bfloat16_rn(v.z - __bfloat162float(hz)),
                                  __float2bfloat16_rn(v.w - __bfloat162float(hw)));
}
__device__ __forceinline__ void cp16(uint32_t dst, const void* src) {
    asm volatile("cp.async.cg.shared.global [%0], [%1], 16;" :: "r"(dst), "l"(src));
}
__device__ __forceinline__ void cp_commit() {
    asm volatile("cp.async.commit_group;" ::: "memory");
}
__device__ __forceinline__ void cp_wait0() {
    asm volatile("cp.async.wait_group 0;" ::: "memory");
}
__device__ __forceinline__ void ldsm4(uint32_t (&r)[4], uint32_t a) {
    asm volatile("ldmatrix.sync.aligned.m8n8.x4.shared.b16 {%0,%1,%2,%3}, [%4];"
                 : "=r"(r[0]), "=r"(r[1]), "=r"(r[2]), "=r"(r[3]) : "r"(a));
}
__device__ __forceinline__ void ldsm4t(uint32_t (&r)[4], uint32_t a) {
    asm volatile("ldmatrix.sync.aligned.m8n8.x4.trans.shared.b16 {%0,%1,%2,%3}, [%4];"
                 : "=r"(r[0]), "=r"(r[1]), "=r"(r[2]), "=r"(r[3]) : "r"(a));
}
__device__ __forceinline__ void mma16816(float (&c)[4], const uint32_t (&a)[4],
                                         uint32_t b0, uint32_t b1) {
    asm volatile(
        "mma.sync.aligned.m16n8k16.row.col.f32.bf16.bf16.f32 "
        "{%0,%1,%2,%3}, {%4,%5,%6,%7}, {%8,%9}, {%0,%1,%2,%3};"
        : "+f"(c[0]), "+f"(c[1]), "+f"(c[2]), "+f"(c[3])
        : "r"(a[0]), "r"(a[1]), "r"(a[2]), "r"(a[3]), "r"(b0), "r"(b1));
}

using BFragA  = wmma::fragment<wmma::matrix_a, 16, 16, 16, __nv_bfloat16, wmma::row_major>;
using BFragBc = wmma::fragment<wmma::matrix_b, 16, 16, 16, __nv_bfloat16, wmma::col_major>;
using FragC   = wmma::fragment<wmma::accumulator, 16, 16, 16, float>;

// ---------------------------------------------------------------------------
#define NXf4 (Mv * Dv / 4)
#define NWf4 (Dv * Dv / 4)

__global__ __launch_bounds__(256) void split_kernel(
    const float* __restrict__ x,
    const float* __restrict__ wq, const float* __restrict__ wk,
    const float* __restrict__ wv, const float* __restrict__ wo)
{
    int i = blockIdx.x * 256 + threadIdx.x;
    const float* src; __nv_bfloat16 *dh, *dl; int j;
    if (i < NXf4) { src = x; j = i; dh = gx_hi; dl = gx_lo; }
    else {
        int r = i - NXf4;
        if (r >= 4 * NWf4) return;
        int sel = r / NWf4; j = r % NWf4;
        src = (sel == 0) ? wq : (sel == 1) ? wk : (sel == 2) ? wv : wo;
        dh = gw_hi + (size_t)sel * Dv * Dv;
        dl = gw_lo + (size_t)sel * Dv * Dv;
    }
    float4 v = ((const float4*)src)[j];
    split_store4(v, dh + 4 * (size_t)j, dl + 4 * (size_t)j);
}

// ===========================================================================
// GEMM: C[128x128] = A(hi+lo).B(hi+lo)^T, K=512. 256 thr, 8 warps (2m x 4n),
// warp 64x32. Chunk 32, reg-staged single-sync double buffer.
// ===========================================================================
#define G_PLB   10240
#define G_STG   40960
#define G_BIAS  81920
#define GEMM_SMEM (81920 + 512)

__device__ __forceinline__ void g_ldg(
    const __nv_bfloat16* __restrict__ Ah, const __nv_bfloat16* __restrict__ Al,
    const __nv_bfloat16* __restrict__ Bh, const __nv_bfloat16* __restrict__ Bl,
    int k0, int t, uint4 (&r)[8])
{
#pragma unroll
    for (int hh = 0; hh < 2; ++hh) {
        const int o = t + 256 * hh;
        const size_t off = (size_t)(o >> 2) * Dv + k0 + (o & 3) * 8;
        r[0 + hh] = *(const uint4*)(Ah + off);
        r[2 + hh] = *(const uint4*)(Al + off);
        r[4 + hh] = *(const uint4*)(Bh + off);
        r[6 + hh] = *(const uint4*)(Bl + off);
    }
}
__device__ __forceinline__ void g_sts(char* smc, int stage, int t,
                                      const uint4 (&r)[8])
{
    char* base = smc + stage * G_STG;
#pragma unroll
    for (int hh = 0; hh < 2; ++hh) {
        const int o = t + 256 * hh;
        const int off = (o >> 2) * 80 + (o & 3) * 16;
        *(uint4*)(base + off)             = r[0 + hh];
        *(uint4*)(base + G_PLB + off)     = r[2 + hh];
        *(uint4*)(base + 2 * G_PLB + off) = r[4 + hh];
        *(uint4*)(base + 3 * G_PLB + off) = r[6 + hh];
    }
}
__device__ __forceinline__ void g_kstep(const char* smc, int stage, int ks,
                                        int wm, int wn, FragC (&acc)[4][2])
{
    const __nv_bfloat16* S  = (const __nv_bfloat16*)(smc + stage * G_STG);
    BFragA ahi[4], alo[4];
#pragma unroll
    for (int i = 0; i < 4; ++i) {
        wmma::load_matrix_sync(ahi[i], S + (wm + 16 * i) * 40 + ks * 16, 40);
        wmma::load_matrix_sync(alo[i], S + 5120 + (wm + 16 * i) * 40 + ks * 16, 40);
    }
#pragma unroll
    for (int j = 0; j < 2; ++j) {
        BFragBc bhi, blo;
        wmma::load_matrix_sync(bhi, S + 10240 + (wn + 16 * j) * 40 + ks * 16, 40);
        wmma::load_matrix_sync(blo, S + 15360 + (wn + 16 * j) * 40 + ks * 16, 40);
#pragma unroll
        for (int i = 0; i < 4; ++i) {
            wmma::mma_sync(acc[i][j], ahi[i], bhi, acc[i][j]);
            wmma::mma_sync(acc[i][j], ahi[i], blo, acc[i][j]);
            wmma::mma_sync(acc[i][j], alo[i], bhi, acc[i][j]);
        }
    }
}
__device__ __forceinline__ void gemm_main(
    const __nv_bfloat16* __restrict__ Ah, const __nv_bfloat16* __restrict__ Al,
    const __nv_bfloat16* __restrict__ Bh, const __nv_bfloat16* __restrict__ Bl,
    char* smc, FragC (&acc)[4][2])
{
    const int t = threadIdx.x;
    const int w = t >> 5;
    const int wm = (w & 1) * 64;
    const int wn = (w >> 1) * 32;
#pragma unroll
    for (int i = 0; i < 4; ++i)
#pragma unroll
        for (int j = 0; j < 2; ++j)
            wmma::fill_fragment(acc[i][j], 0.0f);

    uint4 rg[8];
    g_ldg(Ah, Al, Bh, Bl, 0, t, rg);
    g_sts(smc, 0, t, rg);
    g_ldg(Ah, Al, Bh, Bl, 32, t, rg);
    __syncthreads();
    for (int c = 0; c < 16; ++c) {
        if (c < 15) g_sts(smc, (c + 1) & 1, t, rg);
        if (c < 14) g_ldg(Ah, Al, Bh, Bl, (c + 2) * 32, t, rg);
        g_kstep(smc, c & 1, 0, wm, wn, acc);
        g_kstep(smc, c & 1, 1, wm, wn, acc);
        __syncthreads();
    }
}

__global__ __launch_bounds__(256, 2) void qkv_gemm_p(
    const float* __restrict__ bq, const float* __restrict__ bk,
    const float* __restrict__ bv)
{
    extern __shared__ char smc[];
    const int t = threadIdx.x;
    const int m0   = blockIdx.x * 128;
    const int wsel = blockIdx.y >> 2;
    const int n0   = (blockIdx.y & 3) * 128;

    const float* bias = (wsel == 0) ? bq : (wsel == 1) ? bk : bv;
    __nv_bfloat16* oh = (wsel == 0) ? gq_hi : (wsel == 1) ? gk_hi : gv_hi;
    __nv_bfloat16* ol = (wsel == 0) ? gq_lo : (wsel == 1) ? gk_lo : gv_lo;

    float* biasS = (float*)(smc + G_BIAS);
    if (t < 128) biasS[t] = bias[n0 + t];

    FragC acc[4][2];
    gemm_main(gx_hi + (size_t)m0 * Dv, gx_lo + (size_t)m0 * Dv,
              gw_hi + (size_t)wsel * Dv * Dv + (size_t)n0 * Dv,
              gw_lo + (size_t)wsel * Dv * Dv + (size_t)n0 * Dv, smc, acc);

    float* Cs = (float*)smc;
    const int w = t >> 5, wm = (w & 1) * 64, wn = (w >> 1) * 32;
#pragma unroll
    for (int i = 0; i < 4; ++i)
#pragma unroll
        for (int j = 0; j < 2; ++j)
            wmma::store_matrix_sync(&Cs[(wm + 16 * i) * 132 + wn + 16 * j],
                                    acc[i][j], 132, wmma::mem_row_major);
    __syncthreads();

    const int row = t >> 1, c0 = (t & 1) * 64;
    const int m = m0 + row, tb = m >> 10, n = m & 1023;
    const int h = (n0 + c0) >> 6;
    __nv_bfloat16* dh = oh + ((size_t)(tb * Hv + h) * Nv + n) * HDv;
    __nv_bfloat16* dl = ol + ((size_t)(tb * Hv + h) * Nv + n) * HDv;
#pragma unroll
    for (int c = 0; c < 64; c += 4) {
        float4 v = *(float4*)&Cs[row * 132 + c0 + c];
        v.x += biasS[c0 + c + 0]; v.y += biasS[c0 + c + 1];
        v.z += biasS[c0 + c + 2]; v.w += biasS[c0 + c + 3];
        split_store4(v, dh + c, dl + c);
    }
}

__global__ __launch_bounds__(256, 2) void out_gemm_p(
    const float* __restrict__ bo, float* __restrict__ out)
{
    extern __shared__ char smc[];
    const int t = threadIdx.x;
    const int m0 = blockIdx.x * 128;
    const int n0 = blockIdx.y * 128;

    float* biasS = (float*)(smc + G_BIAS);
    if (t < 128) biasS[t] = bo[n0 + t];

    FragC acc[4][2];
    gemm_main(gc_hi + (size_t)m0 * Dv, gc_lo + (size_t)m0 * Dv,
              gw_hi + (size_t)3 * Dv * Dv + (size_t)n0 * Dv,
              gw_lo + (size_t)3 * Dv * Dv + (size_t)n0 * Dv, smc, acc);

    float* Cs = (float*)smc;
    const int w = t >> 5, wm = (w & 1) * 64, wn = (w >> 1) * 32;
#pragma unroll
    for (int i = 0; i < 4; ++i)
#pragma unroll
        for (int j = 0; j < 2; ++j)
            wmma::store_matrix_sync(&Cs[(wm + 16 * i) * 132 + wn + 16 * j],
                                    acc[i][j], 132, wmma::mem_row_major);
    __syncthreads();

    const int row = t >> 1, c0 = (t & 1) * 64;
    float* dst = out + (size_t)(m0 + row) * Dv + n0 + c0;
#pragma unroll
    for (int c = 0; c < 64; c += 4) {
        float4 v = *(float4*)&Cs[row * 132 + c0 + c];
        v.x += biasS[c0 + c + 0]; v.y += biasS[c0 + c + 1];
        v.z += biasS[c0 + c + 2]; v.w += biasS[c0 + c + 3];
        *(float4*)(dst + c) = v;
    }
}

// ===========================================================================
// Attention: raw mma.sync m16n8k16, S in registers. 512 thr, 16 warps;
// block = 256 q-rows of one (tb,h); warp = 16 q-rows x 64 keys x 64 hd.
// One __syncthreads per key-tile; K/V cp.async one tile ahead.
// ===========================================================================
#define AT_Q    0
#define AT_KV   73728
#define AT_STG  36864
#define AT_PL   9216
#define ATTN_SMEM 147456

__device__ __forceinline__ void kv_prefetch(uint32_t dstbase, size_t hb,
                                            int row0, int t)
{
    const __nv_bfloat16* kvp[4] = {gk_hi + hb, gk_lo + hb, gv_hi + hb, gv_lo + hb};
#pragma unroll
    for (int hh = 0; hh < 4; ++hh) {
        const int o = t + 512 * hh;
        const int plane = o >> 9;
        const int idx = o & 511;
        cp16(dstbase + plane * AT_PL + (idx >> 3) * 144 + (idx & 7) * 16,
             kvp[plane] + (size_t)(row0 + (idx >> 3)) * HDv + (idx & 7) * 8);
    }
}

__global__ __launch_bounds__(512, 1) void attn_m()
{
    extern __shared__ char smc[];
    const uint32_t sb = (uint32_t)__cvta_generic_to_shared(smc);
    const int t = threadIdx.x;
    const int l = t & 31;
    const int w = t >> 5;
    const int qn0 = blockIdx.x * 256;
    const int tbh = blockIdx.y;
    const size_t hb = (size_t)tbh * Nv * HDv;

    // prefetch Q planes (2 x 256 x 64) + KV tile 0
#pragma unroll
    for (int hh = 0; hh < 8; ++hh) {
        const int o = t + 512 * hh;
        const int plane = o >> 11;
        const int idx = o & 2047;
        const __nv_bfloat16* src =
            (plane ? gq_lo : gq_hi) + hb + (size_t)(qn0 + (idx >> 3)) * HDv + (idx & 7) * 8;
        cp16(sb + AT_Q + plane * 36864 + (idx >> 3) * 144 + (idx & 7) * 16, src);
    }
    kv_prefetch(sb + AT_KV, hb, 0, t);
    cp_commit();

    const int wrow = w * 16;
    const uint32_t qaddr = sb + AT_Q + (wrow + (l & 15)) * 144 + (l >> 4) * 16;
    const int kroff = ((l & 7) + ((l >> 4) & 1) * 8) * 144 + ((l >> 3) & 1) * 16;
    const int vroff = ((l & 7) + ((l >> 3) & 1) * 8) * 144 + ((l >> 4) & 1) * 16;

    float ctx[8][4];
#pragma unroll
    for (int i = 0; i < 8; ++i)
#pragma unroll
        for (int j = 0; j < 4; ++j) ctx[i][j] = 0.f;
    float ds0 = 0.f, ds1 = 0.f;

    for (int kt = 0; kt < 16; ++kt) {
        cp_wait0();
        __syncthreads();
        if (kt < 15) {
            kv_prefetch(sb + AT_KV + ((kt + 1) & 1) * AT_STG, hb, (kt + 1) * 64, t);
            cp_commit();
        }
        const uint32_t kst = sb + AT_KV + (kt & 1) * AT_STG;

        // S = Q K^T (3xBF16), S in registers
        float sacc[8][4];
#pragma unroll
        for (int i = 0; i < 8; ++i)
#pragma unroll
            for (int j = 0; j < 4; ++j) sacc[i][j] = 0.f;
#pragma unroll
        for (int ks = 0; ks < 4; ++ks) {
            uint32_t aqh[4], aql[4];
            ldsm4(aqh, qaddr + ks * 32);
            ldsm4(aql, qaddr + 36864 + ks * 32);
#pragma unroll
            for (int np = 0; np < 4; ++np) {
                uint32_t bh[4], bl[4];
                ldsm4(bh, kst + np * 16 * 144 + kroff + ks * 32);
                ldsm4(bl, kst + AT_PL + np * 16 * 144 + kroff + ks * 32);
                mma16816(sacc[2 * np],     aqh, bh[0], bh[1]);
                mma16816(sacc[2 * np],     aqh, bl[0], bl[1]);
                mma16816(sacc[2 * np],     aql, bh[0], bh[1]);
                mma16816(sacc[2 * np + 1], aqh, bh[2], bh[3]);
                mma16816(sacc[2 * np + 1], aqh, bl[2], bl[3]);
                mma16816(sacc[2 * np + 1], aql, bh[2], bh[3]);
            }
        }

        // relu/scale/rowsum/split in registers, then ctx += S V
#pragma unroll
        for (int kf = 0; kf < 4; ++kf) {
            uint32_t sah[4], sal[4];
#pragma unroll
            for (int hh = 0; hh < 2; ++hh) {
                float* c = sacc[2 * kf + hh];
                float c0 = fmaxf(c[0] * 0.125f, 0.f);
                float c1 = fmaxf(c[1] * 0.125f, 0.f);
                float c2 = fmaxf(c[2] * 0.125f, 0.f);
                float c3 = fmaxf(c[3] * 0.125f, 0.f);
                ds0 += c0 + c1;
                ds1 += c2 + c3;
                __nv_bfloat16 h0 = __float2bfloat16_rn(c0);
                __nv_bfloat16 h1 = __float2bfloat16_rn(c1);
                __nv_bfloat16 h2 = __float2bfloat16_rn(c2);
                __nv_bfloat16 h3 = __float2bfloat16_rn(c3);
                sah[2 * hh + 0] = pack_bf2(h0, h1);
                sah[2 * hh + 1] = pack_bf2(h2, h3);
                sal[2 * hh + 0] = pack_bf2(
                    __float2bfloat16_rn(c0 - __bfloat162float(h0)),
                    __float2bfloat16_rn(c1 - __bfloat162float(h1)));
                sal[2 * hh + 1] = pack_bf2(
                    __float2bfloat16_rn(c2 - __bfloat162float(h2)),
                    __float2bfloat16_rn(c3 - __bfloat162float(h3)));
            }
#pragma unroll
            for (int np = 0; np < 4; ++np) {
                uint32_t bvh[4], bvl[4];
                ldsm4t(bvh, kst + 2 * AT_PL + kf * 16 * 144 + vroff + np * 32);
                ldsm4t(bvl, kst + 3 * AT_PL + kf * 16 * 144 + vroff + np * 32);
                mma16816(ctx[2 * np],     sah, bvh[0], bvh[1]);
                mma16816(ctx[2 * np],     sah, bvl[0], bvl[1]);
                mma16816(ctx[2 * np],     sal, bvh[0], bvh[1]);
                mma16816(ctx[2 * np + 1], sah, bvh[2], bvh[3]);
                mma16816(ctx[2 * np + 1], sah, bvl[2], bvl[3]);
                mma16816(ctx[2 * np + 1], sal, bvh[2], bvh[3]);
            }
        }
    }

    // epilogue: quad-reduce rowsums, normalize, write ctx planes
    ds0 += __shfl_xor_sync(0xffffffffu, ds0, 1);
    ds0 += __shfl_xor_sync(0xffffffffu, ds0, 2);
    ds1 += __shfl_xor_sync(0xffffffffu, ds1, 1);
    ds1 += __shfl_xor_sync(0xffffffffu, ds1, 2);
    const float inv0 = 1.f / (ds0 + 1e-6f);
    const float inv1 = 1.f / (ds1 + 1e-6f);

    const int g = l >> 2, tg = l & 3;
    const int mtok = (tbh >> 3) * Nv + qn0 + wrow + g;
    const int hd0 = (tbh & 7) * HDv;
    __nv_bfloat16* dh0 = gc_hi + (size_t)mtok * Dv + hd0;
    __nv_bfloat16* dl0 = gc_lo + (size_t)mtok * Dv + hd0;
    __nv_bfloat16* dh1 = dh0 + 8 * Dv;
    __nv_bfloat16* dl1 = dl0 + 8 * Dv;
#pragma unroll
    for (int i = 0; i < 8; ++i) {
        const int d = (i >> 1) * 16 + (i & 1) * 8 + tg * 2;
        float v0 = ctx[i][0] * inv0, v1 = ctx[i][1] * inv0;
        float v2 = ctx[i][2] * inv1, v3 = ctx[i][3] * inv1;
        __nv_bfloat16 h0 = __float2bfloat16_rn(v0);
        __nv_bfloat16 h1 = __float2bfloat16_rn(v1);
        __nv_bfloat16 h2 = __float2bfloat16_rn(v2);
        __nv_bfloat16 h3 = __float2bfloat16_rn(v3);
        *(uint32_t*)(dh0 + d) = pack_bf2(h0, h1);
        *(uint32_t*)(dl0 + d) = pack_bf2(
            __float2bfloat16_rn(v0 - __bfloat162float(h0)),
            __float2bfloat16_rn(v1 - __bfloat162float(h1)));
        *(uint32_t*)(dh1 + d) = pack_bf2(h2, h3);
        *(uint32_t*)(dl1 + d) = pack_bf2(
            __float2bfloat16_rn(v2 - __bfloat162float(h2)),
            __float2bfloat16_rn(v3 - __bfloat162float(h3)));
    }
}

// ---------------------------------------------------------------------------
extern "C" void kernel_launch(void* const* d_in, const int* in_sizes, int n_in,
                              void* d_out, int out_size)
{
    const float* x  = (const float*)d_in[0];
    const float* wq = (const float*)d_in[1];
    const float* bq = (const float*)d_in[2];
    const float* wk = (const float*)d_in[3];
    const float* bk = (const float*)d_in[4];
    const float* wv = (const float*)d_in[5];
    const float* bv = (const float*)d_in[6];
    const float* wo = (const float*)d_in[7];
    const float* bo = (const float*)d_in[8];
    float* out = (float*)d_out;

    cudaFuncSetAttribute(qkv_gemm_p, cudaFuncAttributeMaxDynamicSharedMemorySize, GEMM_SMEM);
    cudaFuncSetAttribute(out_gemm_p, cudaFuncAttributeMaxDynamicSharedMemorySize, GEMM_SMEM);
    cudaFuncSetAttribute(attn_m, cudaFuncAttributeMaxDynamicSharedMemorySize, ATTN_SMEM);

    const int splitBlocks = (NXf4 + 4 * NWf4 + 255) / 256;
    split_kernel<<<splitBlocks, 256>>>(x, wq, wk, wv, wo);
    qkv_gemm_p<<<dim3(Mv / 128, 12), 256, GEMM_SMEM>>>(bq, bk, bv);
    attn_m<<<dim3(Nv / 256, TBv * Hv), 512, ATTN_SMEM>>>();
    out_gemm_p<<<dim3(Mv / 128, Dv / 128), 256, GEMM_SMEM>>>(bo, out);
}

// round 9
// speedup vs baseline: 1.0692x; 1.0387x over previous
#include <cuda_runtime.h>
#include <cuda_bf16.h>
#include <mma.h>
#include <cstdint>

using namespace nvcuda;

#define TBv 16
#define Nv  1024
#define Dv  512
#define Hv  8
#define HDv 64
#define Mv  (TBv * Nv)

__device__ __nv_bfloat16 gx_hi[(size_t)Mv * Dv], gx_lo[(size_t)Mv * Dv];
__device__ __nv_bfloat16 gw_hi[4 * Dv * Dv],     gw_lo[4 * Dv * Dv];
__device__ __nv_bfloat16 gq_hi[(size_t)Mv * Dv], gq_lo[(size_t)Mv * Dv];
__device__ __nv_bfloat16 gk_hi[(size_t)Mv * Dv], gk_lo[(size_t)Mv * Dv];
__device__ __nv_bfloat16 gv_hi[(size_t)Mv * Dv], gv_lo[(size_t)Mv * Dv];
__device__ __nv_bfloat16 gc_hi[(size_t)Mv * Dv], gc_lo[(size_t)Mv * Dv];

__device__ __forceinline__ uint32_t pack_bf2(__nv_bfloat16 a, __nv_bfloat16 b) {
    __nv_bfloat162 p = __halves2bfloat162(a, b);
    return *(uint32_t*)&p;
}
__device__ __forceinline__ void split_store4(float4 v,
                                             __nv_bfloat16* __restrict__ hp,
                                             __nv_bfloat16* __restrict__ lp)
{
    __nv_bfloat16 hx = __float2bfloat16_rn(v.x), hy = __float2bfloat16_rn(v.y);
    __nv_bfloat16 hz = __float2bfloat16_rn(v.z), hw = __float2bfloat16_rn(v.w);
    ((uint32_t*)hp)[0] = pack_bf2(hx, hy);
    ((uint32_t*)hp)[1] = pack_bf2(hz, hw);
    ((uint32_t*)lp)[0] = pack_bf2(__float2bfloat16_rn(v.x - __bfloat162float(hx)),
                                  __float2bfloat16_rn(v.y - __bfloat162float(hy)));
    ((uint32_t*)lp)[1] = pack_bf2(__float2bfloat16_rn(v.z - __bfloat162float(hz)),
                                  __float2bfloat16_rn(v.w - __bfloat162float(hw)));
}
__device__ __forceinline__ void cp16(uint32_t dst, const void* src) {
    asm volatile("cp.async.cg.shared.global [%0], [%1], 16;" :: "r"(dst), "l"(src));
}
__device__ __forceinline__ void cp_commit() {
    asm volatile("cp.async.commit_group;" ::: "memory");
}
__device__ __forceinline__ void ldsm4(uint32_t (&r)[4], uint32_t a) {
    asm volatile("ldmatrix.sync.aligned.m8n8.x4.shared.b16 {%0,%1,%2,%3}, [%4];"
                 : "=r"(r[0]), "=r"(r[1]), "=r"(r[2]), "=r"(r[3]) : "r"(a));
}
__device__ __forceinline__ void ldsm4t(uint32_t (&r)[4], uint32_t a) {
    asm volatile("ldmatrix.sync.aligned.m8n8.x4.trans.shared.b16 {%0,%1,%2,%3}, [%4];"
                 : "=r"(r[0]), "=r"(r[1]), "=r"(r[2]), "=r"(r[3]) : "r"(a));
}
__device__ __forceinline__ void mma16816(float (&c)[4], const uint32_t (&a)[4],
                                         uint32_t b0, uint32_t b1) {
    asm volatile(
        "mma.sync.aligned.m16n8k16.row.col.f32.bf16.bf16.f32 "
        "{%0,%1,%2,%3}, {%4,%5,%6,%7}, {%8,%9}, {%0,%1,%2,%3};"
        : "+f"(c[0]), "+f"(c[1]), "+f"(c[2]), "+f"(c[3])
        : "r"(a[0]), "r"(a[1]), "r"(a[2]), "r"(a[3]), "r"(b0), "r"(b1));
}

using BFragA  = wmma::fragment<wmma::matrix_a, 16, 16, 16, __nv_bfloat16, wmma::row_major>;
using BFragBc = wmma::fragment<wmma::matrix_b, 16, 16, 16, __nv_bfloat16, wmma::col_major>;
using FragC   = wmma::fragment<wmma::accumulator, 16, 16, 16, float>;

// ---------------------------------------------------------------------------
#define NXf4 (Mv * Dv / 4)
#define NWf4 (Dv * Dv / 4)

__global__ __launch_bounds__(256) void split_kernel(
    const float* __restrict__ x,
    const float* __restrict__ wq, const float* __restrict__ wk,
    const float* __restrict__ wv, const float* __restrict__ wo)
{
    int i = blockIdx.x * 256 + threadIdx.x;
    const float* src; __nv_bfloat16 *dh, *dl; int j;
    if (i < NXf4) { src = x; j = i; dh = gx_hi; dl = gx_lo; }
    else {
        int r = i - NXf4;
        if (r >= 4 * NWf4) return;
        int sel = r / NWf4; j = r % NWf4;
        src = (sel == 0) ? wq : (sel == 1) ? wk : (sel == 2) ? wv : wo;
        dh = gw_hi + (size_t)sel * Dv * Dv;
        dl = gw_lo + (size_t)sel * Dv * Dv;
    }
    float4 v = ((const float4*)src)[j];
    split_store4(v, dh + 4 * (size_t)j, dl + 4 * (size_t)j);
}

// ===========================================================================
// GEMM: C[128x128] = A(hi+lo).B(hi+lo)^T, K=512. 256 thr, 8 warps (2m x 4n),
// warp 64x32. Chunk K=16, 4-stage cp.async ring, loads 3 chunks ahead,
// ONE __syncthreads per chunk. Stage: 4 planes x 128 rows x 24 elems (48B).
// ===========================================================================
#define G_PLE  3072               // plane elems (128*24)
#define G_PLB  6144               // plane bytes
#define G_STG  24576              // stage bytes
#define G_BIAS 98304
#define GEMM_SMEM (98304 + 512)

__device__ __forceinline__ void g_prefetch(
    uint32_t sb, int stage,
    const __nv_bfloat16* __restrict__ Ah, const __nv_bfloat16* __restrict__ Al,
    const __nv_bfloat16* __restrict__ Bh, const __nv_bfloat16* __restrict__ Bl,
    int k0, int t)
{
    const __nv_bfloat16* pl[4] = {Ah, Al, Bh, Bl};
    const uint32_t base = sb + stage * G_STG;
#pragma unroll
    for (int hh = 0; hh < 4; ++hh) {
        const int o = t + 256 * hh;        // 0..1023
        const int plane = o >> 8;
        const int idx = o & 255;
        const int row = idx >> 1, seg = idx & 1;
        cp16(base + plane * G_PLB + row * 48 + seg * 16,
             pl[plane] + (size_t)row * Dv + k0 + seg * 8);
    }
}

__device__ __forceinline__ void g_kstep(const char* smc, int stage,
                                        int wm, int wn, FragC (&acc)[4][2])
{
    const __nv_bfloat16* S = (const __nv_bfloat16*)(smc + stage * G_STG);
    BFragA ahi[4], alo[4];
#pragma unroll
    for (int i = 0; i < 4; ++i) {
        wmma::load_matrix_sync(ahi[i], S + (wm + 16 * i) * 24, 24);
        wmma::load_matrix_sync(alo[i], S + G_PLE + (wm + 16 * i) * 24, 24);
    }
#pragma unroll
    for (int j = 0; j < 2; ++j) {
        BFragBc bhi, blo;
        wmma::load_matrix_sync(bhi, S + 2 * G_PLE + (wn + 16 * j) * 24, 24);
        wmma::load_matrix_sync(blo, S + 3 * G_PLE + (wn + 16 * j) * 24, 24);
#pragma unroll
        for (int i = 0; i < 4; ++i) {
            wmma::mma_sync(acc[i][j], ahi[i], bhi, acc[i][j]);
            wmma::mma_sync(acc[i][j], ahi[i], blo, acc[i][j]);
            wmma::mma_sync(acc[i][j], alo[i], bhi, acc[i][j]);
        }
    }
}

__device__ __forceinline__ void gemm_main(
    const __nv_bfloat16* __restrict__ Ah, const __nv_bfloat16* __restrict__ Al,
    const __nv_bfloat16* __restrict__ Bh, const __nv_bfloat16* __restrict__ Bl,
    char* smc, FragC (&acc)[4][2])
{
    const int t = threadIdx.x;
    const int w = t >> 5;
    const int wm = (w & 1) * 64;
    const int wn = (w >> 1) * 32;
    const uint32_t sb = (uint32_t)__cvta_generic_to_shared(smc);
#pragma unroll
    for (int i = 0; i < 4; ++i)
#pragma unroll
        for (int j = 0; j < 2; ++j)
            wmma::fill_fragment(acc[i][j], 0.0f);

    g_prefetch(sb, 0, Ah, Al, Bh, Bl, 0, t);  cp_commit();
    g_prefetch(sb, 1, Ah, Al, Bh, Bl, 16, t); cp_commit();
    g_prefetch(sb, 2, Ah, Al, Bh, Bl, 32, t); cp_commit();

    for (int c = 0; c < 32; ++c) {
        if (c < 30)       asm volatile("cp.async.wait_group 2;" ::: "memory");
        else if (c == 30) asm volatile("cp.async.wait_group 1;" ::: "memory");
        else              asm volatile("cp.async.wait_group 0;" ::: "memory");
        __syncthreads();
        if (c < 29) {
            g_prefetch(sb, (c + 3) & 3, Ah, Al, Bh, Bl, (c + 3) * 16, t);
            cp_commit();
        }
        g_kstep(smc, c & 3, wm, wn, acc);
    }
}

__global__ __launch_bounds__(256, 2) void qkv_gemm_p(
    const float* __restrict__ bq, const float* __restrict__ bk,
    const float* __restrict__ bv)
{
    extern __shared__ char smc[];
    const int t = threadIdx.x;
    const int m0   = blockIdx.x * 128;
    const int wsel = blockIdx.y >> 2;
    const int n0   = (blockIdx.y & 3) * 128;

    const float* bias = (wsel == 0) ? bq : (wsel == 1) ? bk : bv;
    __nv_bfloat16* oh = (wsel == 0) ? gq_hi : (wsel == 1) ? gk_hi : gv_hi;
    __nv_bfloat16* ol = (wsel == 0) ? gq_lo : (wsel == 1) ? gk_lo : gv_lo;

    float* biasS = (float*)(smc + G_BIAS);
    if (t < 128) biasS[t] = bias[n0 + t];

    FragC acc[4][2];
    gemm_main(gx_hi + (size_t)m0 * Dv, gx_lo + (size_t)m0 * Dv,
              gw_hi + (size_t)wsel * Dv * Dv + (size_t)n0 * Dv,
              gw_lo + (size_t)wsel * Dv * Dv + (size_t)n0 * Dv, smc, acc);
    __syncthreads();

    float* Cs = (float*)smc;
    const int w = t >> 5, wm = (w & 1) * 64, wn = (w >> 1) * 32;
#pragma unroll
    for (int i = 0; i < 4; ++i)
#pragma unroll
        for (int j = 0; j < 2; ++j)
            wmma::store_matrix_sync(&Cs[(wm + 16 * i) * 132 + wn + 16 * j],
                                    acc[i][j], 132, wmma::mem_row_major);
    __syncthreads();

    const int row = t >> 1, c0 = (t & 1) * 64;
    const int m = m0 + row, tb = m >> 10, n = m & 1023;
    const int h = (n0 + c0) >> 6;
    __nv_bfloat16* dh = oh + ((size_t)(tb * Hv + h) * Nv + n) * HDv;
    __nv_bfloat16* dl = ol + ((size_t)(tb * Hv + h) * Nv + n) * HDv;
#pragma unroll
    for (int c = 0; c < 64; c += 4) {
        float4 v = *(float4*)&Cs[row * 132 + c0 + c];
        v.x += biasS[c0 + c + 0]; v.y += biasS[c0 + c + 1];
        v.z += biasS[c0 + c + 2]; v.w += biasS[c0 + c + 3];
        split_store4(v, dh + c, dl + c);
    }
}

__global__ __launch_bounds__(256, 2) void out_gemm_p(
    const float* __restrict__ bo, float* __restrict__ out)
{
    extern __shared__ char smc[];
    const int t = threadIdx.x;
    const int m0 = blockIdx.x * 128;
    const int n0 = blockIdx.y * 128;

    float* biasS = (float*)(smc + G_BIAS);
    if (t < 128) biasS[t] = bo[n0 + t];

    FragC acc[4][2];
    gemm_main(gc_hi + (size_t)m0 * Dv, gc_lo + (size_t)m0 * Dv,
              gw_hi + (size_t)3 * Dv * Dv + (size_t)n0 * Dv,
              gw_lo + (size_t)3 * Dv * Dv + (size_t)n0 * Dv, smc, acc);
    __syncthreads();

    float* Cs = (float*)smc;
    const int w = t >> 5, wm = (w & 1) * 64, wn = (w >> 1) * 32;
#pragma unroll
    for (int i = 0; i < 4; ++i)
#pragma unroll
        for (int j = 0; j < 2; ++j)
            wmma::store_matrix_sync(&Cs[(wm + 16 * i) * 132 + wn + 16 * j],
                                    acc[i][j], 132, wmma::mem_row_major);
    __syncthreads();

    const int row = t >> 1, c0 = (t & 1) * 64;
    float* dst = out + (size_t)(m0 + row) * Dv + n0 + c0;
#pragma unroll
    for (int c = 0; c < 64; c += 4) {
        float4 v = *(float4*)&Cs[row * 132 + c0 + c];
        v.x += biasS[c0 + c + 0]; v.y += biasS[c0 + c + 1];
        v.z += biasS[c0 + c + 2]; v.w += biasS[c0 + c + 3];
        *(float4*)(dst + c) = v;
    }
}

// ===========================================================================
// Attention: raw mma.sync m16n8k16, S in registers. 512 thr, 16 warps;
// block = 256 q-rows of one (tb,h); warp = 16 q-rows x 64 keys x 64 hd.
// K/V: 3-stage cp.async ring (2 tiles of latency cover), one sync per tile.
// ===========================================================================
#define AT_Q    0
#define AT_KV   73728
#define AT_STG  36864
#define AT_PL   9216
#define ATTN_SMEM (73728 + 3 * 36864)   // 184320

__device__ __forceinline__ void kv_prefetch(uint32_t dstbase, size_t hb,
                                            int row0, int t)
{
    const __nv_bfloat16* kvp[4] = {gk_hi + hb, gk_lo + hb, gv_hi + hb, gv_lo + hb};
#pragma unroll
    for (int hh = 0; hh < 4; ++hh) {
        const int o = t + 512 * hh;
        const int plane = o >> 9;
        const int idx = o & 511;
        cp16(dstbase + plane * AT_PL + (idx >> 3) * 144 + (idx & 7) * 16,
             kvp[plane] + (size_t)(row0 + (idx >> 3)) * HDv + (idx & 7) * 8);
    }
}

__global__ __launch_bounds__(512, 1) void attn_m()
{
    extern __shared__ char smc[];
    const uint32_t sb = (uint32_t)__cvta_generic_to_shared(smc);
    const int t = threadIdx.x;
    const int l = t & 31;
    const int w = t >> 5;
    const int qn0 = blockIdx.x * 256;
    const int tbh = blockIdx.y;
    const size_t hb = (size_t)tbh * Nv * HDv;

    // group0: Q planes + KV tile 0; group1: KV tile 1
#pragma unroll
    for (int hh = 0; hh < 8; ++hh) {
        const int o = t + 512 * hh;
        const int plane = o >> 11;
        const int idx = o & 2047;
        const __nv_bfloat16* src =
            (plane ? gq_lo : gq_hi) + hb + (size_t)(qn0 + (idx >> 3)) * HDv + (idx & 7) * 8;
        cp16(sb + AT_Q + plane * 36864 + (idx >> 3) * 144 + (idx & 7) * 16, src);
    }
    kv_prefetch(sb + AT_KV, hb, 0, t);
    cp_commit();
    kv_prefetch(sb + AT_KV + AT_STG, hb, 64, t);
    cp_commit();

    const int wrow = w * 16;
    const uint32_t qaddr = sb + AT_Q + (wrow + (l & 15)) * 144 + (l >> 4) * 16;
    const int kroff = ((l & 7) + ((l >> 4) & 1) * 8) * 144 + ((l >> 3) & 1) * 16;
    const int vroff = ((l & 7) + ((l >> 3) & 1) * 8) * 144 + ((l >> 4) & 1) * 16;

    float ctx[8][4];
#pragma unroll
    for (int i = 0; i < 8; ++i)
#pragma unroll
        for (int j = 0; j < 4; ++j) ctx[i][j] = 0.f;
    float ds0 = 0.f, ds1 = 0.f;

    int stage = 0;
    for (int kt = 0; kt < 16; ++kt) {
        if (kt < 15) asm volatile("cp.async.wait_group 1;" ::: "memory");
        else         asm volatile("cp.async.wait_group 0;" ::: "memory");
        __syncthreads();
        if (kt < 14) {
            int ns = stage + 2; if (ns >= 3) ns -= 3;
            kv_prefetch(sb + AT_KV + ns * AT_STG, hb, (kt + 2) * 64, t);
            cp_commit();
        }
        const uint32_t kst = sb + AT_KV + stage * AT_STG;
        if (++stage == 3) stage = 0;

        float sacc[8][4];
#pragma unroll
        for (int i = 0; i < 8; ++i)
#pragma unroll
            for (int j = 0; j < 4; ++j) sacc[i][j] = 0.f;
#pragma unroll
        for (int ks = 0; ks < 4; ++ks) {
            uint32_t aqh[4], aql[4];
            ldsm4(aqh, qaddr + ks * 32);
            ldsm4(aql, qaddr + 36864 + ks * 32);
#pragma unroll
            for (int np = 0; np < 4; ++np) {
                uint32_t bh[4], bl[4];
                ldsm4(bh, kst + np * 16 * 144 + kroff + ks * 32);
                ldsm4(bl, kst + AT_PL + np * 16 * 144 + kroff + ks * 32);
                mma16816(sacc[2 * np],     aqh, bh[0], bh[1]);
                mma16816(sacc[2 * np],     aqh, bl[0], bl[1]);
                mma16816(sacc[2 * np],     aql, bh[0], bh[1]);
                mma16816(sacc[2 * np + 1], aqh, bh[2], bh[3]);
                mma16816(sacc[2 * np + 1], aqh, bl[2], bl[3]);
                mma16816(sacc[2 * np + 1], aql, bh[2], bh[3]);
            }
        }
#pragma unroll
        for (int kf = 0; kf < 4; ++kf) {
            uint32_t sah[4], sal[4];
#pragma unroll
            for (int hh = 0; hh < 2; ++hh) {
                float* c = sacc[2 * kf + hh];
                float c0 = fmaxf(c[0] * 0.125f, 0.f);
                float c1 = fmaxf(c[1] * 0.125f, 0.f);
                float c2 = fmaxf(c[2] * 0.125f, 0.f);
                float c3 = fmaxf(c[3] * 0.125f, 0.f);
                ds0 += c0 + c1;
                ds1 += c2 + c3;
                __nv_bfloat16 h0 = __float2bfloat16_rn(c0);
                __nv_bfloat16 h1 = __float2bfloat16_rn(c1);
                __nv_bfloat16 h2 = __float2bfloat16_rn(c2);
                __nv_bfloat16 h3 = __float2bfloat16_rn(c3);
                sah[2 * hh + 0] = pack_bf2(h0, h1);
                sah[2 * hh + 1] = pack_bf2(h2, h3);
                sal[2 * hh + 0] = pack_bf2(
                    __float2bfloat16_rn(c0 - __bfloat162float(h0)),
                    __float2bfloat16_rn(c1 - __bfloat162float(h1)));
                sal[2 * hh + 1] = pack_bf2(
                    __float2bfloat16_rn(c2 - __bfloat162float(h2)),
                    __float2bfloat16_rn(c3 - __bfloat162float(h3)));
            }
#pragma unroll
            for (int np = 0; np < 4; ++np) {
                uint32_t bvh[4], bvl[4];
                ldsm4t(bvh, kst + 2 * AT_PL + kf * 16 * 144 + vroff + np * 32);
                ldsm4t(bvl, kst + 3 * AT_PL + kf * 16 * 144 + vroff + np * 32);
                mma16816(ctx[2 * np],     sah, bvh[0], bvh[1]);
                mma16816(ctx[2 * np],     sah, bvl[0], bvl[1]);
                mma16816(ctx[2 * np],     sal, bvh[0], bvh[1]);
                mma16816(ctx[2 * np + 1], sah, bvh[2], bvh[3]);
                mma16816(ctx[2 * np + 1], sah, bvl[2], bvl[3]);
                mma16816(ctx[2 * np + 1], sal, bvh[2], bvh[3]);
            }
        }
    }

    ds0 += __shfl_xor_sync(0xffffffffu, ds0, 1);
    ds0 += __shfl_xor_sync(0xffffffffu, ds0, 2);
    ds1 += __shfl_xor_sync(0xffffffffu, ds1, 1);
    ds1 += __shfl_xor_sync(0xffffffffu, ds1, 2);
    const float inv0 = 1.f / (ds0 + 1e-6f);
    const float inv1 = 1.f / (ds1 + 1e-6f);

    const int g = l >> 2, tg = l & 3;
    const int mtok = (tbh >> 3) * Nv + qn0 + wrow + g;
    const int hd0 = (tbh & 7) * HDv;
    __nv_bfloat16* dh0 = gc_hi + (size_t)mtok * Dv + hd0;
    __nv_bfloat16* dl0 = gc_lo + (size_t)mtok * Dv + hd0;
    __nv_bfloat16* dh1 = dh0 + 8 * Dv;
    __nv_bfloat16* dl1 = dl0 + 8 * Dv;
#pragma unroll
    for (int i = 0; i < 8; ++i) {
        const int d = (i >> 1) * 16 + (i & 1) * 8 + tg * 2;
        float v0 = ctx[i][0] * inv0, v1 = ctx[i][1] * inv0;
        float v2 = ctx[i][2] * inv1, v3 = ctx[i][3] * inv1;
        __nv_bfloat16 h0 = __float2bfloat16_rn(v0);
        __nv_bfloat16 h1 = __float2bfloat16_rn(v1);
        __nv_bfloat16 h2 = __float2bfloat16_rn(v2);
        __nv_bfloat16 h3 = __float2bfloat16_rn(v3);
        *(uint32_t*)(dh0 + d) = pack_bf2(h0, h1);
        *(uint32_t*)(dl0 + d) = pack_bf2(
            __float2bfloat16_rn(v0 - __bfloat162float(h0)),
            __float2bfloat16_rn(v1 - __bfloat162float(h1)));
        *(uint32_t*)(dh1 + d) = pack_bf2(h2, h3);
        *(uint32_t*)(dl1 + d) = pack_bf2(
            __float2bfloat16_rn(v2 - __bfloat162float(h2)),
            __float2bfloat16_rn(v3 - __bfloat162float(h3)));
    }
}

// ---------------------------------------------------------------------------
extern "C" void kernel_launch(void* const* d_in, const int* in_sizes, int n_in,
                              void* d_out, int out_size)
{
    const float* x  = (const float*)d_in[0];
    const float* wq = (const float*)d_in[1];
    const float* bq = (const float*)d_in[2];
    const float* wk = (const float*)d_in[3];
    const float* bk = (const float*)d_in[4];
    const float* wv = (const float*)d_in[5];
    const float* bv = (const float*)d_in[6];
    const float* wo = (const float*)d_in[7];
    const float* bo = (const float*)d_in[8];
    float* out = (float*)d_out;

    cudaFuncSetAttribute(qkv_gemm_p, cudaFuncAttributeMaxDynamicSharedMemorySize, GEMM_SMEM);
    cudaFuncSetAttribute(out_gemm_p, cudaFuncAttributeMaxDynamicSharedMemorySize, GEMM_SMEM);
    cudaFuncSetAttribute(attn_m, cudaFuncAttributeMaxDynamicSharedMemorySize, ATTN_SMEM);

    const int splitBlocks = (NXf4 + 4 * NWf4 + 255) / 256;
    split_kernel<<<splitBlocks, 256>>>(x, wq, wk, wv, wo);
    qkv_gemm_p<<<dim3(Mv / 128, 12), 256, GEMM_SMEM>>>(bq, bk, bv);
    attn_m<<<dim3(Nv / 256, TBv * Hv), 512, ATTN_SMEM>>>();
    out_gemm_p<<<dim3(Mv / 128, Dv / 128), 256, GEMM_SMEM>>>(bo, out);
}

// round 10
// speedup vs baseline: 1.1944x; 1.1170x over previous
#include <cuda_runtime.h>
#include <cuda_bf16.h>
#include <mma.h>
#include <cstdint>

using namespace nvcuda;

#define TBv 16
#define Nv  1024
#define Dv  512
#define Hv  8
#define HDv 64
#define Mv  (TBv * Nv)

__device__ __nv_bfloat16 gx_hi[(size_t)Mv * Dv], gx_lo[(size_t)Mv * Dv];
__device__ __nv_bfloat16 gw_hi[4 * Dv * Dv],     gw_lo[4 * Dv * Dv];
__device__ __nv_bfloat16 gq_hi[(size_t)Mv * Dv], gq_lo[(size_t)Mv * Dv];
__device__ __nv_bfloat16 gk_hi[(size_t)Mv * Dv], gk_lo[(size_t)Mv * Dv];
__device__ __nv_bfloat16 gv_hi[(size_t)Mv * Dv], gv_lo[(size_t)Mv * Dv];
__device__ __nv_bfloat16 gc_hi[(size_t)Mv * Dv], gc_lo[(size_t)Mv * Dv];

__device__ __forceinline__ uint32_t pack_bf2(__nv_bfloat16 a, __nv_bfloat16 b) {
    __nv_bfloat162 p = __halves2bfloat162(a, b);
    return *(uint32_t*)&p;
}
__device__ __forceinline__ void split_store4(float4 v,
                                             __nv_bfloat16* __restrict__ hp,
                                             __nv_bfloat16* __restrict__ lp)
{
    __nv_bfloat16 hx = __float2bfloat16_rn(v.x), hy = __float2bfloat16_rn(v.y);
    __nv_bfloat16 hz = __float2bfloat16_rn(v.z), hw = __float2bfloat16_rn(v.w);
    ((uint32_t*)hp)[0] = pack_bf2(hx, hy);
    ((uint32_t*)hp)[1] = pack_bf2(hz, hw);
    ((uint32_t*)lp)[0] = pack_bf2(__float2bfloat16_rn(v.x - __bfloat162float(hx)),
                                  __float2bfloat16_rn(v.y - __bfloat162float(hy)));
    ((uint32_t*)lp)[1] = pack_bf2(__float2bfloat16_rn(v.z - __bfloat162float(hz)),
                                  __float2bfloat16_rn(v.w - __bfloat162float(hw)));
}
__device__ __forceinline__ void cp16(uint32_t dst, const void* src) {
    asm volatile("cp.async.cg.shared.global [%0], [%1], 16;" :: "r"(dst), "l"(src));
}
__device__ __forceinline__ void cp_commit() {
    asm volatile("cp.async.commit_group;" ::: "memory");
}
__device__ __forceinline__ void ldsm4(uint32_t (&r)[4], uint32_t a) {
    asm volatile("ldmatrix.sync.aligned.m8n8.x4.shared.b16 {%0,%1,%2,%3}, [%4];"
                 : "=r"(r[0]), "=r"(r[1]), "=r"(r[2]), "=r"(r[3]) : "r"(a));
}
__device__ __forceinline__ void ldsm4t(uint32_t (&r)[4], uint32_t a) {
    asm volatile("ldmatrix.sync.aligned.m8n8.x4.trans.shared.b16 {%0,%1,%2,%3}, [%4];"
                 : "=r"(r[0]), "=r"(r[1]), "=r"(r[2]), "=r"(r[3]) : "r"(a));
}
__device__ __forceinline__ void mma16816(float (&c)[4], const uint32_t (&a)[4],
                                         uint32_t b0, uint32_t b1) {
    asm volatile(
        "mma.sync.aligned.m16n8k16.row.col.f32.bf16.bf16.f32 "
        "{%0,%1,%2,%3}, {%4,%5,%6,%7}, {%8,%9}, {%0,%1,%2,%3};"
        : "+f"(c[0]), "+f"(c[1]), "+f"(c[2]), "+f"(c[3])
        : "r"(a[0]), "r"(a[1]), "r"(a[2]), "r"(a[3]), "r"(b0), "r"(b1));
}

using BFragA  = wmma::fragment<wmma::matrix_a, 16, 16, 16, __nv_bfloat16, wmma::row_major>;
using BFragBc = wmma::fragment<wmma::matrix_b, 16, 16, 16, __nv_bfloat16, wmma::col_major>;
using FragC   = wmma::fragment<wmma::accumulator, 16, 16, 16, float>;

// ---------------------------------------------------------------------------
#define NXf4 (Mv * Dv / 4)
#define NWf4 (Dv * Dv / 4)

__global__ __launch_bounds__(256) void split_kernel(
    const float* __restrict__ x,
    const float* __restrict__ wq, const float* __restrict__ wk,
    const float* __restrict__ wv, const float* __restrict__ wo)
{
    int i = blockIdx.x * 256 + threadIdx.x;
    const float* src; __nv_bfloat16 *dh, *dl; int j;
    if (i < NXf4) { src = x; j = i; dh = gx_hi; dl = gx_lo; }
    else {
        int r = i - NXf4;
        if (r >= 4 * NWf4) return;
        int sel = r / NWf4; j = r % NWf4;
        src = (sel == 0) ? wq : (sel == 1) ? wk : (sel == 2) ? wv : wo;
        dh = gw_hi + (size_t)sel * Dv * Dv;
        dl = gw_lo + (size_t)sel * Dv * Dv;
    }
    float4 v = ((const float4*)src)[j];
    split_store4(v, dh + 4 * (size_t)j, dl + 4 * (size_t)j);
}

// ===========================================================================
// GEMM: C[128x128] = A(hi+lo).B(hi+lo)^T, K=512. 256 thr, 8 warps (2m x 4n),
// warp 64x32. R5 schedule: single smem buffer, per chunk (K=32):
//   LDG(regs) -> sync(prev MMA reads done; LDG drains during wait)
//   -> STS -> sync -> 2 ksteps.
// Stage: 4 planes x 128 rows x 40 elems bf16 (80B rows) = 40960 B.
// ===========================================================================
#define G_PLE  5120
#define G_PLB  10240
#define G_BIAS 40960
#define GEMM_SMEM (40960 + 512)

__device__ __forceinline__ void g_kstep(const char* smc, int ks,
                                        int wm, int wn, FragC (&acc)[4][2])
{
    const __nv_bfloat16* S = (const __nv_bfloat16*)smc;
    BFragA ahi[4], alo[4];
#pragma unroll
    for (int i = 0; i < 4; ++i) {
        wmma::load_matrix_sync(ahi[i], S + (wm + 16 * i) * 40 + ks * 16, 40);
        wmma::load_matrix_sync(alo[i], S + G_PLE + (wm + 16 * i) * 40 + ks * 16, 40);
    }
#pragma unroll
    for (int j = 0; j < 2; ++j) {
        BFragBc bhi, blo;
        wmma::load_matrix_sync(bhi, S + 2 * G_PLE + (wn + 16 * j) * 40 + ks * 16, 40);
        wmma::load_matrix_sync(blo, S + 3 * G_PLE + (wn + 16 * j) * 40 + ks * 16, 40);
#pragma unroll
        for (int i = 0; i < 4; ++i) {
            wmma::mma_sync(acc[i][j], ahi[i], bhi, acc[i][j]);
            wmma::mma_sync(acc[i][j], ahi[i], blo, acc[i][j]);
            wmma::mma_sync(acc[i][j], alo[i], bhi, acc[i][j]);
        }
    }
}

__device__ __forceinline__ void gemm_single(
    const __nv_bfloat16* __restrict__ Ah, const __nv_bfloat16* __restrict__ Al,
    const __nv_bfloat16* __restrict__ Bh, const __nv_bfloat16* __restrict__ Bl,
    char* smc, FragC (&acc)[4][2])
{
    const int t = threadIdx.x;
    const int w = t >> 5;
    const int wm = (w & 1) * 64;
    const int wn = (w >> 1) * 32;
#pragma unroll
    for (int i = 0; i < 4; ++i)
#pragma unroll
        for (int j = 0; j < 2; ++j)
            wmma::fill_fragment(acc[i][j], 0.0f);

    for (int ch = 0; ch < 16; ++ch) {
        uint4 rg[8];
#pragma unroll
        for (int hh = 0; hh < 2; ++hh) {
            const int o = t + 256 * hh;
            const size_t off = (size_t)(o >> 2) * Dv + ch * 32 + (o & 3) * 8;
            rg[4 * hh + 0] = *(const uint4*)(Ah + off);
            rg[4 * hh + 1] = *(const uint4*)(Al + off);
            rg[4 * hh + 2] = *(const uint4*)(Bh + off);
            rg[4 * hh + 3] = *(const uint4*)(Bl + off);
        }
        __syncthreads();      // prev chunk MMA reads done; LDGs drain here
#pragma unroll
        for (int hh = 0; hh < 2; ++hh) {
            const int o = t + 256 * hh;
            const int off = (o >> 2) * 80 + (o & 3) * 16;
            *(uint4*)(smc + off)             = rg[4 * hh + 0];
            *(uint4*)(smc + G_PLB + off)     = rg[4 * hh + 1];
            *(uint4*)(smc + 2 * G_PLB + off) = rg[4 * hh + 2];
            *(uint4*)(smc + 3 * G_PLB + off) = rg[4 * hh + 3];
        }
        __syncthreads();      // chunk data visible
        g_kstep(smc, 0, wm, wn, acc);
        g_kstep(smc, 1, wm, wn, acc);
    }
}

// Two-phase epilogue (Cs = 64 x 132 f32 = 33.8 KB fits the 40.96 KB stage).
// Phase p handles rows [p*64, p*64+64): warps with (w&1)==p own those rows.

__global__ __launch_bounds__(256, 2) void qkv_gemm_p(
    const float* __restrict__ bq, const float* __restrict__ bk,
    const float* __restrict__ bv)
{
    extern __shared__ char smc[];
    const int t = threadIdx.x;
    const int m0   = blockIdx.x * 128;
    const int wsel = blockIdx.y >> 2;
    const int n0   = (blockIdx.y & 3) * 128;

    const float* bias = (wsel == 0) ? bq : (wsel == 1) ? bk : bv;
    __nv_bfloat16* oh = (wsel == 0) ? gq_hi : (wsel == 1) ? gk_hi : gv_hi;
    __nv_bfloat16* ol = (wsel == 0) ? gq_lo : (wsel == 1) ? gk_lo : gv_lo;

    float* biasS = (float*)(smc + G_BIAS);
    if (t < 128) biasS[t] = bias[n0 + t];

    FragC acc[4][2];
    gemm_single(gx_hi + (size_t)m0 * Dv, gx_lo + (size_t)m0 * Dv,
                gw_hi + (size_t)wsel * Dv * Dv + (size_t)n0 * Dv,
                gw_lo + (size_t)wsel * Dv * Dv + (size_t)n0 * Dv, smc, acc);

    float* Cs = (float*)smc;
    const int w = t >> 5, wn = (w >> 1) * 32;
    const int erow = t >> 2;              // 0..63
    const int ecol = (t & 3) * 32;        // within one head (64-aligned tiles)
#pragma unroll
    for (int p = 0; p < 2; ++p) {
        __syncthreads();                  // prev reads of smem done
        if ((w & 1) == p) {
#pragma unroll
            for (int i = 0; i < 4; ++i)
#pragma unroll
                for (int j = 0; j < 2; ++j)
                    wmma::store_matrix_sync(&Cs[(16 * i) * 132 + wn + 16 * j],
                                            acc[i][j], 132, wmma::mem_row_major);
        }
        __syncthreads();
        const int m  = m0 + p * 64 + erow;
        const int tb = m >> 10, n = m & 1023;
        const int h  = (n0 + ecol) >> 6;
        const int hd0 = (n0 + ecol) & 63;
        __nv_bfloat16* dh = oh + ((size_t)(tb * Hv + h) * Nv + n) * HDv + hd0;
        __nv_bfloat16* dl = ol + ((size_t)(tb * Hv + h) * Nv + n) * HDv + hd0;
#pragma unroll
        for (int c = 0; c < 32; c += 4) {
            float4 v = *(float4*)&Cs[erow * 132 + ecol + c];
            v.x += biasS[ecol + c + 0]; v.y += biasS[ecol + c + 1];
            v.z += biasS[ecol + c + 2]; v.w += biasS[ecol + c + 3];
            split_store4(v, dh + c, dl + c);
        }
    }
}

__global__ __launch_bounds__(256, 2) void out_gemm_p(
    const float* __restrict__ bo, float* __restrict__ out)
{
    extern __shared__ char smc[];
    const int t = threadIdx.x;
    const int m0 = blockIdx.x * 128;
    const int n0 = blockIdx.y * 128;

    float* biasS = (float*)(smc + G_BIAS);
    if (t < 128) biasS[t] = bo[n0 + t];

    FragC acc[4][2];
    gemm_single(gc_hi + (size_t)m0 * Dv, gc_lo + (size_t)m0 * Dv,
                gw_hi + (size_t)3 * Dv * Dv + (size_t)n0 * Dv,
                gw_lo + (size_t)3 * Dv * Dv + (size_t)n0 * Dv, smc, acc);

    float* Cs = (float*)smc;
    const int w = t >> 5, wn = (w >> 1) * 32;
    const int erow = t >> 2;
    const int ecol = (t & 3) * 32;
#pragma unroll
    for (int p = 0; p < 2; ++p) {
        __syncthreads();
        if ((w & 1) == p) {
#pragma unroll
            for (int i = 0; i < 4; ++i)
#pragma unroll
                for (int j = 0; j < 2; ++j)
                    wmma::store_matrix_sync(&Cs[(16 * i) * 132 + wn + 16 * j],
                                            acc[i][j], 132, wmma::mem_row_major);
        }
        __syncthreads();
        float* dst = out + (size_t)(m0 + p * 64 + erow) * Dv + n0 + ecol;
#pragma unroll
        for (int c = 0; c < 32; c += 4) {
            float4 v = *(float4*)&Cs[erow * 132 + ecol + c];
            v.x += biasS[ecol + c + 0]; v.y += biasS[ecol + c + 1];
            v.z += biasS[ecol + c + 2]; v.w += biasS[ecol + c + 3];
            *(float4*)(dst + c) = v;
        }
    }
}

// ===========================================================================
// Attention: raw mma.sync m16n8k16, S in registers (unchanged from R9).
// 512 thr, 16 warps; block = 256 q-rows of one (tb,h); warp = 16 q x 64 k x 64 hd.
// K/V: 3-stage cp.async ring, one sync per tile.
// ===========================================================================
#define AT_Q    0
#define AT_KV   73728
#define AT_STG  36864
#define AT_PL   9216
#define ATTN_SMEM (73728 + 3 * 36864)

__device__ __forceinline__ void kv_prefetch(uint32_t dstbase, size_t hb,
                                            int row0, int t)
{
    const __nv_bfloat16* kvp[4] = {gk_hi + hb, gk_lo + hb, gv_hi + hb, gv_lo + hb};
#pragma unroll
    for (int hh = 0; hh < 4; ++hh) {
        const int o = t + 512 * hh;
        const int plane = o >> 9;
        const int idx = o & 511;
        cp16(dstbase + plane * AT_PL + (idx >> 3) * 144 + (idx & 7) * 16,
             kvp[plane] + (size_t)(row0 + (idx >> 3)) * HDv + (idx & 7) * 8);
    }
}

__global__ __launch_bounds__(512, 1) void attn_m()
{
    extern __shared__ char smc[];
    const uint32_t sb = (uint32_t)__cvta_generic_to_shared(smc);
    const int t = threadIdx.x;
    const int l = t & 31;
    const int w = t >> 5;
    const int qn0 = blockIdx.x * 256;
    const int tbh = blockIdx.y;
    const size_t hb = (size_t)tbh * Nv * HDv;

#pragma unroll
    for (int hh = 0; hh < 8; ++hh) {
        const int o = t + 512 * hh;
        const int plane = o >> 11;
        const int idx = o & 2047;
        const __nv_bfloat16* src =
            (plane ? gq_lo : gq_hi) + hb + (size_t)(qn0 + (idx >> 3)) * HDv + (idx & 7) * 8;
        cp16(sb + AT_Q + plane * 36864 + (idx >> 3) * 144 + (idx & 7) * 16, src);
    }
    kv_prefetch(sb + AT_KV, hb, 0, t);
    cp_commit();
    kv_prefetch(sb + AT_KV + AT_STG, hb, 64, t);
    cp_commit();

    const int wrow = w * 16;
    const uint32_t qaddr = sb + AT_Q + (wrow + (l & 15)) * 144 + (l >> 4) * 16;
    const int kroff = ((l & 7) + ((l >> 4) & 1) * 8) * 144 + ((l >> 3) & 1) * 16;
    const int vroff = ((l & 7) + ((l >> 3) & 1) * 8) * 144 + ((l >> 4) & 1) * 16;

    float ctx[8][4];
#pragma unroll
    for (int i = 0; i < 8; ++i)
#pragma unroll
        for (int j = 0; j < 4; ++j) ctx[i][j] = 0.f;
    float ds0 = 0.f, ds1 = 0.f;

    int stage = 0;
    for (int kt = 0; kt < 16; ++kt) {
        if (kt < 15) asm volatile("cp.async.wait_group 1;" ::: "memory");
        else         asm volatile("cp.async.wait_group 0;" ::: "memory");
        __syncthreads();
        if (kt < 14) {
            int ns = stage + 2; if (ns >= 3) ns -= 3;
            kv_prefetch(sb + AT_KV + ns * AT_STG, hb, (kt + 2) * 64, t);
            cp_commit();
        }
        const uint32_t kst = sb + AT_KV + stage * AT_STG;
        if (++stage == 3) stage = 0;

        float sacc[8][4];
#pragma unroll
        for (int i = 0; i < 8; ++i)
#pragma unroll
            for (int j = 0; j < 4; ++j) sacc[i][j] = 0.f;
#pragma unroll
        for (int ks = 0; ks < 4; ++ks) {
            uint32_t aqh[4], aql[4];
            ldsm4(aqh, qaddr + ks * 32);
            ldsm4(aql, qaddr + 36864 + ks * 32);
#pragma unroll
            for (int np = 0; np < 4; ++np) {
                uint32_t bh[4], bl[4];
                ldsm4(bh, kst + np * 16 * 144 + kroff + ks * 32);
                ldsm4(bl, kst + AT_PL + np * 16 * 144 + kroff + ks * 32);
                mma16816(sacc[2 * np],     aqh, bh[0], bh[1]);
                mma16816(sacc[2 * np],     aqh, bl[0], bl[1]);
                mma16816(sacc[2 * np],     aql, bh[0], bh[1]);
                mma16816(sacc[2 * np + 1], aqh, bh[2], bh[3]);
                mma16816(sacc[2 * np + 1], aqh, bl[2], bl[3]);
                mma16816(sacc[2 * np + 1], aql, bh[2], bh[3]);
            }
        }
#pragma unroll
        for (int kf = 0; kf < 4; ++kf) {
            uint32_t sah[4], sal[4];
#pragma unroll
            for (int hh = 0; hh < 2; ++hh) {
                float* c = sacc[2 * kf + hh];
                float c0 = fmaxf(c[0] * 0.125f, 0.f);
                float c1 = fmaxf(c[1] * 0.125f, 0.f);
                float c2 = fmaxf(c[2] * 0.125f, 0.f);
                float c3 = fmaxf(c[3] * 0.125f, 0.f);
                ds0 += c0 + c1;
                ds1 += c2 + c3;
                __nv_bfloat16 h0 = __float2bfloat16_rn(c0);
                __nv_bfloat16 h1 = __float2bfloat16_rn(c1);
                __nv_bfloat16 h2 = __float2bfloat16_rn(c2);
                __nv_bfloat16 h3 = __float2bfloat16_rn(c3);
                sah[2 * hh + 0] = pack_bf2(h0, h1);
                sah[2 * hh + 1] = pack_bf2(h2, h3);
                sal[2 * hh + 0] = pack_bf2(
                    __float2bfloat16_rn(c0 - __bfloat162float(h0)),
                    __float2bfloat16_rn(c1 - __bfloat162float(h1)));
                sal[2 * hh + 1] = pack_bf2(
                    __float2bfloat16_rn(c2 - __bfloat162float(h2)),
                    __float2bfloat16_rn(c3 - __bfloat162float(h3)));
            }
#pragma unroll
            for (int np = 0; np < 4; ++np) {
                uint32_t bvh[4], bvl[4];
                ldsm4t(bvh, kst + 2 * AT_PL + kf * 16 * 144 + vroff + np * 32);
                ldsm4t(bvl, kst + 3 * AT_PL + kf * 16 * 144 + vroff + np * 32);
                mma16816(ctx[2 * np],     sah, bvh[0], bvh[1]);
                mma16816(ctx[2 * np],     sah, bvl[0], bvl[1]);
                mma16816(ctx[2 * np],     sal, bvh[0], bvh[1]);
                mma16816(ctx[2 * np + 1], sah, bvh[2], bvh[3]);
                mma16816(ctx[2 * np + 1], sah, bvl[2], bvl[3]);
                mma16816(ctx[2 * np + 1], sal, bvh[2], bvh[3]);
            }
        }
    }

    ds0 += __shfl_xor_sync(0xffffffffu, ds0, 1);
    ds0 += __shfl_xor_sync(0xffffffffu, ds0, 2);
    ds1 += __shfl_xor_sync(0xffffffffu, ds1, 1);
    ds1 += __shfl_xor_sync(0xffffffffu, ds1, 2);
    const float inv0 = 1.f / (ds0 + 1e-6f);
    const float inv1 = 1.f / (ds1 + 1e-6f);

    const int g = l >> 2, tg = l & 3;
    const int mtok = (tbh >> 3) * Nv + qn0 + wrow + g;
    const int hd0 = (tbh & 7) * HDv;
    __nv_bfloat16* dh0 = gc_hi + (size_t)mtok * Dv + hd0;
    __nv_bfloat16* dl0 = gc_lo + (size_t)mtok * Dv + hd0;
    __nv_bfloat16* dh1 = dh0 + 8 * Dv;
    __nv_bfloat16* dl1 = dl0 + 8 * Dv;
#pragma unroll
    for (int i = 0; i < 8; ++i) {
        const int d = (i >> 1) * 16 + (i & 1) * 8 + tg * 2;
        float v0 = ctx[i][0] * inv0, v1 = ctx[i][1] * inv0;
        float v2 = ctx[i][2] * inv1, v3 = ctx[i][3] * inv1;
        __nv_bfloat16 h0 = __float2bfloat16_rn(v0);
        __nv_bfloat16 h1 = __float2bfloat16_rn(v1);
        __nv_bfloat16 h2 = __float2bfloat16_rn(v2);
        __nv_bfloat16 h3 = __float2bfloat16_rn(v3);
        *(uint32_t*)(dh0 + d) = pack_bf2(h0, h1);
        *(uint32_t*)(dl0 + d) = pack_bf2(
            __float2bfloat16_rn(v0 - __bfloat162float(h0)),
            __float2bfloat16_rn(v1 - __bfloat162float(h1)));
        *(uint32_t*)(dh1 + d) = pack_bf2(h2, h3);
        *(uint32_t*)(dl1 + d) = pack_bf2(
            __float2bfloat16_rn(v2 - __bfloat162float(h2)),
            __float2bfloat16_rn(v3 - __bfloat162float(h3)));
    }
}

// ---------------------------------------------------------------------------
extern "C" void kernel_launch(void* const* d_in, const int* in_sizes, int n_in,
                              void* d_out, int out_size)
{
    const float* x  = (const float*)d_in[0];
    const float* wq = (const float*)d_in[1];
    const float* bq = (const float*)d_in[2];
    const float* wk = (const float*)d_in[3];
    const float* bk = (const float*)d_in[4];
    const float* wv = (const float*)d_in[5];
    const float* bv = (const float*)d_in[6];
    const float* wo = (const float*)d_in[7];
    const float* bo = (const float*)d_in[8];
    float* out = (float*)d_out;

    cudaFuncSetAttribute(qkv_gemm_p, cudaFuncAttributeMaxDynamicSharedMemorySize, GEMM_SMEM);
    cudaFuncSetAttribute(out_gemm_p, cudaFuncAttributeMaxDynamicSharedMemorySize, GEMM_SMEM);
    cudaFuncSetAttribute(attn_m, cudaFuncAttributeMaxDynamicSharedMemorySize, ATTN_SMEM);

    const int splitBlocks = (NXf4 + 4 * NWf4 + 255) / 256;
    split_kernel<<<splitBlocks, 256>>>(x, wq, wk, wv, wo);
    qkv_gemm_p<<<dim3(Mv / 128, 12), 256, GEMM_SMEM>>>(bq, bk, bv);
    attn_m<<<dim3(Nv / 256, TBv * Hv), 512, ATTN_SMEM>>>();
    out_gemm_p<<<dim3(Mv / 128, Dv / 128), 256, GEMM_SMEM>>>(bo, out);
}

// round 11
// speedup vs baseline: 1.2182x; 1.0199x over previous
#include <cuda_runtime.h>
#include <cuda_bf16.h>
#include <mma.h>
#include <cstdint>

using namespace nvcuda;

#define TBv 16
#define Nv  1024
#define Dv  512
#define Hv  8
#define HDv 64
#define Mv  (TBv * Nv)

__device__ __nv_bfloat16 gx_hi[(size_t)Mv * Dv], gx_lo[(size_t)Mv * Dv];
__device__ __nv_bfloat16 gw_hi[4 * Dv * Dv],     gw_lo[4 * Dv * Dv];
__device__ __nv_bfloat16 gq_hi[(size_t)Mv * Dv], gq_lo[(size_t)Mv * Dv];
__device__ __nv_bfloat16 gk_hi[(size_t)Mv * Dv], gk_lo[(size_t)Mv * Dv];
__device__ __nv_bfloat16 gv_hi[(size_t)Mv * Dv], gv_lo[(size_t)Mv * Dv];
__device__ __nv_bfloat16 gc_hi[(size_t)Mv * Dv], gc_lo[(size_t)Mv * Dv];

__device__ __forceinline__ uint32_t pack_bf2(__nv_bfloat16 a, __nv_bfloat16 b) {
    __nv_bfloat162 p = __halves2bfloat162(a, b);
    return *(uint32_t*)&p;
}
__device__ __forceinline__ void split_store4(float4 v,
                                             __nv_bfloat16* __restrict__ hp,
                                             __nv_bfloat16* __restrict__ lp)
{
    __nv_bfloat16 hx = __float2bfloat16_rn(v.x), hy = __float2bfloat16_rn(v.y);
    __nv_bfloat16 hz = __float2bfloat16_rn(v.z), hw = __float2bfloat16_rn(v.w);
    ((uint32_t*)hp)[0] = pack_bf2(hx, hy);
    ((uint32_t*)hp)[1] = pack_bf2(hz, hw);
    ((uint32_t*)lp)[0] = pack_bf2(__float2bfloat16_rn(v.x - __bfloat162float(hx)),
                                  __float2bfloat16_rn(v.y - __bfloat162float(hy)));
    ((uint32_t*)lp)[1] = pack_bf2(__float2bfloat16_rn(v.z - __bfloat162float(hz)),
                                  __float2bfloat16_rn(v.w - __bfloat162float(hw)));
}
__device__ __forceinline__ void cp16(uint32_t dst, const void* src) {
    asm volatile("cp.async.cg.shared.global [%0], [%1], 16;" :: "r"(dst), "l"(src));
}
__device__ __forceinline__ void cp_commit() {
    asm volatile("cp.async.commit_group;" ::: "memory");
}
__device__ __forceinline__ void ldsm4(uint32_t (&r)[4], uint32_t a) {
    asm volatile("ldmatrix.sync.aligned.m8n8.x4.shared.b16 {%0,%1,%2,%3}, [%4];"
                 : "=r"(r[0]), "=r"(r[1]), "=r"(r[2]), "=r"(r[3]) : "r"(a));
}
__device__ __forceinline__ void ldsm4t(uint32_t (&r)[4], uint32_t a) {
    asm volatile("ldmatrix.sync.aligned.m8n8.x4.trans.shared.b16 {%0,%1,%2,%3}, [%4];"
                 : "=r"(r[0]), "=r"(r[1]), "=r"(r[2]), "=r"(r[3]) : "r"(a));
}
__device__ __forceinline__ void mma16816(float (&c)[4], const uint32_t (&a)[4],
                                         uint32_t b0, uint32_t b1) {
    asm volatile(
        "mma.sync.aligned.m16n8k16.row.col.f32.bf16.bf16.f32 "
        "{%0,%1,%2,%3}, {%4,%5,%6,%7}, {%8,%9}, {%0,%1,%2,%3};"
        : "+f"(c[0]), "+f"(c[1]), "+f"(c[2]), "+f"(c[3])
        : "r"(a[0]), "r"(a[1]), "r"(a[2]), "r"(a[3]), "r"(b0), "r"(b1));
}

using BFragA  = wmma::fragment<wmma::matrix_a, 16, 16, 16, __nv_bfloat16, wmma::row_major>;
using BFragBc = wmma::fragment<wmma::matrix_b, 16, 16, 16, __nv_bfloat16, wmma::col_major>;
using FragC   = wmma::fragment<wmma::accumulator, 16, 16, 16, float>;

// ---------------------------------------------------------------------------
#define NXf4 (Mv * Dv / 4)
#define NWf4 (Dv * Dv / 4)

__global__ __launch_bounds__(256) void split_kernel(
    const float* __restrict__ x,
    const float* __restrict__ wq, const float* __restrict__ wk,
    const float* __restrict__ wv, const float* __restrict__ wo)
{
    int i = blockIdx.x * 256 + threadIdx.x;
    const float* src; __nv_bfloat16 *dh, *dl; int j;
    if (i < NXf4) { src = x; j = i; dh = gx_hi; dl = gx_lo; }
    else {
        int r = i - NXf4;
        if (r >= 4 * NWf4) return;
        int sel = r / NWf4; j = r % NWf4;
        src = (sel == 0) ? wq : (sel == 1) ? wk : (sel == 2) ? wv : wo;
        dh = gw_hi + (size_t)sel * Dv * Dv;
        dl = gw_lo + (size_t)sel * Dv * Dv;
    }
    float4 v = ((const float4*)src)[j];
    split_store4(v, dh + 4 * (size_t)j, dl + 4 * (size_t)j);
}

// ===========================================================================
// GEMM (unchanged from R10 winner): C[128x128] = A(hi+lo).B(hi+lo)^T, K=512.
// 256 thr, 8 warps (2m x 4n), warp 64x32. Single smem buffer, per chunk:
// LDG(regs) -> sync -> STS -> sync -> 2 ksteps.
// ===========================================================================
#define G_PLE  5120
#define G_PLB  10240
#define G_BIAS 40960
#define GEMM_SMEM (40960 + 512)

__device__ __forceinline__ void g_kstep(const char* smc, int ks,
                                        int wm, int wn, FragC (&acc)[4][2])
{
    const __nv_bfloat16* S = (const __nv_bfloat16*)smc;
    BFragA ahi[4], alo[4];
#pragma unroll
    for (int i = 0; i < 4; ++i) {
        wmma::load_matrix_sync(ahi[i], S + (wm + 16 * i) * 40 + ks * 16, 40);
        wmma::load_matrix_sync(alo[i], S + G_PLE + (wm + 16 * i) * 40 + ks * 16, 40);
    }
#pragma unroll
    for (int j = 0; j < 2; ++j) {
        BFragBc bhi, blo;
        wmma::load_matrix_sync(bhi, S + 2 * G_PLE + (wn + 16 * j) * 40 + ks * 16, 40);
        wmma::load_matrix_sync(blo, S + 3 * G_PLE + (wn + 16 * j) * 40 + ks * 16, 40);
#pragma unroll
        for (int i = 0; i < 4; ++i) {
            wmma::mma_sync(acc[i][j], ahi[i], bhi, acc[i][j]);
            wmma::mma_sync(acc[i][j], ahi[i], blo, acc[i][j]);
            wmma::mma_sync(acc[i][j], alo[i], bhi, acc[i][j]);
        }
    }
}

__device__ __forceinline__ void gemm_single(
    const __nv_bfloat16* __restrict__ Ah, const __nv_bfloat16* __restrict__ Al,
    const __nv_bfloat16* __restrict__ Bh, const __nv_bfloat16* __restrict__ Bl,
    char* smc, FragC (&acc)[4][2])
{
    const int t = threadIdx.x;
    const int w = t >> 5;
    const int wm = (w & 1) * 64;
    const int wn = (w >> 1) * 32;
#pragma unroll
    for (int i = 0; i < 4; ++i)
#pragma unroll
        for (int j = 0; j < 2; ++j)
            wmma::fill_fragment(acc[i][j], 0.0f);

    for (int ch = 0; ch < 16; ++ch) {
        uint4 rg[8];
#pragma unroll
        for (int hh = 0; hh < 2; ++hh) {
            const int o = t + 256 * hh;
            const size_t off = (size_t)(o >> 2) * Dv + ch * 32 + (o & 3) * 8;
            rg[4 * hh + 0] = *(const uint4*)(Ah + off);
            rg[4 * hh + 1] = *(const uint4*)(Al + off);
            rg[4 * hh + 2] = *(const uint4*)(Bh + off);
            rg[4 * hh + 3] = *(const uint4*)(Bl + off);
        }
        __syncthreads();
#pragma unroll
        for (int hh = 0; hh < 2; ++hh) {
            const int o = t + 256 * hh;
            const int off = (o >> 2) * 80 + (o & 3) * 16;
            *(uint4*)(smc + off)             = rg[4 * hh + 0];
            *(uint4*)(smc + G_PLB + off)     = rg[4 * hh + 1];
            *(uint4*)(smc + 2 * G_PLB + off) = rg[4 * hh + 2];
            *(uint4*)(smc + 3 * G_PLB + off) = rg[4 * hh + 3];
        }
        __syncthreads();
        g_kstep(smc, 0, wm, wn, acc);
        g_kstep(smc, 1, wm, wn, acc);
    }
}

__global__ __launch_bounds__(256, 2) void qkv_gemm_p(
    const float* __restrict__ bq, const float* __restrict__ bk,
    const float* __restrict__ bv)
{
    extern __shared__ char smc[];
    const int t = threadIdx.x;
    const int m0   = blockIdx.x * 128;
    const int wsel = blockIdx.y >> 2;
    const int n0   = (blockIdx.y & 3) * 128;

    const float* bias = (wsel == 0) ? bq : (wsel == 1) ? bk : bv;
    __nv_bfloat16* oh = (wsel == 0) ? gq_hi : (wsel == 1) ? gk_hi : gv_hi;
    __nv_bfloat16* ol = (wsel == 0) ? gq_lo : (wsel == 1) ? gk_lo : gv_lo;

    float* biasS = (float*)(smc + G_BIAS);
    if (t < 128) biasS[t] = bias[n0 + t];

    FragC acc[4][2];
    gemm_single(gx_hi + (size_t)m0 * Dv, gx_lo + (size_t)m0 * Dv,
                gw_hi + (size_t)wsel * Dv * Dv + (size_t)n0 * Dv,
                gw_lo + (size_t)wsel * Dv * Dv + (size_t)n0 * Dv, smc, acc);

    float* Cs = (float*)smc;
    const int w = t >> 5, wn = (w >> 1) * 32;
    const int erow = t >> 2;
    const int ecol = (t & 3) * 32;
#pragma unroll
    for (int p = 0; p < 2; ++p) {
        __syncthreads();
        if ((w & 1) == p) {
#pragma unroll
            for (int i = 0; i < 4; ++i)
#pragma unroll
                for (int j = 0; j < 2; ++j)
                    wmma::store_matrix_sync(&Cs[(16 * i) * 132 + wn + 16 * j],
                                            acc[i][j], 132, wmma::mem_row_major);
        }
        __syncthreads();
        const int m  = m0 + p * 64 + erow;
        const int tb = m >> 10, n = m & 1023;
        const int h  = (n0 + ecol) >> 6;
        const int hd0 = (n0 + ecol) & 63;
        __nv_bfloat16* dh = oh + ((size_t)(tb * Hv + h) * Nv + n) * HDv + hd0;
        __nv_bfloat16* dl = ol + ((size_t)(tb * Hv + h) * Nv + n) * HDv + hd0;
#pragma unroll
        for (int c = 0; c < 32; c += 4) {
            float4 v = *(float4*)&Cs[erow * 132 + ecol + c];
            v.x += biasS[ecol + c + 0]; v.y += biasS[ecol + c + 1];
            v.z += biasS[ecol + c + 2]; v.w += biasS[ecol + c + 3];
            split_store4(v, dh + c, dl + c);
        }
    }
}

__global__ __launch_bounds__(256, 2) void out_gemm_p(
    const float* __restrict__ bo, float* __restrict__ out)
{
    extern __shared__ char smc[];
    const int t = threadIdx.x;
    const int m0 = blockIdx.x * 128;
    const int n0 = blockIdx.y * 128;

    float* biasS = (float*)(smc + G_BIAS);
    if (t < 128) biasS[t] = bo[n0 + t];

    FragC acc[4][2];
    gemm_single(gc_hi + (size_t)m0 * Dv, gc_lo + (size_t)m0 * Dv,
                gw_hi + (size_t)3 * Dv * Dv + (size_t)n0 * Dv,
                gw_lo + (size_t)3 * Dv * Dv + (size_t)n0 * Dv, smc, acc);

    float* Cs = (float*)smc;
    const int w = t >> 5, wn = (w >> 1) * 32;
    const int erow = t >> 2;
    const int ecol = (t & 3) * 32;
#pragma unroll
    for (int p = 0; p < 2; ++p) {
        __syncthreads();
        if ((w & 1) == p) {
#pragma unroll
            for (int i = 0; i < 4; ++i)
#pragma unroll
                for (int j = 0; j < 2; ++j)
                    wmma::store_matrix_sync(&Cs[(16 * i) * 132 + wn + 16 * j],
                                            acc[i][j], 132, wmma::mem_row_major);
        }
        __syncthreads();
        float* dst = out + (size_t)(m0 + p * 64 + erow) * Dv + n0 + ecol;
#pragma unroll
        for (int c = 0; c < 32; c += 4) {
            float4 v = *(float4*)&Cs[erow * 132 + ecol + c];
            v.x += biasS[ecol + c + 0]; v.y += biasS[ecol + c + 1];
            v.z += biasS[ecol + c + 2]; v.w += biasS[ecol + c + 3];
            *(float4*)(dst + c) = v;
        }
    }
}

// ===========================================================================
// Attention: mma.sync m16n8k16, S in registers. NOW 256 thr, 8 warps;
// warp = 32 q-rows (two 16-row groups) x 64 keys x 64 hd — K/V ldmatrix
// traffic amortized over 2x MMA. Block = 256 q-rows; K/V 3-stage ring.
// ===========================================================================
#define AT_Q    0
#define AT_KV   73728
#define AT_STG  36864
#define AT_PL   9216
#define ATTN_SMEM (73728 + 3 * 36864)

__device__ __forceinline__ void kv_prefetch(uint32_t dstbase, size_t hb,
                                            int row0, int t)
{
    const __nv_bfloat16* kvp[4] = {gk_hi + hb, gk_lo + hb, gv_hi + hb, gv_lo + hb};
#pragma unroll
    for (int hh = 0; hh < 8; ++hh) {
        const int o = t + 256 * hh;            // 0..2047
        const int plane = o >> 9;
        const int idx = o & 511;
        cp16(dstbase + plane * AT_PL + (idx >> 3) * 144 + (idx & 7) * 16,
             kvp[plane] + (size_t)(row0 + (idx >> 3)) * HDv + (idx & 7) * 8);
    }
}

__global__ __launch_bounds__(256, 1) void attn_m()
{
    extern __shared__ char smc[];
    const uint32_t sb = (uint32_t)__cvta_generic_to_shared(smc);
    const int t = threadIdx.x;
    const int l = t & 31;
    const int w = t >> 5;                      // 0..7
    const int qn0 = blockIdx.x * 256;
    const int tbh = blockIdx.y;
    const size_t hb = (size_t)tbh * Nv * HDv;

    // Q planes (2 x 256 rows) + KV tiles 0,1
#pragma unroll
    for (int hh = 0; hh < 16; ++hh) {
        const int o = t + 256 * hh;            // 0..4095
        const int plane = o >> 11;
        const int idx = o & 2047;
        const __nv_bfloat16* src =
            (plane ? gq_lo : gq_hi) + hb + (size_t)(qn0 + (idx >> 3)) * HDv + (idx & 7) * 8;
        cp16(sb + AT_Q + plane * 36864 + (idx >> 3) * 144 + (idx & 7) * 16, src);
    }
    kv_prefetch(sb + AT_KV, hb, 0, t);
    cp_commit();
    kv_prefetch(sb + AT_KV + AT_STG, hb, 64, t);
    cp_commit();

    const int wrow = w * 32;
    uint32_t qaddr[2];
    qaddr[0] = sb + AT_Q + (wrow + (l & 15)) * 144 + (l >> 4) * 16;
    qaddr[1] = qaddr[0] + 16 * 144;
    const int kroff = ((l & 7) + ((l >> 4) & 1) * 8) * 144 + ((l >> 3) & 1) * 16;
    const int vroff = ((l & 7) + ((l >> 3) & 1) * 8) * 144 + ((l >> 4) & 1) * 16;

    float ctx[2][8][4];
#pragma unroll
    for (int g = 0; g < 2; ++g)
#pragma unroll
        for (int i = 0; i < 8; ++i)
#pragma unroll
            for (int j = 0; j < 4; ++j) ctx[g][i][j] = 0.f;
    float ds[2][2] = {{0.f, 0.f}, {0.f, 0.f}};

    int stage = 0;
    for (int kt = 0; kt < 16; ++kt) {
        if (kt < 15) asm volatile("cp.async.wait_group 1;" ::: "memory");
        else         asm volatile("cp.async.wait_group 0;" ::: "memory");
        __syncthreads();
        if (kt < 14) {
            int ns = stage + 2; if (ns >= 3) ns -= 3;
            kv_prefetch(sb + AT_KV + ns * AT_STG, hb, (kt + 2) * 64, t);
            cp_commit();
        }
        const uint32_t kst = sb + AT_KV + stage * AT_STG;
        if (++stage == 3) stage = 0;

        // S = Q K^T for both 16-row groups, S in registers
        float sacc[2][8][4];
#pragma unroll
        for (int g = 0; g < 2; ++g)
#pragma unroll
            for (int i = 0; i < 8; ++i)
#pragma unroll
                for (int j = 0; j < 4; ++j) sacc[g][i][j] = 0.f;
#pragma unroll
        for (int ks = 0; ks < 4; ++ks) {
            uint32_t aqh[2][4], aql[2][4];
            ldsm4(aqh[0], qaddr[0] + ks * 32);
            ldsm4(aql[0], qaddr[0] + 36864 + ks * 32);
            ldsm4(aqh[1], qaddr[1] + ks * 32);
            ldsm4(aql[1], qaddr[1] + 36864 + ks * 32);
#pragma unroll
            for (int np = 0; np < 4; ++np) {
                uint32_t bh[4], bl[4];
                ldsm4(bh, kst + np * 16 * 144 + kroff + ks * 32);
                ldsm4(bl, kst + AT_PL + np * 16 * 144 + kroff + ks * 32);
#pragma unroll
                for (int g = 0; g < 2; ++g) {
                    mma16816(sacc[g][2 * np],     aqh[g], bh[0], bh[1]);
                    mma16816(sacc[g][2 * np],     aqh[g], bl[0], bl[1]);
                    mma16816(sacc[g][2 * np],     aql[g], bh[0], bh[1]);
                    mma16816(sacc[g][2 * np + 1], aqh[g], bh[2], bh[3]);
                    mma16816(sacc[g][2 * np + 1], aqh[g], bl[2], bl[3]);
                    mma16816(sacc[g][2 * np + 1], aql[g], bh[2], bh[3]);
                }
            }
        }

        // relu/scale/rowsum/split in registers, then ctx += S V
#pragma unroll
        for (int kf = 0; kf < 4; ++kf) {
            uint32_t sah[2][4], sal[2][4];
#pragma unroll
            for (int g = 0; g < 2; ++g) {
#pragma unroll
                for (int hh = 0; hh < 2; ++hh) {
                    float* c = sacc[g][2 * kf + hh];
                    float c0 = fmaxf(c[0] * 0.125f, 0.f);
                    float c1 = fmaxf(c[1] * 0.125f, 0.f);
                    float c2 = fmaxf(c[2] * 0.125f, 0.f);
                    float c3 = fmaxf(c[3] * 0.125f, 0.f);
                    ds[g][0] += c0 + c1;
                    ds[g][1] += c2 + c3;
                    __nv_bfloat16 h0 = __float2bfloat16_rn(c0);
                    __nv_bfloat16 h1 = __float2bfloat16_rn(c1);
                    __nv_bfloat16 h2 = __float2bfloat16_rn(c2);
                    __nv_bfloat16 h3 = __float2bfloat16_rn(c3);
                    sah[g][2 * hh + 0] = pack_bf2(h0, h1);
                    sah[g][2 * hh + 1] = pack_bf2(h2, h3);
                    sal[g][2 * hh + 0] = pack_bf2(
                        __float2bfloat16_rn(c0 - __bfloat162float(h0)),
                        __float2bfloat16_rn(c1 - __bfloat162float(h1)));
                    sal[g][2 * hh + 1] = pack_bf2(
                        __float2bfloat16_rn(c2 - __bfloat162float(h2)),
                        __float2bfloat16_rn(c3 - __bfloat162float(h3)));
                }
            }
#pragma unroll
            for (int np = 0; np < 4; ++np) {
                uint32_t bvh[4], bvl[4];
                ldsm4t(bvh, kst + 2 * AT_PL + kf * 16 * 144 + vroff + np * 32);
                ldsm4t(bvl, kst + 3 * AT_PL + kf * 16 * 144 + vroff + np * 32);
#pragma unroll
                for (int g = 0; g < 2; ++g) {
                    mma16816(ctx[g][2 * np],     sah[g], bvh[0], bvh[1]);
                    mma16816(ctx[g][2 * np],     sah[g], bvl[0], bvl[1]);
                    mma16816(ctx[g][2 * np],     sal[g], bvh[0], bvh[1]);
                    mma16816(ctx[g][2 * np + 1], sah[g], bvh[2], bvh[3]);
                    mma16816(ctx[g][2 * np + 1], sah[g], bvl[2], bvl[3]);
                    mma16816(ctx[g][2 * np + 1], sal[g], bvh[2], bvh[3]);
                }
            }
        }
    }

    // epilogue: quad-reduce rowsums per group, normalize, write ctx planes
    const int gl = l >> 2, tg = l & 3;
    const int hd0 = (tbh & 7) * HDv;
#pragma unroll
    for (int g = 0; g < 2; ++g) {
        float d0 = ds[g][0], d1 = ds[g][1];
        d0 += __shfl_xor_sync(0xffffffffu, d0, 1);
        d0 += __shfl_xor_sync(0xffffffffu, d0, 2);
        d1 += __shfl_xor_sync(0xffffffffu, d1, 1);
        d1 += __shfl_xor_sync(0xffffffffu, d1, 2);
        const float inv0 = 1.f / (d0 + 1e-6f);
        const float inv1 = 1.f / (d1 + 1e-6f);

        const int mtok = (tbh >> 3) * Nv + qn0 + wrow + g * 16 + gl;
        __nv_bfloat16* dh0 = gc_hi + (size_t)mtok * Dv + hd0;
        __nv_bfloat16* dl0 = gc_lo + (size_t)mtok * Dv + hd0;
        __nv_bfloat16* dh1 = dh0 + 8 * Dv;
        __nv_bfloat16* dl1 = dl0 + 8 * Dv;
#pragma unroll
        for (int i = 0; i < 8; ++i) {
            const int d = (i >> 1) * 16 + (i & 1) * 8 + tg * 2;
            float v0 = ctx[g][i][0] * inv0, v1 = ctx[g][i][1] * inv0;
            float v2 = ctx[g][i][2] * inv1, v3 = ctx[g][i][3] * inv1;
            __nv_bfloat16 h0 = __float2bfloat16_rn(v0);
            __nv_bfloat16 h1 = __float2bfloat16_rn(v1);
            __nv_bfloat16 h2 = __float2bfloat16_rn(v2);
            __nv_bfloat16 h3 = __float2bfloat16_rn(v3);
            *(uint32_t*)(dh0 + d) = pack_bf2(h0, h1);
            *(uint32_t*)(dl0 + d) = pack_bf2(
                __float2bfloat16_rn(v0 - __bfloat162float(h0)),
                __float2bfloat16_rn(v1 - __bfloat162float(h1)));
            *(uint32_t*)(dh1 + d) = pack_bf2(h2, h3);
            *(uint32_t*)(dl1 + d) = pack_bf2(
                __float2bfloat16_rn(v2 - __bfloat162float(h2)),
                __float2bfloat16_rn(v3 - __bfloat162float(h3)));
        }
    }
}

// ---------------------------------------------------------------------------
extern "C" void kernel_launch(void* const* d_in, const int* in_sizes, int n_in,
                              void* d_out, int out_size)
{
    const float* x  = (const float*)d_in[0];
    const float* wq = (const float*)d_in[1];
    const float* bq = (const float*)d_in[2];
    const float* wk = (const float*)d_in[3];
    const float* bk = (const float*)d_in[4];
    const float* wv = (const float*)d_in[5];
    const float* bv = (const float*)d_in[6];
    const float* wo = (const float*)d_in[7];
    const float* bo = (const float*)d_in[8];
    float* out = (float*)d_out;

    cudaFuncSetAttribute(qkv_gemm_p, cudaFuncAttributeMaxDynamicSharedMemorySize, GEMM_SMEM);
    cudaFuncSetAttribute(out_gemm_p, cudaFuncAttributeMaxDynamicSharedMemorySize, GEMM_SMEM);
    cudaFuncSetAttribute(attn_m, cudaFuncAttributeMaxDynamicSharedMemorySize, ATTN_SMEM);

    const int splitBlocks = (NXf4 + 4 * NWf4 + 255) / 256;
    split_kernel<<<splitBlocks, 256>>>(x, wq, wk, wv, wo);
    qkv_gemm_p<<<dim3(Mv / 128, 12), 256, GEMM_SMEM>>>(bq, bk, bv);
    attn_m<<<dim3(Nv / 256, TBv * Hv), 256, ATTN_SMEM>>>();
    out_gemm_p<<<dim3(Mv / 128, Dv / 128), 256, GEMM_SMEM>>>(bo, out);
}

// round 12
// speedup vs baseline: 1.2915x; 1.0602x over previous
#include <cuda_runtime.h>
#include <cuda_bf16.h>
#include <mma.h>
#include <cstdint>

using namespace nvcuda;

#define TBv 16
#define Nv  1024
#define Dv  512
#define Hv  8
#define HDv 64
#define Mv  (TBv * Nv)

__device__ __nv_bfloat16 gx_hi[(size_t)Mv * Dv], gx_lo[(size_t)Mv * Dv];
__device__ __nv_bfloat16 gw_hi[4 * Dv * Dv],     gw_lo[4 * Dv * Dv];
__device__ __nv_bfloat16 gq_hi[(size_t)Mv * Dv], gq_lo[(size_t)Mv * Dv];
__device__ __nv_bfloat16 gk_hi[(size_t)Mv * Dv], gk_lo[(size_t)Mv * Dv];
__device__ __nv_bfloat16 gv_hi[(size_t)Mv * Dv], gv_lo[(size_t)Mv * Dv];
__device__ __nv_bfloat16 gc_hi[(size_t)Mv * Dv], gc_lo[(size_t)Mv * Dv];

__device__ __forceinline__ uint32_t pack_bf2(__nv_bfloat16 a, __nv_bfloat16 b) {
    __nv_bfloat162 p = __halves2bfloat162(a, b);
    return *(uint32_t*)&p;
}
__device__ __forceinline__ void split_store4(float4 v,
                                             __nv_bfloat16* __restrict__ hp,
                                             __nv_bfloat16* __restrict__ lp)
{
    __nv_bfloat16 hx = __float2bfloat16_rn(v.x), hy = __float2bfloat16_rn(v.y);
    __nv_bfloat16 hz = __float2bfloat16_rn(v.z), hw = __float2bfloat16_rn(v.w);
    ((uint32_t*)hp)[0] = pack_bf2(hx, hy);
    ((uint32_t*)hp)[1] = pack_bf2(hz, hw);
    ((uint32_t*)lp)[0] = pack_bf2(__float2bfloat16_rn(v.x - __bfloat162float(hx)),
                                  __float2bfloat16_rn(v.y - __bfloat162float(hy)));
    ((uint32_t*)lp)[1] = pack_bf2(__float2bfloat16_rn(v.z - __bfloat162float(hz)),
                                  __float2bfloat16_rn(v.w - __bfloat162float(hw)));
}
__device__ __forceinline__ void cp16(uint32_t dst, const void* src) {
    asm volatile("cp.async.cg.shared.global [%0], [%1], 16;" :: "r"(dst), "l"(src));
}
__device__ __forceinline__ void cp_commit() {
    asm volatile("cp.async.commit_group;" ::: "memory");
}
__device__ __forceinline__ void ldsm4(uint32_t (&r)[4], uint32_t a) {
    asm volatile("ldmatrix.sync.aligned.m8n8.x4.shared.b16 {%0,%1,%2,%3}, [%4];"
                 : "=r"(r[0]), "=r"(r[1]), "=r"(r[2]), "=r"(r[3]) : "r"(a));
}
__device__ __forceinline__ void ldsm4t(uint32_t (&r)[4], uint32_t a) {
    asm volatile("ldmatrix.sync.aligned.m8n8.x4.trans.shared.b16 {%0,%1,%2,%3}, [%4];"
                 : "=r"(r[0]), "=r"(r[1]), "=r"(r[2]), "=r"(r[3]) : "r"(a));
}
__device__ __forceinline__ void mma16816(float (&c)[4], const uint32_t (&a)[4],
                                         uint32_t b0, uint32_t b1) {
    asm volatile(
        "mma.sync.aligned.m16n8k16.row.col.f32.bf16.bf16.f32 "
        "{%0,%1,%2,%3}, {%4,%5,%6,%7}, {%8,%9}, {%0,%1,%2,%3};"
        : "+f"(c[0]), "+f"(c[1]), "+f"(c[2]), "+f"(c[3])
        : "r"(a[0]), "r"(a[1]), "r"(a[2]), "r"(a[3]), "r"(b0), "r"(b1));
}

using BFragA  = wmma::fragment<wmma::matrix_a, 16, 16, 16, __nv_bfloat16, wmma::row_major>;
using BFragBc = wmma::fragment<wmma::matrix_b, 16, 16, 16, __nv_bfloat16, wmma::col_major>;
using FragC   = wmma::fragment<wmma::accumulator, 16, 16, 16, float>;

// ---------------------------------------------------------------------------
#define NXf4 (Mv * Dv / 4)
#define NWf4 (Dv * Dv / 4)

__global__ __launch_bounds__(256) void split_kernel(
    const float* __restrict__ x,
    const float* __restrict__ wq, const float* __restrict__ wk,
    const float* __restrict__ wv, const float* __restrict__ wo)
{
    int i = blockIdx.x * 256 + threadIdx.x;
    const float* src; __nv_bfloat16 *dh, *dl; int j;
    if (i < NXf4) { src = x; j = i; dh = gx_hi; dl = gx_lo; }
    else {
        int r = i - NXf4;
        if (r >= 4 * NWf4) return;
        int sel = r / NWf4; j = r % NWf4;
        src = (sel == 0) ? wq : (sel == 1) ? wk : (sel == 2) ? wv : wo;
        dh = gw_hi + (size_t)sel * Dv * Dv;
        dl = gw_lo + (size_t)sel * Dv * Dv;
    }
    float4 v = ((const float4*)src)[j];
    split_store4(v, dh + 4 * (size_t)j, dl + 4 * (size_t)j);
}

// ===========================================================================
// Shared GEMM kstep (planes at +0/+5120/+10240/+15360 elems, stride 40)
// ===========================================================================
#define G_PLE  5120
#define G_PLB  10240

__device__ __forceinline__ void g_kstep(const char* smc, int ks,
                                        int wm, int wn, FragC (&acc)[4][2])
{
    const __nv_bfloat16* S = (const __nv_bfloat16*)smc;
    BFragA ahi[4], alo[4];
#pragma unroll
    for (int i = 0; i < 4; ++i) {
        wmma::load_matrix_sync(ahi[i], S + (wm + 16 * i) * 40 + ks * 16, 40);
        wmma::load_matrix_sync(alo[i], S + G_PLE + (wm + 16 * i) * 40 + ks * 16, 40);
    }
#pragma unroll
    for (int j = 0; j < 2; ++j) {
        BFragBc bhi, blo;
        wmma::load_matrix_sync(bhi, S + 2 * G_PLE + (wn + 16 * j) * 40 + ks * 16, 40);
        wmma::load_matrix_sync(blo, S + 3 * G_PLE + (wn + 16 * j) * 40 + ks * 16, 40);
#pragma unroll
        for (int i = 0; i < 4; ++i) {
            wmma::mma_sync(acc[i][j], ahi[i], bhi, acc[i][j]);
            wmma::mma_sync(acc[i][j], ahi[i], blo, acc[i][j]);
            wmma::mma_sync(acc[i][j], alo[i], bhi, acc[i][j]);
        }
    }
}

// ---- qkv GEMM: R10 reg-staged single-buffer schedule -----------------------
#define G_BIAS 40960
#define GEMM_SMEM (40960 + 512)

__device__ __forceinline__ void gemm_single(
    const __nv_bfloat16* __restrict__ Ah, const __nv_bfloat16* __restrict__ Al,
    const __nv_bfloat16* __restrict__ Bh, const __nv_bfloat16* __restrict__ Bl,
    char* smc, FragC (&acc)[4][2])
{
    const int t = threadIdx.x;
    const int w = t >> 5;
    const int wm = (w & 1) * 64;
    const int wn = (w >> 1) * 32;
#pragma unroll
    for (int i = 0; i < 4; ++i)
#pragma unroll
        for (int j = 0; j < 2; ++j)
            wmma::fill_fragment(acc[i][j], 0.0f);

    for (int ch = 0; ch < 16; ++ch) {
        uint4 rg[8];
#pragma unroll
        for (int hh = 0; hh < 2; ++hh) {
            const int o = t + 256 * hh;
            const size_t off = (size_t)(o >> 2) * Dv + ch * 32 + (o & 3) * 8;
            rg[4 * hh + 0] = *(const uint4*)(Ah + off);
            rg[4 * hh + 1] = *(const uint4*)(Al + off);
            rg[4 * hh + 2] = *(const uint4*)(Bh + off);
            rg[4 * hh + 3] = *(const uint4*)(Bl + off);
        }
        __syncthreads();
#pragma unroll
        for (int hh = 0; hh < 2; ++hh) {
            const int o = t + 256 * hh;
            const int off = (o >> 2) * 80 + (o & 3) * 16;
            *(uint4*)(smc + off)             = rg[4 * hh + 0];
            *(uint4*)(smc + G_PLB + off)     = rg[4 * hh + 1];
            *(uint4*)(smc + 2 * G_PLB + off) = rg[4 * hh + 2];
            *(uint4*)(smc + 3 * G_PLB + off) = rg[4 * hh + 3];
        }
        __syncthreads();
        g_kstep(smc, 0, wm, wn, acc);
        g_kstep(smc, 1, wm, wn, acc);
    }
}

__global__ __launch_bounds__(256, 2) void qkv_gemm_p(
    const float* __restrict__ bq, const float* __restrict__ bk,
    const float* __restrict__ bv)
{
    extern __shared__ char smc[];
    const int t = threadIdx.x;
    const int m0   = blockIdx.x * 128;
    const int wsel = blockIdx.y >> 2;
    const int n0   = (blockIdx.y & 3) * 128;

    const float* bias = (wsel == 0) ? bq : (wsel == 1) ? bk : bv;
    __nv_bfloat16* oh = (wsel == 0) ? gq_hi : (wsel == 1) ? gk_hi : gv_hi;
    __nv_bfloat16* ol = (wsel == 0) ? gq_lo : (wsel == 1) ? gk_lo : gv_lo;

    float* biasS = (float*)(smc + G_BIAS);
    if (t < 128) biasS[t] = bias[n0 + t];

    FragC acc[4][2];
    gemm_single(gx_hi + (size_t)m0 * Dv, gx_lo + (size_t)m0 * Dv,
                gw_hi + (size_t)wsel * Dv * Dv + (size_t)n0 * Dv,
                gw_lo + (size_t)wsel * Dv * Dv + (size_t)n0 * Dv, smc, acc);

    float* Cs = (float*)smc;
    const int w = t >> 5, wn = (w >> 1) * 32;
    const int erow = t >> 2;
    const int ecol = (t & 3) * 32;
#pragma unroll
    for (int p = 0; p < 2; ++p) {
        __syncthreads();
        if ((w & 1) == p) {
#pragma unroll
            for (int i = 0; i < 4; ++i)
#pragma unroll
                for (int j = 0; j < 2; ++j)
                    wmma::store_matrix_sync(&Cs[(16 * i) * 132 + wn + 16 * j],
                                            acc[i][j], 132, wmma::mem_row_major);
        }
        __syncthreads();
        const int m  = m0 + p * 64 + erow;
        const int tb = m >> 10, n = m & 1023;
        const int h  = (n0 + ecol) >> 6;
        const int hd0 = (n0 + ecol) & 63;
        __nv_bfloat16* dh = oh + ((size_t)(tb * Hv + h) * Nv + n) * HDv + hd0;
        __nv_bfloat16* dl = ol + ((size_t)(tb * Hv + h) * Nv + n) * HDv + hd0;
#pragma unroll
        for (int c = 0; c < 32; c += 4) {
            float4 v = *(float4*)&Cs[erow * 132 + ecol + c];
            v.x += biasS[ecol + c + 0]; v.y += biasS[ecol + c + 1];
            v.z += biasS[ecol + c + 2]; v.w += biasS[ecol + c + 3];
            split_store4(v, dh + c, dl + c);
        }
    }
}

// ---- out GEMM: R6 cp.async 2-stage pipeline (measured best: 111 us) --------
#define G2_STG  40960
#define G2_BIAS 81920
#define GEMM2_SMEM (81920 + 512)

__device__ __forceinline__ void g2_prefetch(
    uint32_t sb, int stage,
    const __nv_bfloat16* __restrict__ Ah, const __nv_bfloat16* __restrict__ Al,
    const __nv_bfloat16* __restrict__ Bh, const __nv_bfloat16* __restrict__ Bl,
    int k0, int t)
{
    const __nv_bfloat16* pl[4] = {Ah, Al, Bh, Bl};
    const uint32_t base = sb + stage * G2_STG;
#pragma unroll
    for (int p = 0; p < 4; ++p) {
#pragma unroll
        for (int hh = 0; hh < 2; ++hh) {
            const int o = t + 256 * hh;
            const int row = o >> 2, seg = o & 3;
            cp16(base + p * G_PLB + row * 80 + seg * 16,
                 pl[p] + (size_t)row * Dv + k0 + seg * 8);
        }
    }
}

__global__ __launch_bounds__(256, 2) void out_gemm_p(
    const float* __restrict__ bo, float* __restrict__ out)
{
    extern __shared__ char smc[];
    const int t = threadIdx.x;
    const int m0 = blockIdx.x * 128;
    const int n0 = blockIdx.y * 128;
    const uint32_t sb = (uint32_t)__cvta_generic_to_shared(smc);

    float* biasS = (float*)(smc + G2_BIAS);
    if (t < 128) biasS[t] = bo[n0 + t];

    const __nv_bfloat16* Ah = gc_hi + (size_t)m0 * Dv;
    const __nv_bfloat16* Al = gc_lo + (size_t)m0 * Dv;
    const __nv_bfloat16* Bh = gw_hi + (size_t)3 * Dv * Dv + (size_t)n0 * Dv;
    const __nv_bfloat16* Bl = gw_lo + (size_t)3 * Dv * Dv + (size_t)n0 * Dv;

    const int w = t >> 5;
    const int wm = (w & 1) * 64;
    const int wn = (w >> 1) * 32;
    FragC acc[4][2];
#pragma unroll
    for (int i = 0; i < 4; ++i)
#pragma unroll
        for (int j = 0; j < 2; ++j)
            wmma::fill_fragment(acc[i][j], 0.0f);

    g2_prefetch(sb, 0, Ah, Al, Bh, Bl, 0, t);
    cp_commit();
    for (int ch = 0; ch < 16; ++ch) {
        if (ch < 15) {
            g2_prefetch(sb, (ch + 1) & 1, Ah, Al, Bh, Bl, (ch + 1) * 32, t);
            cp_commit();
            asm volatile("cp.async.wait_group 1;" ::: "memory");
        } else {
            asm volatile("cp.async.wait_group 0;" ::: "memory");
        }
        __syncthreads();
        g_kstep(smc + (ch & 1) * G2_STG, 0, wm, wn, acc);
        g_kstep(smc + (ch & 1) * G2_STG, 1, wm, wn, acc);
        __syncthreads();
    }

    float* Cs = (float*)smc;
#pragma unroll
    for (int i = 0; i < 4; ++i)
#pragma unroll
        for (int j = 0; j < 2; ++j)
            wmma::store_matrix_sync(&Cs[(wm + 16 * i) * 132 + wn + 16 * j],
                                    acc[i][j], 132, wmma::mem_row_major);
    __syncthreads();

    const int row = t >> 1, c0 = (t & 1) * 64;
    float* dst = out + (size_t)(m0 + row) * Dv + n0 + c0;
#pragma unroll
    for (int c = 0; c < 64; c += 4) {
        float4 v = *(float4*)&Cs[row * 132 + c0 + c];
        v.x += biasS[c0 + c + 0]; v.y += biasS[c0 + c + 1];
        v.z += biasS[c0 + c + 2]; v.w += biasS[c0 + c + 3];
        *(float4*)(dst + c) = v;
    }
}

// ===========================================================================
// Attention: mma.sync m16n8k16, S in registers. 256 thr, 8 warps x 16 q-rows;
// q-tile 128, KV 2-stage ring. smem 110592 B -> 2 blocks/SM (occupancy play).
// ===========================================================================
#define AT_STG  36864
#define AT_PL   9216
#define AT_Q    73728
#define ATTN_SMEM 110592

__device__ __forceinline__ void kv_prefetch(uint32_t dstbase, size_t hb,
                                            int row0, int t)
{
    const __nv_bfloat16* kvp[4] = {gk_hi + hb, gk_lo + hb, gv_hi + hb, gv_lo + hb};
#pragma unroll
    for (int hh = 0; hh < 8; ++hh) {
        const int o = t + 256 * hh;            // 0..2047
        const int plane = o >> 9;
        const int idx = o & 511;
        cp16(dstbase + plane * AT_PL + (idx >> 3) * 144 + (idx & 7) * 16,
             kvp[plane] + (size_t)(row0 + (idx >> 3)) * HDv + (idx & 7) * 8);
    }
}

__global__ __launch_bounds__(256, 2) void attn_m()
{
    extern __shared__ char smc[];
    const uint32_t sb = (uint32_t)__cvta_generic_to_shared(smc);
    const int t = threadIdx.x;
    const int l = t & 31;
    const int w = t >> 5;                      // 0..7
    const int qn0 = blockIdx.x * 128;
    const int tbh = blockIdx.y;
    const size_t hb = (size_t)tbh * Nv * HDv;

    // group0: Q planes (2 x 128 rows) + KV tile 0; group1: KV tile 1
#pragma unroll
    for (int hh = 0; hh < 8; ++hh) {
        const int o = t + 256 * hh;            // 0..2047
        const int plane = o >> 10;
        const int idx = o & 1023;
        const __nv_bfloat16* src =
            (plane ? gq_lo : gq_hi) + hb + (size_t)(qn0 + (idx >> 3)) * HDv + (idx & 7) * 8;
        cp16(sb + AT_Q + plane * 18432 + (idx >> 3) * 144 + (idx & 7) * 16, src);
    }
    kv_prefetch(sb, hb, 0, t);
    cp_commit();
    kv_prefetch(sb + AT_STG, hb, 64, t);
    cp_commit();

    const int wrow = w * 16;
    const uint32_t qaddr = sb + AT_Q + (wrow + (l & 15)) * 144 + (l >> 4) * 16;
    const int kroff = ((l & 7) + ((l >> 4) & 1) * 8) * 144 + ((l >> 3) & 1) * 16;
    const int vroff = ((l & 7) + ((l >> 3) & 1) * 8) * 144 + ((l >> 4) & 1) * 16;

    float ctx[8][4];
#pragma unroll
    for (int i = 0; i < 8; ++i)
#pragma unroll
        for (int j = 0; j < 4; ++j) ctx[i][j] = 0.f;
    float ds0 = 0.f, ds1 = 0.f;

    for (int kt = 0; kt < 16; ++kt) {
        if (kt < 15) asm volatile("cp.async.wait_group 1;" ::: "memory");
        else         asm volatile("cp.async.wait_group 0;" ::: "memory");
        __syncthreads();
        const uint32_t kst = sb + (kt & 1) * AT_STG;

        float sacc[8][4];
#pragma unroll
        for (int i = 0; i < 8; ++i)
#pragma unroll
            for (int j = 0; j < 4; ++j) sacc[i][j] = 0.f;
#pragma unroll
        for (int ks = 0; ks < 4; ++ks) {
            uint32_t aqh[4], aql[4];
            ldsm4(aqh, qaddr + ks * 32);
            ldsm4(aql, qaddr + 18432 + ks * 32);
#pragma unroll
            for (int np = 0; np < 4; ++np) {
                uint32_t bh[4], bl[4];
                ldsm4(bh, kst + np * 16 * 144 + kroff + ks * 32);
                ldsm4(bl, kst + AT_PL + np * 16 * 144 + kroff + ks * 32);
                mma16816(sacc[2 * np],     aqh, bh[0], bh[1]);
                mma16816(sacc[2 * np],     aqh, bl[0], bl[1]);
                mma16816(sacc[2 * np],     aql, bh[0], bh[1]);
                mma16816(sacc[2 * np + 1], aqh, bh[2], bh[3]);
                mma16816(sacc[2 * np + 1], aqh, bl[2], bl[3]);
                mma16816(sacc[2 * np + 1], aql, bh[2], bh[3]);
            }
        }
#pragma unroll
        for (int kf = 0; kf < 4; ++kf) {
            uint32_t sah[4], sal[4];
#pragma unroll
            for (int hh = 0; hh < 2; ++hh) {
                float* c = sacc[2 * kf + hh];
                float c0 = fmaxf(c[0] * 0.125f, 0.f);
                float c1 = fmaxf(c[1] * 0.125f, 0.f);
                float c2 = fmaxf(c[2] * 0.125f, 0.f);
                float c3 = fmaxf(c[3] * 0.125f, 0.f);
                ds0 += c0 + c1;
                ds1 += c2 + c3;
                __nv_bfloat16 h0 = __float2bfloat16_rn(c0);
                __nv_bfloat16 h1 = __float2bfloat16_rn(c1);
                __nv_bfloat16 h2 = __float2bfloat16_rn(c2);
                __nv_bfloat16 h3 = __float2bfloat16_rn(c3);
                sah[2 * hh + 0] = pack_bf2(h0, h1);
                sah[2 * hh + 1] = pack_bf2(h2, h3);
                sal[2 * hh + 0] = pack_bf2(
                    __float2bfloat16_rn(c0 - __bfloat162float(h0)),
                    __float2bfloat16_rn(c1 - __bfloat162float(h1)));
                sal[2 * hh + 1] = pack_bf2(
                    __float2bfloat16_rn(c2 - __bfloat162float(h2)),
                    __float2bfloat16_rn(c3 - __bfloat162float(h3)));
            }
#pragma unroll
            for (int np = 0; np < 4; ++np) {
                uint32_t bvh[4], bvl[4];
                ldsm4t(bvh, kst + 2 * AT_PL + kf * 16 * 144 + vroff + np * 32);
                ldsm4t(bvl, kst + 3 * AT_PL + kf * 16 * 144 + vroff + np * 32);
                mma16816(ctx[2 * np],     sah, bvh[0], bvh[1]);
                mma16816(ctx[2 * np],     sah, bvl[0], bvl[1]);
                mma16816(ctx[2 * np],     sal, bvh[0], bvh[1]);
                mma16816(ctx[2 * np + 1], sah, bvh[2], bvh[3]);
                mma16816(ctx[2 * np + 1], sah, bvl[2], bvl[3]);
                mma16816(ctx[2 * np + 1], sal, bvh[2], bvh[3]);
            }
        }
        __syncthreads();                      // stage consumed
        if (kt < 14) {
            kv_prefetch(sb + (kt & 1) * AT_STG, hb, (kt + 2) * 64, t);
            cp_commit();
        }
    }

    ds0 += __shfl_xor_sync(0xffffffffu, ds0, 1);
    ds0 += __shfl_xor_sync(0xffffffffu, ds0, 2);
    ds1 += __shfl_xor_sync(0xffffffffu, ds1, 1);
    ds1 += __shfl_xor_sync(0xffffffffu, ds1, 2);
    const float inv0 = 1.f / (ds0 + 1e-6f);
    const float inv1 = 1.f / (ds1 + 1e-6f);

    const int g = l >> 2, tg = l & 3;
    const int mtok = (tbh >> 3) * Nv + qn0 + wrow + g;
    const int hd0 = (tbh & 7) * HDv;
    __nv_bfloat16* dh0 = gc_hi + (size_t)mtok * Dv + hd0;
    __nv_bfloat16* dl0 = gc_lo + (size_t)mtok * Dv + hd0;
    __nv_bfloat16* dh1 = dh0 + 8 * Dv;
    __nv_bfloat16* dl1 = dl0 + 8 * Dv;
#pragma unroll
    for (int i = 0; i < 8; ++i) {
        const int d = (i >> 1) * 16 + (i & 1) * 8 + tg * 2;
        float v0 = ctx[i][0] * inv0, v1 = ctx[i][1] * inv0;
        float v2 = ctx[i][2] * inv1, v3 = ctx[i][3] * inv1;
        __nv_bfloat16 h0 = __float2bfloat16_rn(v0);
        __nv_bfloat16 h1 = __float2bfloat16_rn(v1);
        __nv_bfloat16 h2 = __float2bfloat16_rn(v2);
        __nv_bfloat16 h3 = __float2bfloat16_rn(v3);
        *(uint32_t*)(dh0 + d) = pack_bf2(h0, h1);
        *(uint32_t*)(dl0 + d) = pack_bf2(
            __float2bfloat16_rn(v0 - __bfloat162float(h0)),
            __float2bfloat16_rn(v1 - __bfloat162float(h1)));
        *(uint32_t*)(dh1 + d) = pack_bf2(h2, h3);
        *(uint32_t*)(dl1 + d) = pack_bf2(
            __float2bfloat16_rn(v2 - __bfloat162float(h2)),
            __float2bfloat16_rn(v3 - __bfloat162float(h3)));
    }
}

// ---------------------------------------------------------------------------
extern "C" void kernel_launch(void* const* d_in, const int* in_sizes, int n_in,
                              void* d_out, int out_size)
{
    const float* x  = (const float*)d_in[0];
    const float* wq = (const float*)d_in[1];
    const float* bq = (const float*)d_in[2];
    const float* wk = (const float*)d_in[3];
    const float* bk = (const float*)d_in[4];
    const float* wv = (const float*)d_in[5];
    const float* bv = (const float*)d_in[6];
    const float* wo = (const float*)d_in[7];
    const float* bo = (const float*)d_in[8];
    float* out = (float*)d_out;

    cudaFuncSetAttribute(qkv_gemm_p, cudaFuncAttributeMaxDynamicSharedMemorySize, GEMM_SMEM);
    cudaFuncSetAttribute(out_gemm_p, cudaFuncAttributeMaxDynamicSharedMemorySize, GEMM2_SMEM);
    cudaFuncSetAttribute(attn_m, cudaFuncAttributeMaxDynamicSharedMemorySize, ATTN_SMEM);

    const int splitBlocks = (NXf4 + 4 * NWf4 + 255) / 256;
    split_kernel<<<splitBlocks, 256>>>(x, wq, wk, wv, wo);
    qkv_gemm_p<<<dim3(Mv / 128, 12), 256, GEMM_SMEM>>>(bq, bk, bv);
    attn_m<<<dim3(Nv / 128, TBv * Hv), 256, ATTN_SMEM>>>();
    out_gemm_p<<<dim3(Mv / 128, Dv / 128), 256, GEMM2_SMEM>>>(bo, out);
}

// round 13
// speedup vs baseline: 1.3077x; 1.0126x over previous
#include <cuda_runtime.h>
#include <cuda_bf16.h>
#include <mma.h>
#include <cstdint>

using namespace nvcuda;

#define TBv 16
#define Nv  1024
#define Dv  512
#define Hv  8
#define HDv 64
#define Mv  (TBv * Nv)

__device__ __nv_bfloat16 gx_hi[(size_t)Mv * Dv], gx_lo[(size_t)Mv * Dv];
__device__ __nv_bfloat16 gw_hi[4 * Dv * Dv],     gw_lo[4 * Dv * Dv];
__device__ __nv_bfloat16 gq_hi[(size_t)Mv * Dv], gq_lo[(size_t)Mv * Dv];
__device__ __nv_bfloat16 gk_hi[(size_t)Mv * Dv], gk_lo[(size_t)Mv * Dv];
__device__ __nv_bfloat16 gv_hi[(size_t)Mv * Dv], gv_lo[(size_t)Mv * Dv];
__device__ __nv_bfloat16 gc_hi[(size_t)Mv * Dv], gc_lo[(size_t)Mv * Dv];

__device__ __forceinline__ uint32_t pack_bf2(__nv_bfloat16 a, __nv_bfloat16 b) {
    __nv_bfloat162 p = __halves2bfloat162(a, b);
    return *(uint32_t*)&p;
}
__device__ __forceinline__ void split_store4(float4 v,
                                             __nv_bfloat16* __restrict__ hp,
                                             __nv_bfloat16* __restrict__ lp)
{
    __nv_bfloat16 hx = __float2bfloat16_rn(v.x), hy = __float2bfloat16_rn(v.y);
    __nv_bfloat16 hz = __float2bfloat16_rn(v.z), hw = __float2bfloat16_rn(v.w);
    ((uint32_t*)hp)[0] = pack_bf2(hx, hy);
    ((uint32_t*)hp)[1] = pack_bf2(hz, hw);
    ((uint32_t*)lp)[0] = pack_bf2(__float2bfloat16_rn(v.x - __bfloat162float(hx)),
                                  __float2bfloat16_rn(v.y - __bfloat162float(hy)));
    ((uint32_t*)lp)[1] = pack_bf2(__float2bfloat16_rn(v.z - __bfloat162float(hz)),
                                  __float2bfloat16_rn(v.w - __bfloat162float(hw)));
}
__device__ __forceinline__ void cp16(uint32_t dst, const void* src) {
    asm volatile("cp.async.cg.shared.global [%0], [%1], 16;" :: "r"(dst), "l"(src));
}
__device__ __forceinline__ void cp_commit() {
    asm volatile("cp.async.commit_group;" ::: "memory");
}
__device__ __forceinline__ void ldsm4(uint32_t (&r)[4], uint32_t a) {
    asm volatile("ldmatrix.sync.aligned.m8n8.x4.shared.b16 {%0,%1,%2,%3}, [%4];"
                 : "=r"(r[0]), "=r"(r[1]), "=r"(r[2]), "=r"(r[3]) : "r"(a));
}
__device__ __forceinline__ void ldsm4t(uint32_t (&r)[4], uint32_t a) {
    asm volatile("ldmatrix.sync.aligned.m8n8.x4.trans.shared.b16 {%0,%1,%2,%3}, [%4];"
                 : "=r"(r[0]), "=r"(r[1]), "=r"(r[2]), "=r"(r[3]) : "r"(a));
}
__device__ __forceinline__ void mma16816(float (&c)[4], const uint32_t (&a)[4],
                                         uint32_t b0, uint32_t b1) {
    asm volatile(
        "mma.sync.aligned.m16n8k16.row.col.f32.bf16.bf16.f32 "
        "{%0,%1,%2,%3}, {%4,%5,%6,%7}, {%8,%9}, {%0,%1,%2,%3};"
        : "+f"(c[0]), "+f"(c[1]), "+f"(c[2]), "+f"(c[3])
        : "r"(a[0]), "r"(a[1]), "r"(a[2]), "r"(a[3]), "r"(b0), "r"(b1));
}

using BFragA  = wmma::fragment<wmma::matrix_a, 16, 16, 16, __nv_bfloat16, wmma::row_major>;
using BFragBc = wmma::fragment<wmma::matrix_b, 16, 16, 16, __nv_bfloat16, wmma::col_major>;
using FragC   = wmma::fragment<wmma::accumulator, 16, 16, 16, float>;

// ---------------------------------------------------------------------------
#define NXf4 (Mv * Dv / 4)
#define NWf4 (Dv * Dv / 4)

__global__ __launch_bounds__(256) void split_kernel(
    const float* __restrict__ x,
    const float* __restrict__ wq, const float* __restrict__ wk,
    const float* __restrict__ wv, const float* __restrict__ wo)
{
    int i = blockIdx.x * 256 + threadIdx.x;
    const float* src; __nv_bfloat16 *dh, *dl; int j;
    if (i < NXf4) { src = x; j = i; dh = gx_hi; dl = gx_lo; }
    else {
        int r = i - NXf4;
        if (r >= 4 * NWf4) return;
        int sel = r / NWf4; j = r % NWf4;
        src = (sel == 0) ? wq : (sel == 1) ? wk : (sel == 2) ? wv : wo;
        dh = gw_hi + (size_t)sel * Dv * Dv;
        dl = gw_lo + (size_t)sel * Dv * Dv;
    }
    float4 v = ((const float4*)src)[j];
    split_store4(v, dh + 4 * (size_t)j, dl + 4 * (size_t)j);
}

// ===========================================================================
// Shared GEMM kstep (planes at +0/+5120/+10240/+15360 elems, stride 40)
// ===========================================================================
#define G_PLE  5120
#define G_PLB  10240

__device__ __forceinline__ void g_kstep(const char* smc, int ks,
                                        int wm, int wn, FragC (&acc)[4][2])
{
    const __nv_bfloat16* S = (const __nv_bfloat16*)smc;
    BFragA ahi[4], alo[4];
#pragma unroll
    for (int i = 0; i < 4; ++i) {
        wmma::load_matrix_sync(ahi[i], S + (wm + 16 * i) * 40 + ks * 16, 40);
        wmma::load_matrix_sync(alo[i], S + G_PLE + (wm + 16 * i) * 40 + ks * 16, 40);
    }
#pragma unroll
    for (int j = 0; j < 2; ++j) {
        BFragBc bhi, blo;
        wmma::load_matrix_sync(bhi, S + 2 * G_PLE + (wn + 16 * j) * 40 + ks * 16, 40);
        wmma::load_matrix_sync(blo, S + 3 * G_PLE + (wn + 16 * j) * 40 + ks * 16, 40);
#pragma unroll
        for (int i = 0; i < 4; ++i) {
            wmma::mma_sync(acc[i][j], ahi[i], bhi, acc[i][j]);
            wmma::mma_sync(acc[i][j], ahi[i], blo, acc[i][j]);
            wmma::mma_sync(acc[i][j], alo[i], bhi, acc[i][j]);
        }
    }
}

// ---- qkv GEMM: R10 reg-staged single-buffer schedule -----------------------
#define G_BIAS 40960
#define GEMM_SMEM (40960 + 512)

__device__ __forceinline__ void gemm_single(
    const __nv_bfloat16* __restrict__ Ah, const __nv_bfloat16* __restrict__ Al,
    const __nv_bfloat16* __restrict__ Bh, const __nv_bfloat16* __restrict__ Bl,
    char* smc, FragC (&acc)[4][2])
{
    const int t = threadIdx.x;
    const int w = t >> 5;
    const int wm = (w & 1) * 64;
    const int wn = (w >> 1) * 32;
#pragma unroll
    for (int i = 0; i < 4; ++i)
#pragma unroll
        for (int j = 0; j < 2; ++j)
            wmma::fill_fragment(acc[i][j], 0.0f);

    for (int ch = 0; ch < 16; ++ch) {
        uint4 rg[8];
#pragma unroll
        for (int hh = 0; hh < 2; ++hh) {
            const int o = t + 256 * hh;
            const size_t off = (size_t)(o >> 2) * Dv + ch * 32 + (o & 3) * 8;
            rg[4 * hh + 0] = *(const uint4*)(Ah + off);
            rg[4 * hh + 1] = *(const uint4*)(Al + off);
            rg[4 * hh + 2] = *(const uint4*)(Bh + off);
            rg[4 * hh + 3] = *(const uint4*)(Bl + off);
        }
        __syncthreads();
#pragma unroll
        for (int hh = 0; hh < 2; ++hh) {
            const int o = t + 256 * hh;
            const int off = (o >> 2) * 80 + (o & 3) * 16;
            *(uint4*)(smc + off)             = rg[4 * hh + 0];
            *(uint4*)(smc + G_PLB + off)     = rg[4 * hh + 1];
            *(uint4*)(smc + 2 * G_PLB + off) = rg[4 * hh + 2];
            *(uint4*)(smc + 3 * G_PLB + off) = rg[4 * hh + 3];
        }
        __syncthreads();
        g_kstep(smc, 0, wm, wn, acc);
        g_kstep(smc, 1, wm, wn, acc);
    }
}

__global__ __launch_bounds__(256, 2) void qkv_gemm_p(
    const float* __restrict__ bq, const float* __restrict__ bk,
    const float* __restrict__ bv)
{
    extern __shared__ char smc[];
    const int t = threadIdx.x;
    const int m0   = blockIdx.x * 128;
    const int wsel = blockIdx.y >> 2;
    const int n0   = (blockIdx.y & 3) * 128;

    const float* bias = (wsel == 0) ? bq : (wsel == 1) ? bk : bv;
    __nv_bfloat16* oh = (wsel == 0) ? gq_hi : (wsel == 1) ? gk_hi : gv_hi;
    __nv_bfloat16* ol = (wsel == 0) ? gq_lo : (wsel == 1) ? gk_lo : gv_lo;

    float* biasS = (float*)(smc + G_BIAS);
    if (t < 128) biasS[t] = bias[n0 + t];

    FragC acc[4][2];
    gemm_single(gx_hi + (size_t)m0 * Dv, gx_lo + (size_t)m0 * Dv,
                gw_hi + (size_t)wsel * Dv * Dv + (size_t)n0 * Dv,
                gw_lo + (size_t)wsel * Dv * Dv + (size_t)n0 * Dv, smc, acc);

    float* Cs = (float*)smc;
    const int w = t >> 5, wn = (w >> 1) * 32;
    const int erow = t >> 2;
    const int ecol = (t & 3) * 32;
#pragma unroll
    for (int p = 0; p < 2; ++p) {
        __syncthreads();
        if ((w & 1) == p) {
#pragma unroll
            for (int i = 0; i < 4; ++i)
#pragma unroll
                for (int j = 0; j < 2; ++j)
                    wmma::store_matrix_sync(&Cs[(16 * i) * 132 + wn + 16 * j],
                                            acc[i][j], 132, wmma::mem_row_major);
        }
        __syncthreads();
        const int m  = m0 + p * 64 + erow;
        const int tb = m >> 10, n = m & 1023;
        const int h  = (n0 + ecol) >> 6;
        const int hd0 = (n0 + ecol) & 63;
        __nv_bfloat16* dh = oh + ((size_t)(tb * Hv + h) * Nv + n) * HDv + hd0;
        __nv_bfloat16* dl = ol + ((size_t)(tb * Hv + h) * Nv + n) * HDv + hd0;
#pragma unroll
        for (int c = 0; c < 32; c += 4) {
            float4 v = *(float4*)&Cs[erow * 132 + ecol + c];
            v.x += biasS[ecol + c + 0]; v.y += biasS[ecol + c + 1];
            v.z += biasS[ecol + c + 2]; v.w += biasS[ecol + c + 3];
            split_store4(v, dh + c, dl + c);
        }
    }
}

// ---- out GEMM: cp.async 2-stage pipeline (measured best) -------------------
#define G2_STG  40960
#define G2_BIAS 81920
#define GEMM2_SMEM (81920 + 512)

__device__ __forceinline__ void g2_prefetch(
    uint32_t sb, int stage,
    const __nv_bfloat16* __restrict__ Ah, const __nv_bfloat16* __restrict__ Al,
    const __nv_bfloat16* __restrict__ Bh, const __nv_bfloat16* __restrict__ Bl,
    int k0, int t)
{
    const __nv_bfloat16* pl[4] = {Ah, Al, Bh, Bl};
    const uint32_t base = sb + stage * G2_STG;
#pragma unroll
    for (int p = 0; p < 4; ++p) {
#pragma unroll
        for (int hh = 0; hh < 2; ++hh) {
            const int o = t + 256 * hh;
            const int row = o >> 2, seg = o & 3;
            cp16(base + p * G_PLB + row * 80 + seg * 16,
                 pl[p] + (size_t)row * Dv + k0 + seg * 8);
        }
    }
}

__global__ __launch_bounds__(256, 2) void out_gemm_p(
    const float* __restrict__ bo, float* __restrict__ out)
{
    extern __shared__ char smc[];
    const int t = threadIdx.x;
    const int m0 = blockIdx.x * 128;
    const int n0 = blockIdx.y * 128;
    const uint32_t sb = (uint32_t)__cvta_generic_to_shared(smc);

    float* biasS = (float*)(smc + G2_BIAS);
    if (t < 128) biasS[t] = bo[n0 + t];

    const __nv_bfloat16* Ah = gc_hi + (size_t)m0 * Dv;
    const __nv_bfloat16* Al = gc_lo + (size_t)m0 * Dv;
    const __nv_bfloat16* Bh = gw_hi + (size_t)3 * Dv * Dv + (size_t)n0 * Dv;
    const __nv_bfloat16* Bl = gw_lo + (size_t)3 * Dv * Dv + (size_t)n0 * Dv;

    const int w = t >> 5;
    const int wm = (w & 1) * 64;
    const int wn = (w >> 1) * 32;
    FragC acc[4][2];
#pragma unroll
    for (int i = 0; i < 4; ++i)
#pragma unroll
        for (int j = 0; j < 2; ++j)
            wmma::fill_fragment(acc[i][j], 0.0f);

    g2_prefetch(sb, 0, Ah, Al, Bh, Bl, 0, t);
    cp_commit();
    for (int ch = 0; ch < 16; ++ch) {
        if (ch < 15) {
            g2_prefetch(sb, (ch + 1) & 1, Ah, Al, Bh, Bl, (ch + 1) * 32, t);
            cp_commit();
            asm volatile("cp.async.wait_group 1;" ::: "memory");
        } else {
            asm volatile("cp.async.wait_group 0;" ::: "memory");
        }
        __syncthreads();
        g_kstep(smc + (ch & 1) * G2_STG, 0, wm, wn, acc);
        g_kstep(smc + (ch & 1) * G2_STG, 1, wm, wn, acc);
        __syncthreads();
    }

    float* Cs = (float*)smc;
#pragma unroll
    for (int i = 0; i < 4; ++i)
#pragma unroll
        for (int j = 0; j < 2; ++j)
            wmma::store_matrix_sync(&Cs[(wm + 16 * i) * 132 + wn + 16 * j],
                                    acc[i][j], 132, wmma::mem_row_major);
    __syncthreads();

    const int row = t >> 1, c0 = (t & 1) * 64;
    float* dst = out + (size_t)(m0 + row) * Dv + n0 + c0;
#pragma unroll
    for (int c = 0; c < 64; c += 4) {
        float4 v = *(float4*)&Cs[row * 132 + c0 + c];
        v.x += biasS[c0 + c + 0]; v.y += biasS[c0 + c + 1];
        v.z += biasS[c0 + c + 2]; v.w += biasS[c0 + c + 3];
        *(float4*)(dst + c) = v;
    }
}

// ===========================================================================
// Attention: mma.sync m16n8k16, S in registers. 128 thr, 4 warps, each warp
// 32 q-rows (two 16-row groups) -> K/V LDSM amortized 2x; q-tile 128;
// KV 2-stage ring; smem 110592 B -> 2 blocks/SM. Combines R11 amortization
// with R12 occupancy.
// ===========================================================================
#define AT_STG  36864
#define AT_PL   9216
#define AT_Q    73728
#define ATTN_SMEM 110592

__device__ __forceinline__ void kv_prefetch(uint32_t dstbase, size_t hb,
                                            int row0, int t)
{
    const __nv_bfloat16* kvp[4] = {gk_hi + hb, gk_lo + hb, gv_hi + hb, gv_lo + hb};
#pragma unroll
    for (int hh = 0; hh < 16; ++hh) {
        const int o = t + 128 * hh;            // 0..2047
        const int plane = o >> 9;
        const int idx = o & 511;
        cp16(dstbase + plane * AT_PL + (idx >> 3) * 144 + (idx & 7) * 16,
             kvp[plane] + (size_t)(row0 + (idx >> 3)) * HDv + (idx & 7) * 8);
    }
}

__global__ __launch_bounds__(128, 2) void attn_m()
{
    extern __shared__ char smc[];
    const uint32_t sb = (uint32_t)__cvta_generic_to_shared(smc);
    const int t = threadIdx.x;
    const int l = t & 31;
    const int w = t >> 5;                      // 0..3
    const int qn0 = blockIdx.x * 128;
    const int tbh = blockIdx.y;
    const size_t hb = (size_t)tbh * Nv * HDv;

    // group0: Q planes (2 x 128 rows) + KV tile 0; group1: KV tile 1
#pragma unroll
    for (int hh = 0; hh < 16; ++hh) {
        const int o = t + 128 * hh;            // 0..2047
        const int plane = o >> 10;
        const int idx = o & 1023;
        const __nv_bfloat16* src =
            (plane ? gq_lo : gq_hi) + hb + (size_t)(qn0 + (idx >> 3)) * HDv + (idx & 7) * 8;
        cp16(sb + AT_Q + plane * 18432 + (idx >> 3) * 144 + (idx & 7) * 16, src);
    }
    kv_prefetch(sb, hb, 0, t);
    cp_commit();
    kv_prefetch(sb + AT_STG, hb, 64, t);
    cp_commit();

    const int wrow = w * 32;
    uint32_t qaddr[2];
    qaddr[0] = sb + AT_Q + (wrow + (l & 15)) * 144 + (l >> 4) * 16;
    qaddr[1] = qaddr[0] + 16 * 144;
    const int kroff = ((l & 7) + ((l >> 4) & 1) * 8) * 144 + ((l >> 3) & 1) * 16;
    const int vroff = ((l & 7) + ((l >> 3) & 1) * 8) * 144 + ((l >> 4) & 1) * 16;

    float ctx[2][8][4];
#pragma unroll
    for (int g = 0; g < 2; ++g)
#pragma unroll
        for (int i = 0; i < 8; ++i)
#pragma unroll
            for (int j = 0; j < 4; ++j) ctx[g][i][j] = 0.f;
    float ds[2][2] = {{0.f, 0.f}, {0.f, 0.f}};

    for (int kt = 0; kt < 16; ++kt) {
        if (kt < 15) asm volatile("cp.async.wait_group 1;" ::: "memory");
        else         asm volatile("cp.async.wait_group 0;" ::: "memory");
        __syncthreads();
        const uint32_t kst = sb + (kt & 1) * AT_STG;

        float sacc[2][8][4];
#pragma unroll
        for (int g = 0; g < 2; ++g)
#pragma unroll
            for (int i = 0; i < 8; ++i)
#pragma unroll
                for (int j = 0; j < 4; ++j) sacc[g][i][j] = 0.f;
#pragma unroll
        for (int ks = 0; ks < 4; ++ks) {
            uint32_t aqh[2][4], aql[2][4];
            ldsm4(aqh[0], qaddr[0] + ks * 32);
            ldsm4(aql[0], qaddr[0] + 18432 + ks * 32);
            ldsm4(aqh[1], qaddr[1] + ks * 32);
            ldsm4(aql[1], qaddr[1] + 18432 + ks * 32);
#pragma unroll
            for (int np = 0; np < 4; ++np) {
                uint32_t bh[4], bl[4];
                ldsm4(bh, kst + np * 16 * 144 + kroff + ks * 32);
                ldsm4(bl, kst + AT_PL + np * 16 * 144 + kroff + ks * 32);
#pragma unroll
                for (int g = 0; g < 2; ++g) {
                    mma16816(sacc[g][2 * np],     aqh[g], bh[0], bh[1]);
                    mma16816(sacc[g][2 * np],     aqh[g], bl[0], bl[1]);
                    mma16816(sacc[g][2 * np],     aql[g], bh[0], bh[1]);
                    mma16816(sacc[g][2 * np + 1], aqh[g], bh[2], bh[3]);
                    mma16816(sacc[g][2 * np + 1], aqh[g], bl[2], bl[3]);
                    mma16816(sacc[g][2 * np + 1], aql[g], bh[2], bh[3]);
                }
            }
        }
#pragma unroll
        for (int kf = 0; kf < 4; ++kf) {
            uint32_t sah[2][4], sal[2][4];
#pragma unroll
            for (int g = 0; g < 2; ++g) {
#pragma unroll
                for (int hh = 0; hh < 2; ++hh) {
                    float* c = sacc[g][2 * kf + hh];
                    float c0 = fmaxf(c[0] * 0.125f, 0.f);
                    float c1 = fmaxf(c[1] * 0.125f, 0.f);
                    float c2 = fmaxf(c[2] * 0.125f, 0.f);
                    float c3 = fmaxf(c[3] * 0.125f, 0.f);
                    ds[g][0] += c0 + c1;
                    ds[g][1] += c2 + c3;
                    __nv_bfloat16 h0 = __float2bfloat16_rn(c0);
                    __nv_bfloat16 h1 = __float2bfloat16_rn(c1);
                    __nv_bfloat16 h2 = __float2bfloat16_rn(c2);
                    __nv_bfloat16 h3 = __float2bfloat16_rn(c3);
                    sah[g][2 * hh + 0] = pack_bf2(h0, h1);
                    sah[g][2 * hh + 1] = pack_bf2(h2, h3);
                    sal[g][2 * hh + 0] = pack_bf2(
                        __float2bfloat16_rn(c0 - __bfloat162float(h0)),
                        __float2bfloat16_rn(c1 - __bfloat162float(h1)));
                    sal[g][2 * hh + 1] = pack_bf2(
                        __float2bfloat16_rn(c2 - __bfloat162float(h2)),
                        __float2bfloat16_rn(c3 - __bfloat162float(h3)));
                }
            }
#pragma unroll
            for (int np = 0; np < 4; ++np) {
                uint32_t bvh[4], bvl[4];
                ldsm4t(bvh, kst + 2 * AT_PL + kf * 16 * 144 + vroff + np * 32);
                ldsm4t(bvl, kst + 3 * AT_PL + kf * 16 * 144 + vroff + np * 32);
#pragma unroll
                for (int g = 0; g < 2; ++g) {
                    mma16816(ctx[g][2 * np],     sah[g], bvh[0], bvh[1]);
                    mma16816(ctx[g][2 * np],     sah[g], bvl[0], bvl[1]);
                    mma16816(ctx[g][2 * np],     sal[g], bvh[0], bvh[1]);
                    mma16816(ctx[g][2 * np + 1], sah[g], bvh[2], bvh[3]);
                    mma16816(ctx[g][2 * np + 1], sah[g], bvl[2], bvl[3]);
                    mma16816(ctx[g][2 * np + 1], sal[g], bvh[2], bvh[3]);
                }
            }
        }
        __syncthreads();                      // stage consumed
        if (kt < 14) {
            kv_prefetch(sb + (kt & 1) * AT_STG, hb, (kt + 2) * 64, t);
            cp_commit();
        }
    }

    // epilogue: quad-reduce rowsums per group, normalize, write ctx planes
    const int gl = l >> 2, tg = l & 3;
    const int hd0 = (tbh & 7) * HDv;
#pragma unroll
    for (int g = 0; g < 2; ++g) {
        float d0 = ds[g][0], d1 = ds[g][1];
        d0 += __shfl_xor_sync(0xffffffffu, d0, 1);
        d0 += __shfl_xor_sync(0xffffffffu, d0, 2);
        d1 += __shfl_xor_sync(0xffffffffu, d1, 1);
        d1 += __shfl_xor_sync(0xffffffffu, d1, 2);
        const float inv0 = 1.f / (d0 + 1e-6f);
        const float inv1 = 1.f / (d1 + 1e-6f);

        const int mtok = (tbh >> 3) * Nv + qn0 + wrow + g * 16 + gl;
        __nv_bfloat16* dh0 = gc_hi + (size_t)mtok * Dv + hd0;
        __nv_bfloat16* dl0 = gc_lo + (size_t)mtok * Dv + hd0;
        __nv_bfloat16* dh1 = dh0 + 8 * Dv;
        __nv_bfloat16* dl1 = dl0 + 8 * Dv;
#pragma unroll
        for (int i = 0; i < 8; ++i) {
            const int d = (i >> 1) * 16 + (i & 1) * 8 + tg * 2;
            float v0 = ctx[g][i][0] * inv0, v1 = ctx[g][i][1] * inv0;
            float v2 = ctx[g][i][2] * inv1, v3 = ctx[g][i][3] * inv1;
            __nv_bfloat16 h0 = __float2bfloat16_rn(v0);
            __nv_bfloat16 h1 = __float2bfloat16_rn(v1);
            __nv_bfloat16 h2 = __float2bfloat16_rn(v2);
            __nv_bfloat16 h3 = __float2bfloat16_rn(v3);
            *(uint32_t*)(dh0 + d) = pack_bf2(h0, h1);
            *(uint32_t*)(dl0 + d) = pack_bf2(
                __float2bfloat16_rn(v0 - __bfloat162float(h0)),
                __float2bfloat16_rn(v1 - __bfloat162float(h1)));
            *(uint32_t*)(dh1 + d) = pack_bf2(h2, h3);
            *(uint32_t*)(dl1 + d) = pack_bf2(
                __float2bfloat16_rn(v2 - __bfloat162float(h2)),
                __float2bfloat16_rn(v3 - __bfloat162float(h3)));
        }
    }
}

// ---------------------------------------------------------------------------
extern "C" void kernel_launch(void* const* d_in, const int* in_sizes, int n_in,
                              void* d_out, int out_size)
{
    const float* x  = (const float*)d_in[0];
    const float* wq = (const float*)d_in[1];
    const float* bq = (const float*)d_in[2];
    const float* wk = (const float*)d_in[3];
    const float* bk = (const float*)d_in[4];
    const float* wv = (const float*)d_in[5];
    const float* bv = (const float*)d_in[6];
    const float* wo = (const float*)d_in[7];
    const float* bo = (const float*)d_in[8];
    float* out = (float*)d_out;

    cudaFuncSetAttribute(qkv_gemm_p, cudaFuncAttributeMaxDynamicSharedMemorySize, GEMM_SMEM);
    cudaFuncSetAttribute(out_gemm_p, cudaFuncAttributeMaxDynamicSharedMemorySize, GEMM2_SMEM);
    cudaFuncSetAttribute(attn_m, cudaFuncAttributeMaxDynamicSharedMemorySize, ATTN_SMEM);

    const int splitBlocks = (NXf4 + 4 * NWf4 + 255) / 256;
    split_kernel<<<splitBlocks, 256>>>(x, wq, wk, wv, wo);
    qkv_gemm_p<<<dim3(Mv / 128, 12), 256, GEMM_SMEM>>>(bq, bk, bv);
    attn_m<<<dim3(Nv / 128, TBv * Hv), 128, ATTN_SMEM>>>();
    out_gemm_p<<<dim3(Mv / 128, Dv / 128), 256, GEMM2_SMEM>>>(bo, out);
}

// round 14
// speedup vs baseline: 1.3170x; 1.0071x over previous
#include <cuda_runtime.h>
#include <cuda_bf16.h>
#include <mma.h>
#include <cstdint>

using namespace nvcuda;

#define TBv 16
#define Nv  1024
#define Dv  512
#define Hv  8
#define HDv 64
#define Mv  (TBv * Nv)

__device__ __nv_bfloat16 gx_hi[(size_t)Mv * Dv], gx_lo[(size_t)Mv * Dv];
__device__ __nv_bfloat16 gw_hi[4 * Dv * Dv],     gw_lo[4 * Dv * Dv];
__device__ __nv_bfloat16 gq_hi[(size_t)Mv * Dv], gq_lo[(size_t)Mv * Dv];
__device__ __nv_bfloat16 gk_hi[(size_t)Mv * Dv], gk_lo[(size_t)Mv * Dv];
__device__ __nv_bfloat16 gv_hi[(size_t)Mv * Dv], gv_lo[(size_t)Mv * Dv];
__device__ __nv_bfloat16 gc_hi[(size_t)Mv * Dv], gc_lo[(size_t)Mv * Dv];

// ---- packed bf16x2 conversion helpers (1 cvt for 2 values) ----------------
__device__ __forceinline__ uint32_t cvt_bf2(float x, float y) { // {lo=x, hi=y}
    uint32_t r;
    asm("cvt.rn.bf16x2.f32 %0, %1, %2;" : "=r"(r) : "f"(y), "f"(x));
    return r;
}
__device__ __forceinline__ float bflo_f(uint32_t p) { return __uint_as_float(p << 16); }
__device__ __forceinline__ float bfhi_f(uint32_t p) { return __uint_as_float(p & 0xffff0000u); }

__device__ __forceinline__ void split_store4(float4 v,
                                             __nv_bfloat16* __restrict__ hp,
                                             __nv_bfloat16* __restrict__ lp)
{
    uint32_t h01 = cvt_bf2(v.x, v.y);
    uint32_t h23 = cvt_bf2(v.z, v.w);
    ((uint32_t*)hp)[0] = h01;
    ((uint32_t*)hp)[1] = h23;
    ((uint32_t*)lp)[0] = cvt_bf2(v.x - bflo_f(h01), v.y - bfhi_f(h01));
    ((uint32_t*)lp)[1] = cvt_bf2(v.z - bflo_f(h23), v.w - bfhi_f(h23));
}
__device__ __forceinline__ void cp16(uint32_t dst, const void* src) {
    asm volatile("cp.async.cg.shared.global [%0], [%1], 16;" :: "r"(dst), "l"(src));
}
__device__ __forceinline__ void cp_commit() {
    asm volatile("cp.async.commit_group;" ::: "memory");
}
__device__ __forceinline__ void ldsm4(uint32_t (&r)[4], uint32_t a) {
    asm volatile("ldmatrix.sync.aligned.m8n8.x4.shared.b16 {%0,%1,%2,%3}, [%4];"
                 : "=r"(r[0]), "=r"(r[1]), "=r"(r[2]), "=r"(r[3]) : "r"(a));
}
__device__ __forceinline__ void ldsm4t(uint32_t (&r)[4], uint32_t a) {
    asm volatile("ldmatrix.sync.aligned.m8n8.x4.trans.shared.b16 {%0,%1,%2,%3}, [%4];"
                 : "=r"(r[0]), "=r"(r[1]), "=r"(r[2]), "=r"(r[3]) : "r"(a));
}
__device__ __forceinline__ void mma16816(float (&c)[4], const uint32_t (&a)[4],
                                         uint32_t b0, uint32_t b1) {
    asm volatile(
        "mma.sync.aligned.m16n8k16.row.col.f32.bf16.bf16.f32 "
        "{%0,%1,%2,%3}, {%4,%5,%6,%7}, {%8,%9}, {%0,%1,%2,%3};"
        : "+f"(c[0]), "+f"(c[1]), "+f"(c[2]), "+f"(c[3])
        : "r"(a[0]), "r"(a[1]), "r"(a[2]), "r"(a[3]), "r"(b0), "r"(b1));
}

using BFragA  = wmma::fragment<wmma::matrix_a, 16, 16, 16, __nv_bfloat16, wmma::row_major>;
using BFragBc = wmma::fragment<wmma::matrix_b, 16, 16, 16, __nv_bfloat16, wmma::col_major>;
using FragC   = wmma::fragment<wmma::accumulator, 16, 16, 16, float>;

// ---------------------------------------------------------------------------
#define NXf4 (Mv * Dv / 4)
#define NWf4 (Dv * Dv / 4)

__global__ __launch_bounds__(256) void split_kernel(
    const float* __restrict__ x,
    const float* __restrict__ wq, const float* __restrict__ wk,
    const float* __restrict__ wv, const float* __restrict__ wo)
{
    int i = blockIdx.x * 256 + threadIdx.x;
    const float* src; __nv_bfloat16 *dh, *dl; int j;
    if (i < NXf4) { src = x; j = i; dh = gx_hi; dl = gx_lo; }
    else {
        int r = i - NXf4;
        if (r >= 4 * NWf4) return;
        int sel = r / NWf4; j = r % NWf4;
        src = (sel == 0) ? wq : (sel == 1) ? wk : (sel == 2) ? wv : wo;
        dh = gw_hi + (size_t)sel * Dv * Dv;
        dl = gw_lo + (size_t)sel * Dv * Dv;
    }
    float4 v = ((const float4*)src)[j];
    split_store4(v, dh + 4 * (size_t)j, dl + 4 * (size_t)j);
}

// ===========================================================================
// Shared GEMM kstep (planes at +0/+5120/+10240/+15360 elems, stride 40)
// ===========================================================================
#define G_PLE  5120
#define G_PLB  10240

__device__ __forceinline__ void g_kstep(const char* smc, int ks,
                                        int wm, int wn, FragC (&acc)[4][2])
{
    const __nv_bfloat16* S = (const __nv_bfloat16*)smc;
    BFragA ahi[4], alo[4];
#pragma unroll
    for (int i = 0; i < 4; ++i) {
        wmma::load_matrix_sync(ahi[i], S + (wm + 16 * i) * 40 + ks * 16, 40);
        wmma::load_matrix_sync(alo[i], S + G_PLE + (wm + 16 * i) * 40 + ks * 16, 40);
    }
#pragma unroll
    for (int j = 0; j < 2; ++j) {
        BFragBc bhi, blo;
        wmma::load_matrix_sync(bhi, S + 2 * G_PLE + (wn + 16 * j) * 40 + ks * 16, 40);
        wmma::load_matrix_sync(blo, S + 3 * G_PLE + (wn + 16 * j) * 40 + ks * 16, 40);
#pragma unroll
        for (int i = 0; i < 4; ++i) {
            wmma::mma_sync(acc[i][j], ahi[i], bhi, acc[i][j]);
            wmma::mma_sync(acc[i][j], ahi[i], blo, acc[i][j]);
            wmma::mma_sync(acc[i][j], alo[i], bhi, acc[i][j]);
        }
    }
}

// ---- qkv GEMM: reg-staged single-buffer schedule ---------------------------
#define G_BIAS 40960
#define GEMM_SMEM (40960 + 512)

__device__ __forceinline__ void gemm_single(
    const __nv_bfloat16* __restrict__ Ah, const __nv_bfloat16* __restrict__ Al,
    const __nv_bfloat16* __restrict__ Bh, const __nv_bfloat16* __restrict__ Bl,
    char* smc, FragC (&acc)[4][2])
{
    const int t = threadIdx.x;
    const int w = t >> 5;
    const int wm = (w & 1) * 64;
    const int wn = (w >> 1) * 32;
#pragma unroll
    for (int i = 0; i < 4; ++i)
#pragma unroll
        for (int j = 0; j < 2; ++j)
            wmma::fill_fragment(acc[i][j], 0.0f);

    for (int ch = 0; ch < 16; ++ch) {
        uint4 rg[8];
#pragma unroll
        for (int hh = 0; hh < 2; ++hh) {
            const int o = t + 256 * hh;
            const size_t off = (size_t)(o >> 2) * Dv + ch * 32 + (o & 3) * 8;
            rg[4 * hh + 0] = *(const uint4*)(Ah + off);
            rg[4 * hh + 1] = *(const uint4*)(Al + off);
            rg[4 * hh + 2] = *(const uint4*)(Bh + off);
            rg[4 * hh + 3] = *(const uint4*)(Bl + off);
        }
        __syncthreads();
#pragma unroll
        for (int hh = 0; hh < 2; ++hh) {
            const int o = t + 256 * hh;
            const int off = (o >> 2) * 80 + (o & 3) * 16;
            *(uint4*)(smc + off)             = rg[4 * hh + 0];
            *(uint4*)(smc + G_PLB + off)     = rg[4 * hh + 1];
            *(uint4*)(smc + 2 * G_PLB + off) = rg[4 * hh + 2];
            *(uint4*)(smc + 3 * G_PLB + off) = rg[4 * hh + 3];
        }
        __syncthreads();
        g_kstep(smc, 0, wm, wn, acc);
        g_kstep(smc, 1, wm, wn, acc);
    }
}

__global__ __launch_bounds__(256, 2) void qkv_gemm_p(
    const float* __restrict__ bq, const float* __restrict__ bk,
    const float* __restrict__ bv)
{
    extern __shared__ char smc[];
    const int t = threadIdx.x;
    const int m0   = blockIdx.x * 128;
    const int wsel = blockIdx.y >> 2;
    const int n0   = (blockIdx.y & 3) * 128;

    const float* bias = (wsel == 0) ? bq : (wsel == 1) ? bk : bv;
    __nv_bfloat16* oh = (wsel == 0) ? gq_hi : (wsel == 1) ? gk_hi : gv_hi;
    __nv_bfloat16* ol = (wsel == 0) ? gq_lo : (wsel == 1) ? gk_lo : gv_lo;

    float* biasS = (float*)(smc + G_BIAS);
    if (t < 128) biasS[t] = bias[n0 + t];

    FragC acc[4][2];
    gemm_single(gx_hi + (size_t)m0 * Dv, gx_lo + (size_t)m0 * Dv,
                gw_hi + (size_t)wsel * Dv * Dv + (size_t)n0 * Dv,
                gw_lo + (size_t)wsel * Dv * Dv + (size_t)n0 * Dv, smc, acc);

    float* Cs = (float*)smc;
    const int w = t >> 5, wn = (w >> 1) * 32;
    const int erow = t >> 2;
    const int ecol = (t & 3) * 32;
#pragma unroll
    for (int p = 0; p < 2; ++p) {
        __syncthreads();
        if ((w & 1) == p) {
#pragma unroll
            for (int i = 0; i < 4; ++i)
#pragma unroll
                for (int j = 0; j < 2; ++j)
                    wmma::store_matrix_sync(&Cs[(16 * i) * 132 + wn + 16 * j],
                                            acc[i][j], 132, wmma::mem_row_major);
        }
        __syncthreads();
        const int m  = m0 + p * 64 + erow;
        const int tb = m >> 10, n = m & 1023;
        const int h  = (n0 + ecol) >> 6;
        const int hd0 = (n0 + ecol) & 63;
        __nv_bfloat16* dh = oh + ((size_t)(tb * Hv + h) * Nv + n) * HDv + hd0;
        __nv_bfloat16* dl = ol + ((size_t)(tb * Hv + h) * Nv + n) * HDv + hd0;
#pragma unroll
        for (int c = 0; c < 32; c += 4) {
            float4 v = *(float4*)&Cs[erow * 132 + ecol + c];
            v.x += biasS[ecol + c + 0]; v.y += biasS[ecol + c + 1];
            v.z += biasS[ecol + c + 2]; v.w += biasS[ecol + c + 3];
            split_store4(v, dh + c, dl + c);
        }
    }
}

// ---- out GEMM: cp.async 2-stage pipeline (measured best) -------------------
#define G2_STG  40960
#define G2_BIAS 81920
#define GEMM2_SMEM (81920 + 512)

__device__ __forceinline__ void g2_prefetch(
    uint32_t sb, int stage,
    const __nv_bfloat16* __restrict__ Ah, const __nv_bfloat16* __restrict__ Al,
    const __nv_bfloat16* __restrict__ Bh, const __nv_bfloat16* __restrict__ Bl,
    int k0, int t)
{
    const __nv_bfloat16* pl[4] = {Ah, Al, Bh, Bl};
    const uint32_t base = sb + stage * G2_STG;
#pragma unroll
    for (int p = 0; p < 4; ++p) {
#pragma unroll
        for (int hh = 0; hh < 2; ++hh) {
            const int o = t + 256 * hh;
            const int row = o >> 2, seg = o & 3;
            cp16(base + p * G_PLB + row * 80 + seg * 16,
                 pl[p] + (size_t)row * Dv + k0 + seg * 8);
        }
    }
}

__global__ __launch_bounds__(256, 2) void out_gemm_p(
    const float* __restrict__ bo, float* __restrict__ out)
{
    extern __shared__ char smc[];
    const int t = threadIdx.x;
    const int m0 = blockIdx.x * 128;
    const int n0 = blockIdx.y * 128;
    const uint32_t sb = (uint32_t)__cvta_generic_to_shared(smc);

    float* biasS = (float*)(smc + G2_BIAS);
    if (t < 128) biasS[t] = bo[n0 + t];

    const __nv_bfloat16* Ah = gc_hi + (size_t)m0 * Dv;
    const __nv_bfloat16* Al = gc_lo + (size_t)m0 * Dv;
    const __nv_bfloat16* Bh = gw_hi + (size_t)3 * Dv * Dv + (size_t)n0 * Dv;
    const __nv_bfloat16* Bl = gw_lo + (size_t)3 * Dv * Dv + (size_t)n0 * Dv;

    const int w = t >> 5;
    const int wm = (w & 1) * 64;
    const int wn = (w >> 1) * 32;
    FragC acc[4][2];
#pragma unroll
    for (int i = 0; i < 4; ++i)
#pragma unroll
        for (int j = 0; j < 2; ++j)
            wmma::fill_fragment(acc[i][j], 0.0f);

    g2_prefetch(sb, 0, Ah, Al, Bh, Bl, 0, t);
    cp_commit();
    for (int ch = 0; ch < 16; ++ch) {
        if (ch < 15) {
            g2_prefetch(sb, (ch + 1) & 1, Ah, Al, Bh, Bl, (ch + 1) * 32, t);
            cp_commit();
            asm volatile("cp.async.wait_group 1;" ::: "memory");
        } else {
            asm volatile("cp.async.wait_group 0;" ::: "memory");
        }
        __syncthreads();
        g_kstep(smc + (ch & 1) * G2_STG, 0, wm, wn, acc);
        g_kstep(smc + (ch & 1) * G2_STG, 1, wm, wn, acc);
        __syncthreads();
    }

    float* Cs = (float*)smc;
#pragma unroll
    for (int i = 0; i < 4; ++i)
#pragma unroll
        for (int j = 0; j < 2; ++j)
            wmma::store_matrix_sync(&Cs[(wm + 16 * i) * 132 + wn + 16 * j],
                                    acc[i][j], 132, wmma::mem_row_major);
    __syncthreads();

    const int row = t >> 1, c0 = (t & 1) * 64;
    float* dst = out + (size_t)(m0 + row) * Dv + n0 + c0;
#pragma unroll
    for (int c = 0; c < 64; c += 4) {
        float4 v = *(float4*)&Cs[row * 132 + c0 + c];
        v.x += biasS[c0 + c + 0]; v.y += biasS[c0 + c + 1];
        v.z += biasS[c0 + c + 2]; v.w += biasS[c0 + c + 3];
        *(float4*)(dst + c) = v;
    }
}

// ===========================================================================
// Attention: mma.sync m16n8k16, S in registers. 128 thr, 4 warps, each warp
// 32 q-rows (two 16-row groups); q-tile 128; KV 2-stage ring; 2 blocks/SM.
// Split phase uses packed cvt.rn.bf16x2.f32 (half the CVT instructions).
// ===========================================================================
#define AT_STG  36864
#define AT_PL   9216
#define AT_Q    73728
#define ATTN_SMEM 110592

__device__ __forceinline__ void kv_prefetch(uint32_t dstbase, size_t hb,
                                            int row0, int t)
{
    const __nv_bfloat16* kvp[4] = {gk_hi + hb, gk_lo + hb, gv_hi + hb, gv_lo + hb};
#pragma unroll
    for (int hh = 0; hh < 16; ++hh) {
        const int o = t + 128 * hh;            // 0..2047
        const int plane = o >> 9;
        const int idx = o & 511;
        cp16(dstbase + plane * AT_PL + (idx >> 3) * 144 + (idx & 7) * 16,
             kvp[plane] + (size_t)(row0 + (idx >> 3)) * HDv + (idx & 7) * 8);
    }
}

__global__ __launch_bounds__(128, 2) void attn_m()
{
    extern __shared__ char smc[];
    const uint32_t sb = (uint32_t)__cvta_generic_to_shared(smc);
    const int t = threadIdx.x;
    const int l = t & 31;
    const int w = t >> 5;                      // 0..3
    const int qn0 = blockIdx.x * 128;
    const int tbh = blockIdx.y;
    const size_t hb = (size_t)tbh * Nv * HDv;

#pragma unroll
    for (int hh = 0; hh < 16; ++hh) {
        const int o = t + 128 * hh;            // 0..2047
        const int plane = o >> 10;
        const int idx = o & 1023;
        const __nv_bfloat16* src =
            (plane ? gq_lo : gq_hi) + hb + (size_t)(qn0 + (idx >> 3)) * HDv + (idx & 7) * 8;
        cp16(sb + AT_Q + plane * 18432 + (idx >> 3) * 144 + (idx & 7) * 16, src);
    }
    kv_prefetch(sb, hb, 0, t);
    cp_commit();
    kv_prefetch(sb + AT_STG, hb, 64, t);
    cp_commit();

    const int wrow = w * 32;
    uint32_t qaddr[2];
    qaddr[0] = sb + AT_Q + (wrow + (l & 15)) * 144 + (l >> 4) * 16;
    qaddr[1] = qaddr[0] + 16 * 144;
    const int kroff = ((l & 7) + ((l >> 4) & 1) * 8) * 144 + ((l >> 3) & 1) * 16;
    const int vroff = ((l & 7) + ((l >> 3) & 1) * 8) * 144 + ((l >> 4) & 1) * 16;

    float ctx[2][8][4];
#pragma unroll
    for (int g = 0; g < 2; ++g)
#pragma unroll
        for (int i = 0; i < 8; ++i)
#pragma unroll
            for (int j = 0; j < 4; ++j) ctx[g][i][j] = 0.f;
    float ds[2][2] = {{0.f, 0.f}, {0.f, 0.f}};

    for (int kt = 0; kt < 16; ++kt) {
        if (kt < 15) asm volatile("cp.async.wait_group 1;" ::: "memory");
        else         asm volatile("cp.async.wait_group 0;" ::: "memory");
        __syncthreads();
        const uint32_t kst = sb + (kt & 1) * AT_STG;

        float sacc[2][8][4];
#pragma unroll
        for (int g = 0; g < 2; ++g)
#pragma unroll
            for (int i = 0; i < 8; ++i)
#pragma unroll
                for (int j = 0; j < 4; ++j) sacc[g][i][j] = 0.f;
#pragma unroll
        for (int ks = 0; ks < 4; ++ks) {
            uint32_t aqh[2][4], aql[2][4];
            ldsm4(aqh[0], qaddr[0] + ks * 32);
            ldsm4(aql[0], qaddr[0] + 18432 + ks * 32);
            ldsm4(aqh[1], qaddr[1] + ks * 32);
            ldsm4(aql[1], qaddr[1] + 18432 + ks * 32);
#pragma unroll
            for (int np = 0; np < 4; ++np) {
                uint32_t bh[4], bl[4];
                ldsm4(bh, kst + np * 16 * 144 + kroff + ks * 32);
                ldsm4(bl, kst + AT_PL + np * 16 * 144 + kroff + ks * 32);
#pragma unroll
                for (int g = 0; g < 2; ++g) {
                    mma16816(sacc[g][2 * np],     aqh[g], bh[0], bh[1]);
                    mma16816(sacc[g][2 * np],     aqh[g], bl[0], bl[1]);
                    mma16816(sacc[g][2 * np],     aql[g], bh[0], bh[1]);
                    mma16816(sacc[g][2 * np + 1], aqh[g], bh[2], bh[3]);
                    mma16816(sacc[g][2 * np + 1], aqh[g], bl[2], bl[3]);
                    mma16816(sacc[g][2 * np + 1], aql[g], bh[2], bh[3]);
                }
            }
        }
#pragma unroll
        for (int kf = 0; kf < 4; ++kf) {
            uint32_t sah[2][4], sal[2][4];
#pragma unroll
            for (int g = 0; g < 2; ++g) {
#pragma unroll
                for (int hh = 0; hh < 2; ++hh) {
                    float* c = sacc[g][2 * kf + hh];
                    float c0 = fmaxf(c[0] * 0.125f, 0.f);
                    float c1 = fmaxf(c[1] * 0.125f, 0.f);
                    float c2 = fmaxf(c[2] * 0.125f, 0.f);
                    float c3 = fmaxf(c[3] * 0.125f, 0.f);
                    ds[g][0] += c0 + c1;
                    ds[g][1] += c2 + c3;
                    uint32_t h01 = cvt_bf2(c0, c1);
                    uint32_t h23 = cvt_bf2(c2, c3);
                    sah[g][2 * hh + 0] = h01;
                    sah[g][2 * hh + 1] = h23;
                    sal[g][2 * hh + 0] = cvt_bf2(c0 - bflo_f(h01), c1 - bfhi_f(h01));
                    sal[g][2 * hh + 1] = cvt_bf2(c2 - bflo_f(h23), c3 - bfhi_f(h23));
                }
            }
#pragma unroll
            for (int np = 0; np < 4; ++np) {
                uint32_t bvh[4], bvl[4];
                ldsm4t(bvh, kst + 2 * AT_PL + kf * 16 * 144 + vroff + np * 32);
                ldsm4t(bvl, kst + 3 * AT_PL + kf * 16 * 144 + vroff + np * 32);
#pragma unroll
                for (int g = 0; g < 2; ++g) {
                    mma16816(ctx[g][2 * np],     sah[g], bvh[0], bvh[1]);
                    mma16816(ctx[g][2 * np],     sah[g], bvl[0], bvl[1]);
                    mma16816(ctx[g][2 * np],     sal[g], bvh[0], bvh[1]);
                    mma16816(ctx[g][2 * np + 1], sah[g], bvh[2], bvh[3]);
                    mma16816(ctx[g][2 * np + 1], sah[g], bvl[2], bvl[3]);
                    mma16816(ctx[g][2 * np + 1], sal[g], bvh[2], bvh[3]);
                }
            }
        }
        __syncthreads();                      // stage consumed
        if (kt < 14) {
            kv_prefetch(sb + (kt & 1) * AT_STG, hb, (kt + 2) * 64, t);
            cp_commit();
        }
    }

    // epilogue: quad-reduce rowsums per group, normalize, write ctx planes
    const int gl = l >> 2, tg = l & 3;
    const int hd0 = (tbh & 7) * HDv;
#pragma unroll
    for (int g = 0; g < 2; ++g) {
        float d0 = ds[g][0], d1 = ds[g][1];
        d0 += __shfl_xor_sync(0xffffffffu, d0, 1);
        d0 += __shfl_xor_sync(0xffffffffu, d0, 2);
        d1 += __shfl_xor_sync(0xffffffffu, d1, 1);
        d1 += __shfl_xor_sync(0xffffffffu, d1, 2);
        const float inv0 = 1.f / (d0 + 1e-6f);
        const float inv1 = 1.f / (d1 + 1e-6f);

        const int mtok = (tbh >> 3) * Nv + qn0 + wrow + g * 16 + gl;
        __nv_bfloat16* dh0 = gc_hi + (size_t)mtok * Dv + hd0;
        __nv_bfloat16* dl0 = gc_lo + (size_t)mtok * Dv + hd0;
        __nv_bfloat16* dh1 = dh0 + 8 * Dv;
        __nv_bfloat16* dl1 = dl0 + 8 * Dv;
#pragma unroll
        for (int i = 0; i < 8; ++i) {
            const int d = (i >> 1) * 16 + (i & 1) * 8 + tg * 2;
            float v0 = ctx[g][i][0] * inv0, v1 = ctx[g][i][1] * inv0;
            float v2 = ctx[g][i][2] * inv1, v3 = ctx[g][i][3] * inv1;
            uint32_t h01 = cvt_bf2(v0, v1);
            uint32_t h23 = cvt_bf2(v2, v3);
            *(uint32_t*)(dh0 + d) = h01;
            *(uint32_t*)(dl0 + d) = cvt_bf2(v0 - bflo_f(h01), v1 - bfhi_f(h01));
            *(uint32_t*)(dh1 + d) = h23;
            *(uint32_t*)(dl1 + d) = cvt_bf2(v2 - bflo_f(h23), v3 - bfhi_f(h23));
        }
    }
}

// ---------------------------------------------------------------------------
extern "C" void kernel_launch(void* const* d_in, const int* in_sizes, int n_in,
                              void* d_out, int out_size)
{
    const float* x  = (const float*)d_in[0];
    const float* wq = (const float*)d_in[1];
    const float* bq = (const float*)d_in[2];
    const float* wk = (const float*)d_in[3];
    const float* bk = (const float*)d_in[4];
    const float* wv = (const float*)d_in[5];
    const float* bv = (const float*)d_in[6];
    const float* wo = (const float*)d_in[7];
    const float* bo = (const float*)d_in[8];
    float* out = (float*)d_out;

    cudaFuncSetAttribute(qkv_gemm_p, cudaFuncAttributeMaxDynamicSharedMemorySize, GEMM_SMEM);
    cudaFuncSetAttribute(out_gemm_p, cudaFuncAttributeMaxDynamicSharedMemorySize, GEMM2_SMEM);
    cudaFuncSetAttribute(attn_m, cudaFuncAttributeMaxDynamicSharedMemorySize, ATTN_SMEM);

    const int splitBlocks = (NXf4 + 4 * NWf4 + 255) / 256;
    split_kernel<<<splitBlocks, 256>>>(x, wq, wk, wv, wo);
    qkv_gemm_p<<<dim3(Mv / 128, 12), 256, GEMM_SMEM>>>(bq, bk, bv);
    attn_m<<<dim3(Nv / 128, TBv * Hv), 128, ATTN_SMEM>>>();
    out_gemm_p<<<dim3(Mv / 128, Dv / 128), 256, GEMM2_SMEM>>>(bo, out);
}

// round 15
// speedup vs baseline: 1.3218x; 1.0036x over previous
#include <cuda_runtime.h>
#include <cuda_bf16.h>
#include <mma.h>
#include <cstdint>

using namespace nvcuda;

#define TBv 16
#define Nv  1024
#define Dv  512
#define Hv  8
#define HDv 64
#define Mv  (TBv * Nv)

__device__ __nv_bfloat16 gx_hi[(size_t)Mv * Dv], gx_lo[(size_t)Mv * Dv];
__device__ __nv_bfloat16 gw_hi[4 * Dv * Dv],     gw_lo[4 * Dv * Dv];
__device__ __nv_bfloat16 gq_hi[(size_t)Mv * Dv], gq_lo[(size_t)Mv * Dv];
__device__ __nv_bfloat16 gk_hi[(size_t)Mv * Dv], gk_lo[(size_t)Mv * Dv];
__device__ __nv_bfloat16 gv_hi[(size_t)Mv * Dv], gv_lo[(size_t)Mv * Dv];
__device__ __nv_bfloat16 gc_hi[(size_t)Mv * Dv], gc_lo[(size_t)Mv * Dv];

// ---- packed bf16x2 conversion helpers -------------------------------------
__device__ __forceinline__ uint32_t cvt_bf2(float x, float y) { // {lo=x, hi=y}
    uint32_t r;
    asm("cvt.rn.bf16x2.f32 %0, %1, %2;" : "=r"(r) : "f"(y), "f"(x));
    return r;
}
__device__ __forceinline__ float bflo_f(uint32_t p) { return __uint_as_float(p << 16); }
__device__ __forceinline__ float bfhi_f(uint32_t p) { return __uint_as_float(p & 0xffff0000u); }

__device__ __forceinline__ void split_store4(float4 v,
                                             __nv_bfloat16* __restrict__ hp,
                                             __nv_bfloat16* __restrict__ lp)
{
    uint32_t h01 = cvt_bf2(v.x, v.y);
    uint32_t h23 = cvt_bf2(v.z, v.w);
    ((uint32_t*)hp)[0] = h01;
    ((uint32_t*)hp)[1] = h23;
    ((uint32_t*)lp)[0] = cvt_bf2(v.x - bflo_f(h01), v.y - bfhi_f(h01));
    ((uint32_t*)lp)[1] = cvt_bf2(v.z - bflo_f(h23), v.w - bfhi_f(h23));
}
__device__ __forceinline__ void cp16(uint32_t dst, const void* src) {
    asm volatile("cp.async.cg.shared.global [%0], [%1], 16;" :: "r"(dst), "l"(src));
}
__device__ __forceinline__ void cp_commit() {
    asm volatile("cp.async.commit_group;" ::: "memory");
}
__device__ __forceinline__ void ldsm4(uint32_t (&r)[4], uint32_t a) {
    asm volatile("ldmatrix.sync.aligned.m8n8.x4.shared.b16 {%0,%1,%2,%3}, [%4];"
                 : "=r"(r[0]), "=r"(r[1]), "=r"(r[2]), "=r"(r[3]) : "r"(a));
}
__device__ __forceinline__ void ldsm4t(uint32_t (&r)[4], uint32_t a) {
    asm volatile("ldmatrix.sync.aligned.m8n8.x4.trans.shared.b16 {%0,%1,%2,%3}, [%4];"
                 : "=r"(r[0]), "=r"(r[1]), "=r"(r[2]), "=r"(r[3]) : "r"(a));
}
__device__ __forceinline__ void mma16816(float (&c)[4], const uint32_t (&a)[4],
                                         uint32_t b0, uint32_t b1) {
    asm volatile(
        "mma.sync.aligned.m16n8k16.row.col.f32.bf16.bf16.f32 "
        "{%0,%1,%2,%3}, {%4,%5,%6,%7}, {%8,%9}, {%0,%1,%2,%3};"
        : "+f"(c[0]), "+f"(c[1]), "+f"(c[2]), "+f"(c[3])
        : "r"(a[0]), "r"(a[1]), "r"(a[2]), "r"(a[3]), "r"(b0), "r"(b1));
}

using BFragA  = wmma::fragment<wmma::matrix_a, 16, 16, 16, __nv_bfloat16, wmma::row_major>;
using BFragBc = wmma::fragment<wmma::matrix_b, 16, 16, 16, __nv_bfloat16, wmma::col_major>;
using FragC   = wmma::fragment<wmma::accumulator, 16, 16, 16, float>;

// ---------------------------------------------------------------------------
#define NXf4 (Mv * Dv / 4)
#define NWf4 (Dv * Dv / 4)

__global__ __launch_bounds__(256) void split_kernel(
    const float* __restrict__ x,
    const float* __restrict__ wq, const float* __restrict__ wk,
    const float* __restrict__ wv, const float* __restrict__ wo)
{
    int i = blockIdx.x * 256 + threadIdx.x;
    const float* src; __nv_bfloat16 *dh, *dl; int j;
    if (i < NXf4) { src = x; j = i; dh = gx_hi; dl = gx_lo; }
    else {
        int r = i - NXf4;
        if (r >= 4 * NWf4) return;
        int sel = r / NWf4; j = r % NWf4;
        src = (sel == 0) ? wq : (sel == 1) ? wk : (sel == 2) ? wv : wo;
        dh = gw_hi + (size_t)sel * Dv * Dv;
        dl = gw_lo + (size_t)sel * Dv * Dv;
    }
    float4 v = ((const float4*)src)[j];
    split_store4(v, dh + 4 * (size_t)j, dl + 4 * (size_t)j);
}

// ===========================================================================
// Shared GEMM kstep — TERM-MAJOR MMA order: all 8 independent (i,j) MMAs of
// each 3xBF16 term issued together (dependent-reuse distance 1 -> 8).
// ===========================================================================
#define G_PLE  5120
#define G_PLB  10240

__device__ __forceinline__ void g_kstep(const char* smc, int ks,
                                        int wm, int wn, FragC (&acc)[4][2])
{
    const __nv_bfloat16* S = (const __nv_bfloat16*)smc;
    BFragA ahi[4], alo[4];
#pragma unroll
    for (int i = 0; i < 4; ++i) {
        wmma::load_matrix_sync(ahi[i], S + (wm + 16 * i) * 40 + ks * 16, 40);
        wmma::load_matrix_sync(alo[i], S + G_PLE + (wm + 16 * i) * 40 + ks * 16, 40);
    }
    BFragBc bhi[2], blo[2];
#pragma unroll
    for (int j = 0; j < 2; ++j) {
        wmma::load_matrix_sync(bhi[j], S + 2 * G_PLE + (wn + 16 * j) * 40 + ks * 16, 40);
        wmma::load_matrix_sync(blo[j], S + 3 * G_PLE + (wn + 16 * j) * 40 + ks * 16, 40);
    }
#pragma unroll
    for (int j = 0; j < 2; ++j)
#pragma unroll
        for (int i = 0; i < 4; ++i)
            wmma::mma_sync(acc[i][j], ahi[i], bhi[j], acc[i][j]);
#pragma unroll
    for (int j = 0; j < 2; ++j)
#pragma unroll
        for (int i = 0; i < 4; ++i)
            wmma::mma_sync(acc[i][j], ahi[i], blo[j], acc[i][j]);
#pragma unroll
    for (int j = 0; j < 2; ++j)
#pragma unroll
        for (int i = 0; i < 4; ++i)
            wmma::mma_sync(acc[i][j], alo[i], bhi[j], acc[i][j]);
}

// ---- qkv GEMM: reg-staged single-buffer schedule ---------------------------
#define G_BIAS 40960
#define GEMM_SMEM (40960 + 512)

__device__ __forceinline__ void gemm_single(
    const __nv_bfloat16* __restrict__ Ah, const __nv_bfloat16* __restrict__ Al,
    const __nv_bfloat16* __restrict__ Bh, const __nv_bfloat16* __restrict__ Bl,
    char* smc, FragC (&acc)[4][2])
{
    const int t = threadIdx.x;
    const int w = t >> 5;
    const int wm = (w & 1) * 64;
    const int wn = (w >> 1) * 32;
#pragma unroll
    for (int i = 0; i < 4; ++i)
#pragma unroll
        for (int j = 0; j < 2; ++j)
            wmma::fill_fragment(acc[i][j], 0.0f);

    for (int ch = 0; ch < 16; ++ch) {
        uint4 rg[8];
#pragma unroll
        for (int hh = 0; hh < 2; ++hh) {
            const int o = t + 256 * hh;
            const size_t off = (size_t)(o >> 2) * Dv + ch * 32 + (o & 3) * 8;
            rg[4 * hh + 0] = *(const uint4*)(Ah + off);
            rg[4 * hh + 1] = *(const uint4*)(Al + off);
            rg[4 * hh + 2] = *(const uint4*)(Bh + off);
            rg[4 * hh + 3] = *(const uint4*)(Bl + off);
        }
        __syncthreads();
#pragma unroll
        for (int hh = 0; hh < 2; ++hh) {
            const int o = t + 256 * hh;
            const int off = (o >> 2) * 80 + (o & 3) * 16;
            *(uint4*)(smc + off)             = rg[4 * hh + 0];
            *(uint4*)(smc + G_PLB + off)     = rg[4 * hh + 1];
            *(uint4*)(smc + 2 * G_PLB + off) = rg[4 * hh + 2];
            *(uint4*)(smc + 3 * G_PLB + off) = rg[4 * hh + 3];
        }
        __syncthreads();
        g_kstep(smc, 0, wm, wn, acc);
        g_kstep(smc, 1, wm, wn, acc);
    }
}

__global__ __launch_bounds__(256, 2) void qkv_gemm_p(
    const float* __restrict__ bq, const float* __restrict__ bk,
    const float* __restrict__ bv)
{
    extern __shared__ char smc[];
    const int t = threadIdx.x;
    const int m0   = blockIdx.x * 128;
    const int wsel = blockIdx.y >> 2;
    const int n0   = (blockIdx.y & 3) * 128;

    const float* bias = (wsel == 0) ? bq : (wsel == 1) ? bk : bv;
    __nv_bfloat16* oh = (wsel == 0) ? gq_hi : (wsel == 1) ? gk_hi : gv_hi;
    __nv_bfloat16* ol = (wsel == 0) ? gq_lo : (wsel == 1) ? gk_lo : gv_lo;

    float* biasS = (float*)(smc + G_BIAS);
    if (t < 128) biasS[t] = bias[n0 + t];

    FragC acc[4][2];
    gemm_single(gx_hi + (size_t)m0 * Dv, gx_lo + (size_t)m0 * Dv,
                gw_hi + (size_t)wsel * Dv * Dv + (size_t)n0 * Dv,
                gw_lo + (size_t)wsel * Dv * Dv + (size_t)n0 * Dv, smc, acc);

    float* Cs = (float*)smc;
    const int w = t >> 5, wn = (w >> 1) * 32;
    const int erow = t >> 2;
    const int ecol = (t & 3) * 32;
#pragma unroll
    for (int p = 0; p < 2; ++p) {
        __syncthreads();
        if ((w & 1) == p) {
#pragma unroll
            for (int i = 0; i < 4; ++i)
#pragma unroll
                for (int j = 0; j < 2; ++j)
                    wmma::store_matrix_sync(&Cs[(16 * i) * 132 + wn + 16 * j],
                                            acc[i][j], 132, wmma::mem_row_major);
        }
        __syncthreads();
        const int m  = m0 + p * 64 + erow;
        const int tb = m >> 10, n = m & 1023;
        const int h  = (n0 + ecol) >> 6;
        const int hd0 = (n0 + ecol) & 63;
        __nv_bfloat16* dh = oh + ((size_t)(tb * Hv + h) * Nv + n) * HDv + hd0;
        __nv_bfloat16* dl = ol + ((size_t)(tb * Hv + h) * Nv + n) * HDv + hd0;
#pragma unroll
        for (int c = 0; c < 32; c += 4) {
            float4 v = *(float4*)&Cs[erow * 132 + ecol + c];
            v.x += biasS[ecol + c + 0]; v.y += biasS[ecol + c + 1];
            v.z += biasS[ecol + c + 2]; v.w += biasS[ecol + c + 3];
            split_store4(v, dh + c, dl + c);
        }
    }
}

// ---- out GEMM: cp.async 2-stage pipeline -----------------------------------
#define G2_STG  40960
#define G2_BIAS 81920
#define GEMM2_SMEM (81920 + 512)

__device__ __forceinline__ void g2_prefetch(
    uint32_t sb, int stage,
    const __nv_bfloat16* __restrict__ Ah, const __nv_bfloat16* __restrict__ Al,
    const __nv_bfloat16* __restrict__ Bh, const __nv_bfloat16* __restrict__ Bl,
    int k0, int t)
{
    const __nv_bfloat16* pl[4] = {Ah, Al, Bh, Bl};
    const uint32_t base = sb + stage * G2_STG;
#pragma unroll
    for (int p = 0; p < 4; ++p) {
#pragma unroll
        for (int hh = 0; hh < 2; ++hh) {
            const int o = t + 256 * hh;
            const int row = o >> 2, seg = o & 3;
            cp16(base + p * G_PLB + row * 80 + seg * 16,
                 pl[p] + (size_t)row * Dv + k0 + seg * 8);
        }
    }
}

__global__ __launch_bounds__(256, 2) void out_gemm_p(
    const float* __restrict__ bo, float* __restrict__ out)
{
    extern __shared__ char smc[];
    const int t = threadIdx.x;
    const int m0 = blockIdx.x * 128;
    const int n0 = blockIdx.y * 128;
    const uint32_t sb = (uint32_t)__cvta_generic_to_shared(smc);

    float* biasS = (float*)(smc + G2_BIAS);
    if (t < 128) biasS[t] = bo[n0 + t];

    const __nv_bfloat16* Ah = gc_hi + (size_t)m0 * Dv;
    const __nv_bfloat16* Al = gc_lo + (size_t)m0 * Dv;
    const __nv_bfloat16* Bh = gw_hi + (size_t)3 * Dv * Dv + (size_t)n0 * Dv;
    const __nv_bfloat16* Bl = gw_lo + (size_t)3 * Dv * Dv + (size_t)n0 * Dv;

    const int w = t >> 5;
    const int wm = (w & 1) * 64;
    const int wn = (w >> 1) * 32;
    FragC acc[4][2];
#pragma unroll
    for (int i = 0; i < 4; ++i)
#pragma unroll
        for (int j = 0; j < 2; ++j)
            wmma::fill_fragment(acc[i][j], 0.0f);

    g2_prefetch(sb, 0, Ah, Al, Bh, Bl, 0, t);
    cp_commit();
    for (int ch = 0; ch < 16; ++ch) {
        if (ch < 15) {
            g2_prefetch(sb, (ch + 1) & 1, Ah, Al, Bh, Bl, (ch + 1) * 32, t);
            cp_commit();
            asm volatile("cp.async.wait_group 1;" ::: "memory");
        } else {
            asm volatile("cp.async.wait_group 0;" ::: "memory");
        }
        __syncthreads();
        g_kstep(smc + (ch & 1) * G2_STG, 0, wm, wn, acc);
        g_kstep(smc + (ch & 1) * G2_STG, 1, wm, wn, acc);
        __syncthreads();
    }

    float* Cs = (float*)smc;
#pragma unroll
    for (int i = 0; i < 4; ++i)
#pragma unroll
        for (int j = 0; j < 2; ++j)
            wmma::store_matrix_sync(&Cs[(wm + 16 * i) * 132 + wn + 16 * j],
                                    acc[i][j], 132, wmma::mem_row_major);
    __syncthreads();

    const int row = t >> 1, c0 = (t & 1) * 64;
    float* dst = out + (size_t)(m0 + row) * Dv + n0 + c0;
#pragma unroll
    for (int c = 0; c < 64; c += 4) {
        float4 v = *(float4*)&Cs[row * 132 + c0 + c];
        v.x += biasS[c0 + c + 0]; v.y += biasS[c0 + c + 1];
        v.z += biasS[c0 + c + 2]; v.w += biasS[c0 + c + 3];
        *(float4*)(dst + c) = v;
    }
}

// ===========================================================================
// Attention: mma.sync m16n8k16, S in registers; 128 thr, 4 warps x 32 q-rows;
// MMA phases reordered term-major across (g, acc-half) (dep distance 3 -> 4+).
// ===========================================================================
#define AT_STG  36864
#define AT_PL   9216
#define AT_Q    73728
#define ATTN_SMEM 110592

__device__ __forceinline__ void kv_prefetch(uint32_t dstbase, size_t hb,
                                            int row0, int t)
{
    const __nv_bfloat16* kvp[4] = {gk_hi + hb, gk_lo + hb, gv_hi + hb, gv_lo + hb};
#pragma unroll
    for (int hh = 0; hh < 16; ++hh) {
        const int o = t + 128 * hh;            // 0..2047
        const int plane = o >> 9;
        const int idx = o & 511;
        cp16(dstbase + plane * AT_PL + (idx >> 3) * 144 + (idx & 7) * 16,
             kvp[plane] + (size_t)(row0 + (idx >> 3)) * HDv + (idx & 7) * 8);
    }
}

__global__ __launch_bounds__(128, 2) void attn_m()
{
    extern __shared__ char smc[];
    const uint32_t sb = (uint32_t)__cvta_generic_to_shared(smc);
    const int t = threadIdx.x;
    const int l = t & 31;
    const int w = t >> 5;                      // 0..3
    const int qn0 = blockIdx.x * 128;
    const int tbh = blockIdx.y;
    const size_t hb = (size_t)tbh * Nv * HDv;

#pragma unroll
    for (int hh = 0; hh < 16; ++hh) {
        const int o = t + 128 * hh;            // 0..2047
        const int plane = o >> 10;
        const int idx = o & 1023;
        const __nv_bfloat16* src =
            (plane ? gq_lo : gq_hi) + hb + (size_t)(qn0 + (idx >> 3)) * HDv + (idx & 7) * 8;
        cp16(sb + AT_Q + plane * 18432 + (idx >> 3) * 144 + (idx & 7) * 16, src);
    }
    kv_prefetch(sb, hb, 0, t);
    cp_commit();
    kv_prefetch(sb + AT_STG, hb, 64, t);
    cp_commit();

    const int wrow = w * 32;
    uint32_t qaddr[2];
    qaddr[0] = sb + AT_Q + (wrow + (l & 15)) * 144 + (l >> 4) * 16;
    qaddr[1] = qaddr[0] + 16 * 144;
    const int kroff = ((l & 7) + ((l >> 4) & 1) * 8) * 144 + ((l >> 3) & 1) * 16;
    const int vroff = ((l & 7) + ((l >> 3) & 1) * 8) * 144 + ((l >> 4) & 1) * 16;

    float ctx[2][8][4];
#pragma unroll
    for (int g = 0; g < 2; ++g)
#pragma unroll
        for (int i = 0; i < 8; ++i)
#pragma unroll
            for (int j = 0; j < 4; ++j) ctx[g][i][j] = 0.f;
    float ds[2][2] = {{0.f, 0.f}, {0.f, 0.f}};

    for (int kt = 0; kt < 16; ++kt) {
        if (kt < 15) asm volatile("cp.async.wait_group 1;" ::: "memory");
        else         asm volatile("cp.async.wait_group 0;" ::: "memory");
        __syncthreads();
        const uint32_t kst = sb + (kt & 1) * AT_STG;

        float sacc[2][8][4];
#pragma unroll
        for (int g = 0; g < 2; ++g)
#pragma unroll
            for (int i = 0; i < 8; ++i)
#pragma unroll
                for (int j = 0; j < 4; ++j) sacc[g][i][j] = 0.f;
#pragma unroll
        for (int ks = 0; ks < 4; ++ks) {
            uint32_t aqh[2][4], aql[2][4];
            ldsm4(aqh[0], qaddr[0] + ks * 32);
            ldsm4(aql[0], qaddr[0] + 18432 + ks * 32);
            ldsm4(aqh[1], qaddr[1] + ks * 32);
            ldsm4(aql[1], qaddr[1] + 18432 + ks * 32);
#pragma unroll
            for (int np = 0; np < 4; ++np) {
                uint32_t bh[4], bl[4];
                ldsm4(bh, kst + np * 16 * 144 + kroff + ks * 32);
                ldsm4(bl, kst + AT_PL + np * 16 * 144 + kroff + ks * 32);
                // term-major: 4 independent MMAs per term group
#pragma unroll
                for (int g = 0; g < 2; ++g) mma16816(sacc[g][2 * np],     aqh[g], bh[0], bh[1]);
#pragma unroll
                for (int g = 0; g < 2; ++g) mma16816(sacc[g][2 * np + 1], aqh[g], bh[2], bh[3]);
#pragma unroll
                for (int g = 0; g < 2; ++g) mma16816(sacc[g][2 * np],     aqh[g], bl[0], bl[1]);
#pragma unroll
                for (int g = 0; g < 2; ++g) mma16816(sacc[g][2 * np + 1], aqh[g], bl[2], bl[3]);
#pragma unroll
                for (int g = 0; g < 2; ++g) mma16816(sacc[g][2 * np],     aql[g], bh[0], bh[1]);
#pragma unroll
                for (int g = 0; g < 2; ++g) mma16816(sacc[g][2 * np + 1], aql[g], bh[2], bh[3]);
            }
        }
#pragma unroll
        for (int kf = 0; kf < 4; ++kf) {
            uint32_t sah[2][4], sal[2][4];
#pragma unroll
            for (int g = 0; g < 2; ++g) {
#pragma unroll
                for (int hh = 0; hh < 2; ++hh) {
                    float* c = sacc[g][2 * kf + hh];
                    float c0 = fmaxf(c[0] * 0.125f, 0.f);
                    float c1 = fmaxf(c[1] * 0.125f, 0.f);
                    float c2 = fmaxf(c[2] * 0.125f, 0.f);
                    float c3 = fmaxf(c[3] * 0.125f, 0.f);
                    ds[g][0] += c0 + c1;
                    ds[g][1] += c2 + c3;
                    uint32_t h01 = cvt_bf2(c0, c1);
                    uint32_t h23 = cvt_bf2(c2, c3);
                    sah[g][2 * hh + 0] = h01;
                    sah[g][2 * hh + 1] = h23;
                    sal[g][2 * hh + 0] = cvt_bf2(c0 - bflo_f(h01), c1 - bfhi_f(h01));
                    sal[g][2 * hh + 1] = cvt_bf2(c2 - bflo_f(h23), c3 - bfhi_f(h23));
                }
            }
#pragma unroll
            for (int np = 0; np < 4; ++np) {
                uint32_t bvh[4], bvl[4];
                ldsm4t(bvh, kst + 2 * AT_PL + kf * 16 * 144 + vroff + np * 32);
                ldsm4t(bvl, kst + 3 * AT_PL + kf * 16 * 144 + vroff + np * 32);
#pragma unroll
                for (int g = 0; g < 2; ++g) mma16816(ctx[g][2 * np],     sah[g], bvh[0], bvh[1]);
#pragma unroll
                for (int g = 0; g < 2; ++g) mma16816(ctx[g][2 * np + 1], sah[g], bvh[2], bvh[3]);
#pragma unroll
                for (int g = 0; g < 2; ++g) mma16816(ctx[g][2 * np],     sah[g], bvl[0], bvl[1]);
#pragma unroll
                for (int g = 0; g < 2; ++g) mma16816(ctx[g][2 * np + 1], sah[g], bvl[2], bvl[3]);
#pragma unroll
                for (int g = 0; g < 2; ++g) mma16816(ctx[g][2 * np],     sal[g], bvh[0], bvh[1]);
#pragma unroll
                for (int g = 0; g < 2; ++g) mma16816(ctx[g][2 * np + 1], sal[g], bvh[2], bvh[3]);
            }
        }
        __syncthreads();                      // stage consumed
        if (kt < 14) {
            kv_prefetch(sb + (kt & 1) * AT_STG, hb, (kt + 2) * 64, t);
            cp_commit();
        }
    }

    // epilogue: quad-reduce rowsums per group, normalize, write ctx planes
    const int gl = l >> 2, tg = l & 3;
    const int hd0 = (tbh & 7) * HDv;
#pragma unroll
    for (int g = 0; g < 2; ++g) {
        float d0 = ds[g][0], d1 = ds[g][1];
        d0 += __shfl_xor_sync(0xffffffffu, d0, 1);
        d0 += __shfl_xor_sync(0xffffffffu, d0, 2);
        d1 += __shfl_xor_sync(0xffffffffu, d1, 1);
        d1 += __shfl_xor_sync(0xffffffffu, d1, 2);
        const float inv0 = 1.f / (d0 + 1e-6f);
        const float inv1 = 1.f / (d1 + 1e-6f);

        const int mtok = (tbh >> 3) * Nv + qn0 + wrow + g * 16 + gl;
        __nv_bfloat16* dh0 = gc_hi + (size_t)mtok * Dv + hd0;
        __nv_bfloat16* dl0 = gc_lo + (size_t)mtok * Dv + hd0;
        __nv_bfloat16* dh1 = dh0 + 8 * Dv;
        __nv_bfloat16* dl1 = dl0 + 8 * Dv;
#pragma unroll
        for (int i = 0; i < 8; ++i) {
            const int d = (i >> 1) * 16 + (i & 1) * 8 + tg * 2;
            float v0 = ctx[g][i][0] * inv0, v1 = ctx[g][i][1] * inv0;
            float v2 = ctx[g][i][2] * inv1, v3 = ctx[g][i][3] * inv1;
            uint32_t h01 = cvt_bf2(v0, v1);
            uint32_t h23 = cvt_bf2(v2, v3);
            *(uint32_t*)(dh0 + d) = h01;
            *(uint32_t*)(dl0 + d) = cvt_bf2(v0 - bflo_f(h01), v1 - bfhi_f(h01));
            *(uint32_t*)(dh1 + d) = h23;
            *(uint32_t*)(dl1 + d) = cvt_bf2(v2 - bflo_f(h23), v3 - bfhi_f(h23));
        }
    }
}

// ---------------------------------------------------------------------------
extern "C" void kernel_launch(void* const* d_in, const int* in_sizes, int n_in,
                              void* d_out, int out_size)
{
    const float* x  = (const float*)d_in[0];
    const float* wq = (const float*)d_in[1];
    const float* bq = (const float*)d_in[2];
    const float* wk = (const float*)d_in[3];
    const float* bk = (const float*)d_in[4];
    const float* wv = (const float*)d_in[5];
    const float* bv = (const float*)d_in[6];
    const float* wo = (const float*)d_in[7];
    const float* bo = (const float*)d_in[8];
    float* out = (float*)d_out;

    cudaFuncSetAttribute(qkv_gemm_p, cudaFuncAttributeMaxDynamicSharedMemorySize, GEMM_SMEM);
    cudaFuncSetAttribute(out_gemm_p, cudaFuncAttributeMaxDynamicSharedMemorySize, GEMM2_SMEM);
    cudaFuncSetAttribute(attn_m, cudaFuncAttributeMaxDynamicSharedMemorySize, ATTN_SMEM);

    const int splitBlocks = (NXf4 + 4 * NWf4 + 255) / 256;
    split_kernel<<<splitBlocks, 256>>>(x, wq, wk, wv, wo);
    qkv_gemm_p<<<dim3(Mv / 128, 12), 256, GEMM_SMEM>>>(bq, bk, bv);
    attn_m<<<dim3(Nv / 128, TBv * Hv), 128, ATTN_SMEM>>>();
    out_gemm_p<<<dim3(Mv / 128, Dv / 128), 256, GEMM2_SMEM>>>(bo, out);
}